// round 10
// baseline (speedup 1.0000x reference)
#include <cuda_runtime.h>
#include <cuda_bf16.h>
#include <stdint.h>
#include <math.h>

// ---------------------------------------------------------------------------
// Problem constants
// ---------------------------------------------------------------------------
#define BB   2
#define SS   1025
#define DD   1024
#define HH_  16
#define HD_  64
#define PP   1024
#define KR_  32
#define SCALE_ 0.125f
#define INV_TEMP 10.0f

// ---------------------------------------------------------------------------
// Scratch (float units). bf16 buffers live inside the float array.
// ---------------------------------------------------------------------------
static const size_t F_QR   = 2048ull * 1024;        // f32 q_r (pre-l2norm)
static const size_t F_KR   = 2048ull * 1024;        // f32 k_r (must follow QR!)
static const size_t F_SC   = 2048ull * 1024;        // f32 scores
static const size_t F_QKV  = 2050ull * 3072;        // f32 qkv
static const size_t F_LW   = 2048ull * 32;
static const size_t F_RT   = 2048ull * 32;
// bf16 plane sizes in float units (= elems/2)
static const size_t H_XN   = 2050ull * 1024 / 2;    // XN hi (and lo)
static const size_t H_QKR  = 4096ull * 1024 / 2;    // q_r|k_r normalized hi/lo
static const size_t H_ATT  = 2050ull * 1024 / 2;
static const size_t H_HN   = 2050ull * 1024 / 2;
static const size_t H_HH   = 2050ull * 4096 / 2;
static const size_t H_W    = 14680064ull / 2;       // all weights hi (and lo)

static const size_t O_QR   = 0;
static const size_t O_KR   = O_QR  + F_QR;
static const size_t O_SC   = O_KR  + F_KR;
static const size_t O_QKV  = O_SC  + F_SC;
static const size_t O_LW   = O_QKV + F_QKV;
static const size_t O_RT   = O_LW  + F_LW;
static const size_t O_XNH  = O_RT  + F_RT;
static const size_t O_XNL  = O_XNH + H_XN;
static const size_t O_QKRH = O_XNL + H_XN;
static const size_t O_QKRL = O_QKRH + H_QKR;
static const size_t O_ATTH = O_QKRL + H_QKR;
static const size_t O_ATTL = O_ATTH + H_ATT;
static const size_t O_HNH  = O_ATTL + H_ATT;
static const size_t O_HNL  = O_HNH + H_HN;
static const size_t O_HHH  = O_HNL + H_HN;
static const size_t O_HHL  = O_HHH + H_HH;
static const size_t O_WH   = O_HHL + H_HH;
static const size_t O_WL   = O_WH  + H_W;
static const size_t SCR_TOTAL = O_WL + H_W;

// weight offsets within the W slab (bf16 elems)
static const size_t W_RQ   = 0;
static const size_t W_RK   = 1048576;
static const size_t W_QKV  = 2097152;
static const size_t W_PROJ = 5242880;
static const size_t W_FC1  = 6291456;
static const size_t W_FC2  = 10485760;

__device__ float g_scratch[SCR_TOTAL];

// ---------------------------------------------------------------------------
// Block reductions (blockDim.x == 256)
// ---------------------------------------------------------------------------
__device__ __forceinline__ float blockReduceSum(float v, float* sbuf) {
    int lane = threadIdx.x & 31, wid = threadIdx.x >> 5;
    #pragma unroll
    for (int o = 16; o; o >>= 1) v += __shfl_xor_sync(0xffffffffu, v, o);
    if (lane == 0) sbuf[wid] = v;
    __syncthreads();
    if (wid == 0) {
        v = (lane < 8) ? sbuf[lane] : 0.f;
        #pragma unroll
        for (int o = 4; o; o >>= 1) v += __shfl_xor_sync(0xffffffffu, v, o);
        if (lane == 0) sbuf[0] = v;
    }
    __syncthreads();
    float r = sbuf[0];
    __syncthreads();
    return r;
}

__device__ __forceinline__ float blockReduceMax(float v, float* sbuf) {
    int lane = threadIdx.x & 31, wid = threadIdx.x >> 5;
    #pragma unroll
    for (int o = 16; o; o >>= 1) v = fmaxf(v, __shfl_xor_sync(0xffffffffu, v, o));
    if (lane == 0) sbuf[wid] = v;
    __syncthreads();
    if (wid == 0) {
        v = (lane < 8) ? sbuf[lane] : -3.4e38f;
        #pragma unroll
        for (int o = 4; o; o >>= 1) v = fmaxf(v, __shfl_xor_sync(0xffffffffu, v, o));
        if (lane == 0) sbuf[0] = v;
    }
    __syncthreads();
    float r = sbuf[0];
    __syncthreads();
    return r;
}

__device__ __forceinline__ void split1(float v, __nv_bfloat16* hi, __nv_bfloat16* lo) {
    __nv_bfloat16 h = __float2bfloat16(v);
    *hi = h;
    *lo = __float2bfloat16(v - __bfloat162float(h));
}

// ---------------------------------------------------------------------------
// Weight split: f32 -> hi/lo bf16 planes (grid-stride, float4)
// ---------------------------------------------------------------------------
__global__ void split_w_kernel(const float* __restrict__ src,
                               __nv_bfloat16* __restrict__ hi,
                               __nv_bfloat16* __restrict__ lo, int n4) {
    for (int i = blockIdx.x * blockDim.x + threadIdx.x; i < n4; i += gridDim.x * blockDim.x) {
        float4 f = ((const float4*)src)[i];
        __nv_bfloat162 h0 = __floats2bfloat162_rn(f.x, f.y);
        __nv_bfloat162 h1 = __floats2bfloat162_rn(f.z, f.w);
        __nv_bfloat162 l0 = __floats2bfloat162_rn(f.x - __bfloat162float(h0.x),
                                                  f.y - __bfloat162float(h0.y));
        __nv_bfloat162 l1 = __floats2bfloat162_rn(f.z - __bfloat162float(h1.x),
                                                  f.w - __bfloat162float(h1.y));
        uint2 hv; hv.x = *(unsigned*)&h0; hv.y = *(unsigned*)&h1;
        uint2 lv; lv.x = *(unsigned*)&l0; lv.y = *(unsigned*)&l1;
        *(uint2*)(hi + (size_t)i * 4) = hv;
        *(uint2*)(lo + (size_t)i * 4) = lv;
    }
}

// ---------------------------------------------------------------------------
// LayerNorm -> hi/lo bf16 planes
// ---------------------------------------------------------------------------
__global__ void layernorm_split_kernel(const float* __restrict__ in,
                                       const float* __restrict__ w,
                                       const float* __restrict__ b,
                                       __nv_bfloat16* __restrict__ outh,
                                       __nv_bfloat16* __restrict__ outl) {
    __shared__ float red[32];
    int row = blockIdx.x, tid = threadIdx.x;
    const float4* ip = (const float4*)(in + (size_t)row * 1024);
    float4 v = ip[tid];
    float s = v.x + v.y + v.z + v.w;
    float mean = blockReduceSum(s, red) * (1.f / 1024.f);
    float dx = v.x - mean, dy = v.y - mean, dz = v.z - mean, dw = v.w - mean;
    float ss = dx * dx + dy * dy + dz * dz + dw * dw;
    float var = blockReduceSum(ss, red) * (1.f / 1024.f);
    float rstd = rsqrtf(var + 1e-5f);
    float4 wv = ((const float4*)w)[tid];
    float4 bv = ((const float4*)b)[tid];
    float ox = dx * rstd * wv.x + bv.x;
    float oy = dy * rstd * wv.y + bv.y;
    float oz = dz * rstd * wv.z + bv.z;
    float ow = dw * rstd * wv.w + bv.w;
    __nv_bfloat162 h0 = __floats2bfloat162_rn(ox, oy);
    __nv_bfloat162 h1 = __floats2bfloat162_rn(oz, ow);
    __nv_bfloat162 l0 = __floats2bfloat162_rn(ox - __bfloat162float(h0.x),
                                              oy - __bfloat162float(h0.y));
    __nv_bfloat162 l1 = __floats2bfloat162_rn(oz - __bfloat162float(h1.x),
                                              ow - __bfloat162float(h1.y));
    uint2 hv; hv.x = *(unsigned*)&h0; hv.y = *(unsigned*)&h1;
    uint2 lv; lv.x = *(unsigned*)&l0; lv.y = *(unsigned*)&l1;
    *(uint2*)(outh + (size_t)row * 1024 + tid * 4) = hv;
    *(uint2*)(outl + (size_t)row * 1024 + tid * 4) = lv;
}

// ---------------------------------------------------------------------------
// L2 norm: reads f32 rows, writes hi/lo bf16 planes
// ---------------------------------------------------------------------------
__global__ void l2norm_split_kernel(const float* __restrict__ buf,
                                    __nv_bfloat16* __restrict__ outh,
                                    __nv_bfloat16* __restrict__ outl) {
    __shared__ float red[32];
    int row = blockIdx.x, tid = threadIdx.x;
    const float4* p = (const float4*)(buf + (size_t)row * 1024);
    float4 v = p[tid];
    float ss = v.x * v.x + v.y * v.y + v.z * v.z + v.w * v.w;
    float tot = blockReduceSum(ss, red);
    float sc = 1.f / fmaxf(sqrtf(tot), 1e-12f);
    float ox = v.x * sc, oy = v.y * sc, oz = v.z * sc, ow = v.w * sc;
    __nv_bfloat162 h0 = __floats2bfloat162_rn(ox, oy);
    __nv_bfloat162 h1 = __floats2bfloat162_rn(oz, ow);
    __nv_bfloat162 l0 = __floats2bfloat162_rn(ox - __bfloat162float(h0.x),
                                              oy - __bfloat162float(h0.y));
    __nv_bfloat162 l1 = __floats2bfloat162_rn(oz - __bfloat162float(h1.x),
                                              ow - __bfloat162float(h1.y));
    uint2 hv; hv.x = *(unsigned*)&h0; hv.y = *(unsigned*)&h1;
    uint2 lv; lv.x = *(unsigned*)&l0; lv.y = *(unsigned*)&l1;
    *(uint2*)(outh + (size_t)row * 1024 + tid * 4) = hv;
    *(uint2*)(outl + (size_t)row * 1024 + tid * 4) = lv;
}

// ---------------------------------------------------------------------------
// bf16x3 tensor-core NT GEMM, pure cp.async loader + ldmatrix fragments.
// C[M,N] = (Ah+Al)[M,K] * (Bh+Bl)[N,K]^T  (+ epilogue)
// 128x128 block tile, 256 threads, 8 warps of 32x64, chunk=32 k, m16n8k16.
// ---------------------------------------------------------------------------
#define EPI_BIAS        1
#define EPI_BIAS_RESID  2
#define EPI_GELU_SPLIT  3
#define EPI_SCORES      4

#define KSTRIDE 40                      // 32 + 8 pad, bf16 units
#define TILE_BF16 (128 * KSTRIDE)
#define SMA(st,hl,row,k) ((((st) * 2 + (hl)) * 128 + (row)) * KSTRIDE + (k))
#define SB_BASE (4 * TILE_BF16)
#define GEMM_SMEM_BYTES (8 * TILE_BF16 * 2)   // 81920

__device__ __forceinline__ void mma_bf16(float* d, const unsigned* a, const unsigned* b) {
    asm volatile(
        "mma.sync.aligned.m16n8k16.row.col.f32.bf16.bf16.f32 "
        "{%0,%1,%2,%3}, {%4,%5,%6,%7}, {%8,%9}, {%0,%1,%2,%3};"
        : "+f"(d[0]), "+f"(d[1]), "+f"(d[2]), "+f"(d[3])
        : "r"(a[0]), "r"(a[1]), "r"(a[2]), "r"(a[3]), "r"(b[0]), "r"(b[1]));
}

__device__ __forceinline__ void ldsm4(unsigned addr, unsigned& r0, unsigned& r1,
                                      unsigned& r2, unsigned& r3) {
    asm volatile("ldmatrix.sync.aligned.m8n8.x4.shared.b16 {%0,%1,%2,%3}, [%4];"
                 : "=r"(r0), "=r"(r1), "=r"(r2), "=r"(r3) : "r"(addr));
}

__device__ __forceinline__ void cpasync16(unsigned dst, const void* src, unsigned sz) {
    asm volatile("cp.async.ca.shared.global [%0], [%1], 16, %2;"
                 :: "r"(dst), "l"(src), "r"(sz));
}

template <int EPI>
__global__ __launch_bounds__(256) void gemm_bf3(
    const __nv_bfloat16* __restrict__ Ah, const __nv_bfloat16* __restrict__ Al,
    const __nv_bfloat16* __restrict__ Bh, const __nv_bfloat16* __restrict__ Bl,
    const float* __restrict__ bias, const float* __restrict__ extra,
    float* __restrict__ C, __nv_bfloat16* __restrict__ Ch, __nv_bfloat16* __restrict__ Cl,
    int M, int N, int Kd, long sA, long sB, long sC) {

    Ah += (long)blockIdx.z * sA;  Al += (long)blockIdx.z * sA;
    Bh += (long)blockIdx.z * sB;  Bl += (long)blockIdx.z * sB;
    const long cOff = (long)blockIdx.z * sC;

    extern __shared__ __nv_bfloat16 sm[];

    const int tid  = threadIdx.x;
    const int lane = tid & 31;
    const int wid  = tid >> 5;
    const int wr   = wid & 3;
    const int wc   = wid >> 2;
    const int g    = lane >> 2;
    const int tig  = lane & 3;
    const int bm   = blockIdx.y * 128;
    const int bn   = blockIdx.x * 128;

    float acc[2][8][4];
    #pragma unroll
    for (int mi = 0; mi < 2; mi++)
        #pragma unroll
        for (int ni = 0; ni < 8; ni++)
            #pragma unroll
            for (int r = 0; r < 4; r++) acc[mi][ni][r] = 0.f;

    // loader mapping: thread -> (row, half); 2x16B per plane per thread
    const int ldRow = tid >> 1;
    const int half  = tid & 1;
    const int aRow  = bm + ldRow;
    const unsigned aSz = (aRow < M) ? 16u : 0u;
    const long aOff = (long)((aRow < M) ? aRow : 0) * Kd + half * 16;
    const long bOff = (long)(bn + ldRow) * Kd + half * 16;
    const __nv_bfloat16* aH = Ah + aOff;
    const __nv_bfloat16* aL = Al + aOff;
    const __nv_bfloat16* bH = Bh + bOff;
    const __nv_bfloat16* bL = Bl + bOff;

    const unsigned smBase = (unsigned)__cvta_generic_to_shared(sm);
    const unsigned dA0 = smBase + 2u * (unsigned)(ldRow * KSTRIDE + half * 16);
    const unsigned stagePitch = 2u * (unsigned)(2 * TILE_BF16);   // bytes per stage step
    const unsigned hlPitch    = 2u * (unsigned)TILE_BF16;
    const unsigned bPlane     = 2u * (unsigned)SB_BASE;

    // ldmatrix lane offsets (element units within a plane) — same as round 9
    const int aRowL = wr * 32 + (lane & 7) + ((lane >> 3) & 1) * 8;
    const int aKL   = ((lane >> 4) & 1) * 8;
    const unsigned aLaneOff = (unsigned)(aRowL * KSTRIDE + aKL);
    const int bRowL = wc * 64 + (lane & 7) + ((lane >> 4) & 1) * 8;
    const int bKL   = ((lane >> 3) & 1) * 8;
    const unsigned bLaneOff = (unsigned)(bRowL * KSTRIDE + bKL);

    const int nIter = Kd >> 5;

    #define ISSUE(st, itv) do {                                              \
        const long k0 = (long)(itv) * 32;                                    \
        unsigned d0 = dA0 + (unsigned)(st) * stagePitch;                     \
        cpasync16(d0,            aH + k0,     aSz);                          \
        cpasync16(d0 + 16,       aH + k0 + 8, aSz);                          \
        cpasync16(d0 + hlPitch,      aL + k0,     aSz);                      \
        cpasync16(d0 + hlPitch + 16, aL + k0 + 8, aSz);                      \
        unsigned d1 = d0 + bPlane;                                           \
        cpasync16(d1,            bH + k0,     16u);                          \
        cpasync16(d1 + 16,       bH + k0 + 8, 16u);                          \
        cpasync16(d1 + hlPitch,      bL + k0,     16u);                      \
        cpasync16(d1 + hlPitch + 16, bL + k0 + 8, 16u);                      \
        asm volatile("cp.async.commit_group;");                              \
    } while (0)

    ISSUE(0, 0);
    if (nIter > 1) ISSUE(1, 1);

    for (int it = 0; it < nIter; ++it) {
        if (it == nIter - 1) asm volatile("cp.async.wait_group 0;");
        else                 asm volatile("cp.async.wait_group 1;");
        __syncthreads();

        const int s = it & 1;
        const unsigned pA_hi = (unsigned)((s * 2 + 0) * TILE_BF16);
        const unsigned pA_lo = (unsigned)((s * 2 + 1) * TILE_BF16);
        const unsigned pB_hi = (unsigned)(SB_BASE + (s * 2 + 0) * TILE_BF16);
        const unsigned pB_lo = (unsigned)(SB_BASE + (s * 2 + 1) * TILE_BF16);

        #pragma unroll
        for (int ks = 0; ks < 2; ks++) {
            const int kb = ks * 16;
            unsigned Ahf[2][4], Alf[2][4], Bhf[8][2], Blf[8][2];
            #pragma unroll
            for (int mi = 0; mi < 2; mi++) {
                unsigned off = (unsigned)(mi * 16 * KSTRIDE + kb) + aLaneOff;
                ldsm4(smBase + 2u * (pA_hi + off), Ahf[mi][0], Ahf[mi][1], Ahf[mi][2], Ahf[mi][3]);
                ldsm4(smBase + 2u * (pA_lo + off), Alf[mi][0], Alf[mi][1], Alf[mi][2], Alf[mi][3]);
            }
            #pragma unroll
            for (int j = 0; j < 4; j++) {
                unsigned off = (unsigned)(j * 16 * KSTRIDE + kb) + bLaneOff;
                ldsm4(smBase + 2u * (pB_hi + off),
                      Bhf[j * 2][0], Bhf[j * 2][1], Bhf[j * 2 + 1][0], Bhf[j * 2 + 1][1]);
                ldsm4(smBase + 2u * (pB_lo + off),
                      Blf[j * 2][0], Blf[j * 2][1], Blf[j * 2 + 1][0], Blf[j * 2 + 1][1]);
            }
            #pragma unroll
            for (int mi = 0; mi < 2; mi++)
                #pragma unroll
                for (int ni = 0; ni < 8; ni++) {
                    mma_bf16(acc[mi][ni], Ahf[mi], Bhf[ni]);
                    mma_bf16(acc[mi][ni], Alf[mi], Bhf[ni]);
                    mma_bf16(acc[mi][ni], Ahf[mi], Blf[ni]);
                }
        }
        __syncthreads();

        if (it + 2 < nIter) ISSUE(s, it + 2);
    }
    #undef ISSUE

    // epilogue
    #pragma unroll
    for (int mi = 0; mi < 2; mi++) {
        #pragma unroll
        for (int rr = 0; rr < 2; rr++) {
            const int m = bm + wr * 32 + mi * 16 + g + rr * 8;
            if (m >= M) continue;
            #pragma unroll
            for (int ni = 0; ni < 8; ni++) {
                #pragma unroll
                for (int cc = 0; cc < 2; cc++) {
                    const int n = bn + wc * 64 + ni * 8 + tig * 2 + cc;
                    float v = acc[mi][ni][rr * 2 + cc];
                    const long idx = cOff + (long)m * N + n;
                    if (EPI == EPI_BIAS) {
                        C[idx] = v + bias[n];
                    } else if (EPI == EPI_BIAS_RESID) {
                        C[idx] = v + bias[n] + extra[(long)m * N + n];
                    } else if (EPI == EPI_GELU_SPLIT) {
                        v += bias[n];
                        v = 0.5f * v * (1.0f + erff(v * 0.70710678118654752f));
                        split1(v, Ch + idx, Cl + idx);
                    } else if (EPI == EPI_SCORES) {
                        v += extra[(long)m * N + n];
                        if (m == n) v = -1e9f;
                        C[idx] = v;
                    }
                }
            }
        }
    }
}

// ---------------------------------------------------------------------------
// Top-K=32 + log-softmax routing weights (clipped)
// ---------------------------------------------------------------------------
__global__ void topk_kernel(const float* __restrict__ scores,
                            int* __restrict__ routes,
                            float* __restrict__ logw) {
    __shared__ float s[1024];
    __shared__ float selv[32];
    __shared__ int   seli[32];
    __shared__ float rv[8];
    __shared__ int   ri[8];
    int row = blockIdx.x, tid = threadIdx.x;
    int lane = tid & 31, wid = tid >> 5;
    const float* src = scores + (size_t)row * 1024;
    s[tid] = src[tid]; s[tid + 256] = src[tid + 256];
    s[tid + 512] = src[tid + 512]; s[tid + 768] = src[tid + 768];
    __syncthreads();

    for (int it = 0; it < 32; it++) {
        float bv = -3.4e38f; int bi = 0x7fffffff;
        #pragma unroll
        for (int c = 0; c < 4; c++) {
            int idx = tid + c * 256;
            float v = s[idx];
            if (v > bv || (v == bv && idx < bi)) { bv = v; bi = idx; }
        }
        #pragma unroll
        for (int o = 16; o; o >>= 1) {
            float ov = __shfl_xor_sync(0xffffffffu, bv, o);
            int   oi = __shfl_xor_sync(0xffffffffu, bi, o);
            if (ov > bv || (ov == bv && oi < bi)) { bv = ov; bi = oi; }
        }
        if (lane == 0) { rv[wid] = bv; ri[wid] = bi; }
        __syncthreads();
        if (tid == 0) {
            float fv = rv[0]; int fi = ri[0];
            #pragma unroll
            for (int wn = 1; wn < 8; wn++)
                if (rv[wn] > fv || (rv[wn] == fv && ri[wn] < fi)) { fv = rv[wn]; fi = ri[wn]; }
            selv[it] = fv; seli[it] = fi;
            s[fi] = -3.4e38f;
        }
        __syncthreads();
    }

    if (tid < 32) {
        float t = selv[tid] * INV_TEMP;
        float tmax = selv[0] * INV_TEMP;
        float e = expf(t - tmax);
        float z = e;
        #pragma unroll
        for (int o = 16; o; o >>= 1) z += __shfl_xor_sync(0xffffffffu, z, o);
        float lw = t - (tmax + logf(z));
        routes[(size_t)row * 32 + tid] = seli[tid];
        logw[(size_t)row * 32 + tid] = fmaxf(lw, -10.f);
    }
}

// ---------------------------------------------------------------------------
// CLS attention -> hi/lo ATT planes
// ---------------------------------------------------------------------------
__global__ void cls_attn_kernel(const float* __restrict__ qkv,
                                __nv_bfloat16* __restrict__ atth,
                                __nv_bfloat16* __restrict__ attl) {
    __shared__ float q[64];
    __shared__ float sp[SS];
    __shared__ float red[32];
    __shared__ float po[4][64];
    int bh = blockIdx.x, b = bh >> 4, h = bh & 15;
    int tid = threadIdx.x;
    const float* base = qkv + (size_t)b * SS * 3072;
    if (tid < 64) q[tid] = base[h * 64 + tid];
    __syncthreads();

    float lmax = -3.4e38f;
    for (int j = tid; j < SS; j += 256) {
        const float* kr = base + (size_t)j * 3072 + 1024 + h * 64;
        float d = 0.f;
        #pragma unroll
        for (int dd = 0; dd < 64; dd++) d += q[dd] * kr[dd];
        d *= SCALE_;
        sp[j] = d;
        lmax = fmaxf(lmax, d);
    }
    float M = blockReduceMax(lmax, red);
    float ls = 0.f;
    for (int j = tid; j < SS; j += 256) {
        float e = expf(sp[j] - M);
        sp[j] = e;
        ls += e;
    }
    float Z = blockReduceSum(ls, red);

    int g = tid >> 6, d = tid & 63;
    float o = 0.f;
    for (int j = g; j < SS; j += 4)
        o += sp[j] * base[(size_t)j * 3072 + 2048 + h * 64 + d];
    po[g][d] = o;
    __syncthreads();
    if (tid < 64) {
        float r = (po[0][tid] + po[1][tid] + po[2][tid] + po[3][tid]) / Z;
        size_t idx = (size_t)b * SS * 1024 + h * 64 + tid;   // row b*SS + 0
        split1(r, atth + idx, attl + idx);
    }
}

// ---------------------------------------------------------------------------
// Routed patch attention -> hi/lo ATT planes
// ---------------------------------------------------------------------------
__global__ void patch_attn_kernel(const float* __restrict__ qkv,
                                  const int* __restrict__ routes,
                                  const float* __restrict__ logw,
                                  __nv_bfloat16* __restrict__ atth,
                                  __nv_bfloat16* __restrict__ attl) {
    __shared__ float Kg[32][64];
    __shared__ float Vg[32][64];
    __shared__ float q[64];
    __shared__ float sc[32];
    __shared__ int   rt[32];
    __shared__ float lw[32];
    __shared__ float po[4][64];
    int bp = blockIdx.x, b = bp >> 10, p = bp & 1023;
    int tid = threadIdx.x, lane = tid & 31, w = tid >> 5;
    if (tid < 32) {
        rt[tid] = routes[(size_t)bp * 32 + tid];
        lw[tid] = logw[(size_t)bp * 32 + tid];
    }
    __syncthreads();
    const float* base = qkv + (size_t)b * SS * 3072;
    const size_t qoff = (size_t)(p + 1) * 3072;

    for (int h = 0; h < HH_; h++) {
        if (tid < 64) q[tid] = base[qoff + h * 64 + tid];
        for (int e = tid; e < 2048; e += 256) {
            int k = e >> 6, d = e & 63;
            size_t toff = (size_t)(rt[k] + 1) * 3072 + h * 64 + d;
            Kg[k][d] = base[toff + 1024];
            Vg[k][d] = base[toff + 2048];
        }
        __syncthreads();

        for (int kk = w; kk < 32; kk += 8) {
            float part = q[lane] * Kg[kk][lane] + q[lane + 32] * Kg[kk][lane + 32];
            #pragma unroll
            for (int o = 16; o; o >>= 1) part += __shfl_xor_sync(0xffffffffu, part, o);
            if (lane == 0) sc[kk] = part * SCALE_ + lw[kk];
        }
        __syncthreads();

        if (tid < 32) {
            float v = sc[tid], m = v;
            #pragma unroll
            for (int o = 16; o; o >>= 1) m = fmaxf(m, __shfl_xor_sync(0xffffffffu, m, o));
            float e = expf(v - m), z = e;
            #pragma unroll
            for (int o = 16; o; o >>= 1) z += __shfl_xor_sync(0xffffffffu, z, o);
            sc[tid] = e / z;
        }
        __syncthreads();

        int g = tid >> 6, d = tid & 63;
        float o = 0.f;
        #pragma unroll
        for (int kk = g; kk < 32; kk += 4) o += sc[kk] * Vg[kk][d];
        po[g][d] = o;
        __syncthreads();
        if (tid < 64) {
            float r = po[0][tid] + po[1][tid] + po[2][tid] + po[3][tid];
            size_t idx = ((size_t)b * SS + p + 1) * 1024 + h * 64 + tid;
            split1(r, atth + idx, attl + idx);
        }
        __syncthreads();
    }
}

// ---------------------------------------------------------------------------
// Orchestration
// ---------------------------------------------------------------------------
extern "C" void kernel_launch(void* const* d_in, const int* in_sizes, int n_in,
                              void* d_out, int out_size) {
    const float* x        = (const float*)d_in[0];
    const float* n1w      = (const float*)d_in[1];
    const float* n1b      = (const float*)d_in[2];
    const float* rq_w     = (const float*)d_in[3];
    const float* rq_b     = (const float*)d_in[4];
    const float* rk_w     = (const float*)d_in[5];
    const float* rk_b     = (const float*)d_in[6];
    const float* pos_bias = (const float*)d_in[7];
    const float* qkv_w    = (const float*)d_in[8];
    const float* qkv_b    = (const float*)d_in[9];
    const float* proj_w   = (const float*)d_in[10];
    const float* proj_b   = (const float*)d_in[11];
    const float* n2w      = (const float*)d_in[12];
    const float* n2b      = (const float*)d_in[13];
    const float* fc1_w    = (const float*)d_in[14];
    const float* fc1_b    = (const float*)d_in[15];
    const float* fc2_w    = (const float*)d_in[16];
    const float* fc2_b    = (const float*)d_in[17];
    float* out = (float*)d_out;

    void* sp = nullptr;
    cudaGetSymbolAddress(&sp, g_scratch);
    float* SCR = (float*)sp;
    float* QRf = SCR + O_QR;
    float* KRf = SCR + O_KR;
    float* SC  = SCR + O_SC;
    float* QKV = SCR + O_QKV;
    float* LW  = SCR + O_LW;
    int*   RT  = (int*)(SCR + O_RT);
    __nv_bfloat16* XNh  = (__nv_bfloat16*)(SCR + O_XNH);
    __nv_bfloat16* XNl  = (__nv_bfloat16*)(SCR + O_XNL);
    __nv_bfloat16* QKRh = (__nv_bfloat16*)(SCR + O_QKRH);
    __nv_bfloat16* QKRl = (__nv_bfloat16*)(SCR + O_QKRL);
    __nv_bfloat16* ATTh = (__nv_bfloat16*)(SCR + O_ATTH);
    __nv_bfloat16* ATTl = (__nv_bfloat16*)(SCR + O_ATTL);
    __nv_bfloat16* HNh  = (__nv_bfloat16*)(SCR + O_HNH);
    __nv_bfloat16* HNl  = (__nv_bfloat16*)(SCR + O_HNL);
    __nv_bfloat16* HHh  = (__nv_bfloat16*)(SCR + O_HHH);
    __nv_bfloat16* HHl  = (__nv_bfloat16*)(SCR + O_HHL);
    __nv_bfloat16* WH   = (__nv_bfloat16*)(SCR + O_WH);
    __nv_bfloat16* WL   = (__nv_bfloat16*)(SCR + O_WL);

    cudaFuncSetAttribute(gemm_bf3<EPI_BIAS>,
                         cudaFuncAttributeMaxDynamicSharedMemorySize, GEMM_SMEM_BYTES);
    cudaFuncSetAttribute(gemm_bf3<EPI_BIAS_RESID>,
                         cudaFuncAttributeMaxDynamicSharedMemorySize, GEMM_SMEM_BYTES);
    cudaFuncSetAttribute(gemm_bf3<EPI_GELU_SPLIT>,
                         cudaFuncAttributeMaxDynamicSharedMemorySize, GEMM_SMEM_BYTES);
    cudaFuncSetAttribute(gemm_bf3<EPI_SCORES>,
                         cudaFuncAttributeMaxDynamicSharedMemorySize, GEMM_SMEM_BYTES);

    // 0. pre-split all weights into hi/lo bf16 planes
    split_w_kernel<<<512, 256>>>(rq_w,   WH + W_RQ,   WL + W_RQ,   1048576 / 4);
    split_w_kernel<<<512, 256>>>(rk_w,   WH + W_RK,   WL + W_RK,   1048576 / 4);
    split_w_kernel<<<1024, 256>>>(qkv_w, WH + W_QKV,  WL + W_QKV,  3145728 / 4);
    split_w_kernel<<<512, 256>>>(proj_w, WH + W_PROJ, WL + W_PROJ, 1048576 / 4);
    split_w_kernel<<<1024, 256>>>(fc1_w, WH + W_FC1,  WL + W_FC1,  4194304 / 4);
    split_w_kernel<<<1024, 256>>>(fc2_w, WH + W_FC2,  WL + W_FC2,  4194304 / 4);

    // 1. LayerNorm 1 -> XN hi/lo
    layernorm_split_kernel<<<BB * SS, 256>>>(x, n1w, n1b, XNh, XNl);

    // 2. Routing projections (per batch via z-stride) -> f32
    dim3 gR(8, 8, 2);
    gemm_bf3<EPI_BIAS><<<gR, 256, GEMM_SMEM_BYTES>>>(
        XNh + 1024, XNl + 1024, WH + W_RQ, WL + W_RQ, rq_b, nullptr,
        QRf, nullptr, nullptr, 1024, 1024, 1024, (long)SS * DD, 0, (long)PP * DD);
    gemm_bf3<EPI_BIAS><<<gR, 256, GEMM_SMEM_BYTES>>>(
        XNh + 1024, XNl + 1024, WH + W_RK, WL + W_RK, rk_b, nullptr,
        KRf, nullptr, nullptr, 1024, 1024, 1024, (long)SS * DD, 0, (long)PP * DD);

    // 3. L2 normalize (QRf and KRf contiguous: 4096 rows) -> QKR hi/lo
    l2norm_split_kernel<<<2 * BB * PP, 256>>>(QRf, QKRh, QKRl);

    // 4. Routing scores (A = q_r rows, B = k_r rows at +2048*1024)
    gemm_bf3<EPI_SCORES><<<gR, 256, GEMM_SMEM_BYTES>>>(
        QKRh, QKRl, QKRh + 2048ull * 1024, QKRl + 2048ull * 1024, nullptr, pos_bias,
        SC, nullptr, nullptr, 1024, 1024, 1024,
        (long)PP * DD, (long)PP * DD, (long)PP * PP);

    // 5. Top-32 + routing weights
    topk_kernel<<<BB * PP, 256>>>(SC, RT, LW);

    // 6. QKV projection -> f32 (consumed by attention)
    dim3 gQ(24, 17, 1);
    gemm_bf3<EPI_BIAS><<<gQ, 256, GEMM_SMEM_BYTES>>>(
        XNh, XNl, WH + W_QKV, WL + W_QKV, qkv_b, nullptr,
        QKV, nullptr, nullptr, 2050, 3072, 1024, 0, 0, 0);

    // 7. CLS attention -> ATT hi/lo
    cls_attn_kernel<<<BB * HH_, 256>>>(QKV, ATTh, ATTl);

    // 8. Routed patch attention -> ATT hi/lo
    patch_attn_kernel<<<BB * PP, 256>>>(QKV, RT, LW, ATTh, ATTl);

    // 9. Output projection + residual -> d_out (f32)
    dim3 gP(8, 17, 1);
    gemm_bf3<EPI_BIAS_RESID><<<gP, 256, GEMM_SMEM_BYTES>>>(
        ATTh, ATTl, WH + W_PROJ, WL + W_PROJ, proj_b, x,
        out, nullptr, nullptr, 2050, 1024, 1024, 0, 0, 0);

    // 10. LayerNorm 2 -> HN hi/lo
    layernorm_split_kernel<<<BB * SS, 256>>>(out, n2w, n2b, HNh, HNl);

    // 11. FC1 + exact GELU -> HH hi/lo (split in epilogue)
    dim3 gF1(32, 17, 1);
    gemm_bf3<EPI_GELU_SPLIT><<<gF1, 256, GEMM_SMEM_BYTES>>>(
        HNh, HNl, WH + W_FC1, WL + W_FC1, fc1_b, nullptr,
        nullptr, HHh, HHl, 2050, 4096, 1024, 0, 0, 0);

    // 12. FC2 + residual -> d_out (f32)
    dim3 gF2(8, 17, 1);
    gemm_bf3<EPI_BIAS_RESID><<<gF2, 256, GEMM_SMEM_BYTES>>>(
        HHh, HHl, WH + W_FC2, WL + W_FC2, fc2_b, out,
        out, nullptr, nullptr, 2050, 1024, 4096, 0, 0, 0);

    (void)in_sizes; (void)n_in; (void)out_size;
}

// round 12
// speedup vs baseline: 1.1344x; 1.1344x over previous
#include <cuda_runtime.h>
#include <cuda_bf16.h>
#include <stdint.h>
#include <math.h>

// ---------------------------------------------------------------------------
// Problem constants
// ---------------------------------------------------------------------------
#define BB   2
#define SS   1025
#define DD   1024
#define HH_  16
#define HD_  64
#define PP   1024
#define KR_  32
#define SCALE_ 0.125f
#define INV_TEMP 10.0f

// ---------------------------------------------------------------------------
// Scratch (float units). bf16 buffers live inside the float array.
// ---------------------------------------------------------------------------
static const size_t F_QR   = 2048ull * 1024;
static const size_t F_KR   = 2048ull * 1024;
static const size_t F_SC   = 2048ull * 1024;
static const size_t F_QKV  = 2050ull * 3072;
static const size_t F_LW   = 2048ull * 32;
static const size_t F_RT   = 2048ull * 32;
static const size_t H_XN   = 2050ull * 1024 / 2;
static const size_t H_QKR  = 4096ull * 1024 / 2;
static const size_t H_ATT  = 2050ull * 1024 / 2;
static const size_t H_HN   = 2050ull * 1024 / 2;
static const size_t H_HH   = 2050ull * 4096 / 2;
static const size_t H_W    = 14680064ull / 2;

static const size_t O_QR   = 0;
static const size_t O_KR   = O_QR  + F_QR;
static const size_t O_SC   = O_KR  + F_KR;
static const size_t O_QKV  = O_SC  + F_SC;
static const size_t O_LW   = O_QKV + F_QKV;
static const size_t O_RT   = O_LW  + F_LW;
static const size_t O_XNH  = O_RT  + F_RT;
static const size_t O_XNL  = O_XNH + H_XN;
static const size_t O_QKRH = O_XNL + H_XN;
static const size_t O_QKRL = O_QKRH + H_QKR;
static const size_t O_ATTH = O_QKRL + H_QKR;
static const size_t O_ATTL = O_ATTH + H_ATT;
static const size_t O_HNH  = O_ATTL + H_ATT;
static const size_t O_HNL  = O_HNH + H_HN;
static const size_t O_HHH  = O_HNL + H_HN;
static const size_t O_HHL  = O_HHH + H_HH;
static const size_t O_WH   = O_HHL + H_HH;
static const size_t O_WL   = O_WH  + H_W;
static const size_t SCR_TOTAL = O_WL + H_W;

static const size_t W_RQ   = 0;
static const size_t W_RK   = 1048576;
static const size_t W_QKV  = 2097152;
static const size_t W_PROJ = 5242880;
static const size_t W_FC1  = 6291456;
static const size_t W_FC2  = 10485760;

__device__ float g_scratch[SCR_TOTAL];

// ---------------------------------------------------------------------------
// Block reductions (blockDim.x == 256)
// ---------------------------------------------------------------------------
__device__ __forceinline__ float blockReduceSum(float v, float* sbuf) {
    int lane = threadIdx.x & 31, wid = threadIdx.x >> 5;
    #pragma unroll
    for (int o = 16; o; o >>= 1) v += __shfl_xor_sync(0xffffffffu, v, o);
    if (lane == 0) sbuf[wid] = v;
    __syncthreads();
    if (wid == 0) {
        v = (lane < 8) ? sbuf[lane] : 0.f;
        #pragma unroll
        for (int o = 4; o; o >>= 1) v += __shfl_xor_sync(0xffffffffu, v, o);
        if (lane == 0) sbuf[0] = v;
    }
    __syncthreads();
    float r = sbuf[0];
    __syncthreads();
    return r;
}

__device__ __forceinline__ float blockReduceMax(float v, float* sbuf) {
    int lane = threadIdx.x & 31, wid = threadIdx.x >> 5;
    #pragma unroll
    for (int o = 16; o; o >>= 1) v = fmaxf(v, __shfl_xor_sync(0xffffffffu, v, o));
    if (lane == 0) sbuf[wid] = v;
    __syncthreads();
    if (wid == 0) {
        v = (lane < 8) ? sbuf[lane] : -3.4e38f;
        #pragma unroll
        for (int o = 4; o; o >>= 1) v = fmaxf(v, __shfl_xor_sync(0xffffffffu, v, o));
        if (lane == 0) sbuf[0] = v;
    }
    __syncthreads();
    float r = sbuf[0];
    __syncthreads();
    return r;
}

__device__ __forceinline__ void split1(float v, __nv_bfloat16* hi, __nv_bfloat16* lo) {
    __nv_bfloat16 h = __float2bfloat16(v);
    *hi = h;
    *lo = __float2bfloat16(v - __bfloat162float(h));
}

// ---------------------------------------------------------------------------
// Fused weight split: all 6 weights in one launch
// ---------------------------------------------------------------------------
struct WSplit6 {
    const float* src[6];
    long dstoff[6];
    int n4[6];
};

__global__ void split_all_w_kernel(WSplit6 a,
                                   __nv_bfloat16* __restrict__ hi,
                                   __nv_bfloat16* __restrict__ lo) {
    #pragma unroll
    for (int s = 0; s < 6; s++) {
        const float4* sp = (const float4*)a.src[s];
        __nv_bfloat16* hp = hi + a.dstoff[s];
        __nv_bfloat16* lp = lo + a.dstoff[s];
        const int n4 = a.n4[s];
        for (int i = blockIdx.x * blockDim.x + threadIdx.x; i < n4;
             i += gridDim.x * blockDim.x) {
            float4 f = sp[i];
            __nv_bfloat162 h0 = __floats2bfloat162_rn(f.x, f.y);
            __nv_bfloat162 h1 = __floats2bfloat162_rn(f.z, f.w);
            __nv_bfloat162 l0 = __floats2bfloat162_rn(f.x - __bfloat162float(h0.x),
                                                      f.y - __bfloat162float(h0.y));
            __nv_bfloat162 l1 = __floats2bfloat162_rn(f.z - __bfloat162float(h1.x),
                                                      f.w - __bfloat162float(h1.y));
            uint2 hv; hv.x = *(unsigned*)&h0; hv.y = *(unsigned*)&h1;
            uint2 lv; lv.x = *(unsigned*)&l0; lv.y = *(unsigned*)&l1;
            *(uint2*)(hp + (size_t)i * 4) = hv;
            *(uint2*)(lp + (size_t)i * 4) = lv;
        }
    }
}

// ---------------------------------------------------------------------------
// LayerNorm -> hi/lo bf16 planes
// ---------------------------------------------------------------------------
__global__ void layernorm_split_kernel(const float* __restrict__ in,
                                       const float* __restrict__ w,
                                       const float* __restrict__ b,
                                       __nv_bfloat16* __restrict__ outh,
                                       __nv_bfloat16* __restrict__ outl) {
    __shared__ float red[32];
    int row = blockIdx.x, tid = threadIdx.x;
    const float4* ip = (const float4*)(in + (size_t)row * 1024);
    float4 v = ip[tid];
    float s = v.x + v.y + v.z + v.w;
    float mean = blockReduceSum(s, red) * (1.f / 1024.f);
    float dx = v.x - mean, dy = v.y - mean, dz = v.z - mean, dw = v.w - mean;
    float ss = dx * dx + dy * dy + dz * dz + dw * dw;
    float var = blockReduceSum(ss, red) * (1.f / 1024.f);
    float rstd = rsqrtf(var + 1e-5f);
    float4 wv = ((const float4*)w)[tid];
    float4 bv = ((const float4*)b)[tid];
    float ox = dx * rstd * wv.x + bv.x;
    float oy = dy * rstd * wv.y + bv.y;
    float oz = dz * rstd * wv.z + bv.z;
    float ow = dw * rstd * wv.w + bv.w;
    __nv_bfloat162 h0 = __floats2bfloat162_rn(ox, oy);
    __nv_bfloat162 h1 = __floats2bfloat162_rn(oz, ow);
    __nv_bfloat162 l0 = __floats2bfloat162_rn(ox - __bfloat162float(h0.x),
                                              oy - __bfloat162float(h0.y));
    __nv_bfloat162 l1 = __floats2bfloat162_rn(oz - __bfloat162float(h1.x),
                                              ow - __bfloat162float(h1.y));
    uint2 hv; hv.x = *(unsigned*)&h0; hv.y = *(unsigned*)&h1;
    uint2 lv; lv.x = *(unsigned*)&l0; lv.y = *(unsigned*)&l1;
    *(uint2*)(outh + (size_t)row * 1024 + tid * 4) = hv;
    *(uint2*)(outl + (size_t)row * 1024 + tid * 4) = lv;
}

// ---------------------------------------------------------------------------
// L2 norm -> hi/lo bf16 planes
// ---------------------------------------------------------------------------
__global__ void l2norm_split_kernel(const float* __restrict__ buf,
                                    __nv_bfloat16* __restrict__ outh,
                                    __nv_bfloat16* __restrict__ outl) {
    __shared__ float red[32];
    int row = blockIdx.x, tid = threadIdx.x;
    const float4* p = (const float4*)(buf + (size_t)row * 1024);
    float4 v = p[tid];
    float ss = v.x * v.x + v.y * v.y + v.z * v.z + v.w * v.w;
    float tot = blockReduceSum(ss, red);
    float sc = 1.f / fmaxf(sqrtf(tot), 1e-12f);
    float ox = v.x * sc, oy = v.y * sc, oz = v.z * sc, ow = v.w * sc;
    __nv_bfloat162 h0 = __floats2bfloat162_rn(ox, oy);
    __nv_bfloat162 h1 = __floats2bfloat162_rn(oz, ow);
    __nv_bfloat162 l0 = __floats2bfloat162_rn(ox - __bfloat162float(h0.x),
                                              oy - __bfloat162float(h0.y));
    __nv_bfloat162 l1 = __floats2bfloat162_rn(oz - __bfloat162float(h1.x),
                                              ow - __bfloat162float(h1.y));
    uint2 hv; hv.x = *(unsigned*)&h0; hv.y = *(unsigned*)&h1;
    uint2 lv; lv.x = *(unsigned*)&l0; lv.y = *(unsigned*)&l1;
    *(uint2*)(outh + (size_t)row * 1024 + tid * 4) = hv;
    *(uint2*)(outl + (size_t)row * 1024 + tid * 4) = lv;
}

// ---------------------------------------------------------------------------
// bf16x3 tensor-core NT GEMM, pure cp.async loader + ldmatrix fragments.
// (unchanged from round 10 — passing, rel_err 4.1e-4)
// ---------------------------------------------------------------------------
#define EPI_BIAS        1
#define EPI_BIAS_RESID  2
#define EPI_GELU_SPLIT  3
#define EPI_SCORES      4

#define KSTRIDE 40
#define TILE_BF16 (128 * KSTRIDE)
#define SB_BASE (4 * TILE_BF16)
#define GEMM_SMEM_BYTES (8 * TILE_BF16 * 2)   // 81920

__device__ __forceinline__ void mma_bf16(float* d, const unsigned* a, const unsigned* b) {
    asm volatile(
        "mma.sync.aligned.m16n8k16.row.col.f32.bf16.bf16.f32 "
        "{%0,%1,%2,%3}, {%4,%5,%6,%7}, {%8,%9}, {%0,%1,%2,%3};"
        : "+f"(d[0]), "+f"(d[1]), "+f"(d[2]), "+f"(d[3])
        : "r"(a[0]), "r"(a[1]), "r"(a[2]), "r"(a[3]), "r"(b[0]), "r"(b[1]));
}

__device__ __forceinline__ void ldsm4(unsigned addr, unsigned& r0, unsigned& r1,
                                      unsigned& r2, unsigned& r3) {
    asm volatile("ldmatrix.sync.aligned.m8n8.x4.shared.b16 {%0,%1,%2,%3}, [%4];"
                 : "=r"(r0), "=r"(r1), "=r"(r2), "=r"(r3) : "r"(addr));
}

__device__ __forceinline__ void cpasync16(unsigned dst, const void* src, unsigned sz) {
    asm volatile("cp.async.ca.shared.global [%0], [%1], 16, %2;"
                 :: "r"(dst), "l"(src), "r"(sz));
}

template <int EPI>
__global__ __launch_bounds__(256) void gemm_bf3(
    const __nv_bfloat16* __restrict__ Ah, const __nv_bfloat16* __restrict__ Al,
    const __nv_bfloat16* __restrict__ Bh, const __nv_bfloat16* __restrict__ Bl,
    const float* __restrict__ bias, const float* __restrict__ extra,
    float* __restrict__ C, __nv_bfloat16* __restrict__ Ch, __nv_bfloat16* __restrict__ Cl,
    int M, int N, int Kd, long sA, long sB, long sC) {

    Ah += (long)blockIdx.z * sA;  Al += (long)blockIdx.z * sA;
    Bh += (long)blockIdx.z * sB;  Bl += (long)blockIdx.z * sB;
    const long cOff = (long)blockIdx.z * sC;

    extern __shared__ __nv_bfloat16 sm[];

    const int tid  = threadIdx.x;
    const int lane = tid & 31;
    const int wid  = tid >> 5;
    const int wr   = wid & 3;
    const int wc   = wid >> 2;
    const int g    = lane >> 2;
    const int tig  = lane & 3;
    const int bm   = blockIdx.y * 128;
    const int bn   = blockIdx.x * 128;

    float acc[2][8][4];
    #pragma unroll
    for (int mi = 0; mi < 2; mi++)
        #pragma unroll
        for (int ni = 0; ni < 8; ni++)
            #pragma unroll
            for (int r = 0; r < 4; r++) acc[mi][ni][r] = 0.f;

    const int ldRow = tid >> 1;
    const int half  = tid & 1;
    const int aRow  = bm + ldRow;
    const unsigned aSz = (aRow < M) ? 16u : 0u;
    const long aOff = (long)((aRow < M) ? aRow : 0) * Kd + half * 16;
    const long bOff = (long)(bn + ldRow) * Kd + half * 16;
    const __nv_bfloat16* aH = Ah + aOff;
    const __nv_bfloat16* aL = Al + aOff;
    const __nv_bfloat16* bH = Bh + bOff;
    const __nv_bfloat16* bL = Bl + bOff;

    const unsigned smBase = (unsigned)__cvta_generic_to_shared(sm);
    const unsigned dA0 = smBase + 2u * (unsigned)(ldRow * KSTRIDE + half * 16);
    const unsigned stagePitch = 2u * (unsigned)(2 * TILE_BF16);
    const unsigned hlPitch    = 2u * (unsigned)TILE_BF16;
    const unsigned bPlane     = 2u * (unsigned)SB_BASE;

    const int aRowL = wr * 32 + (lane & 7) + ((lane >> 3) & 1) * 8;
    const int aKL   = ((lane >> 4) & 1) * 8;
    const unsigned aLaneOff = (unsigned)(aRowL * KSTRIDE + aKL);
    const int bRowL = wc * 64 + (lane & 7) + ((lane >> 4) & 1) * 8;
    const int bKL   = ((lane >> 3) & 1) * 8;
    const unsigned bLaneOff = (unsigned)(bRowL * KSTRIDE + bKL);

    const int nIter = Kd >> 5;

    #define ISSUE(st, itv) do {                                              \
        const long k0 = (long)(itv) * 32;                                    \
        unsigned d0 = dA0 + (unsigned)(st) * stagePitch;                     \
        cpasync16(d0,            aH + k0,     aSz);                          \
        cpasync16(d0 + 16,       aH + k0 + 8, aSz);                          \
        cpasync16(d0 + hlPitch,      aL + k0,     aSz);                      \
        cpasync16(d0 + hlPitch + 16, aL + k0 + 8, aSz);                      \
        unsigned d1 = d0 + bPlane;                                           \
        cpasync16(d1,            bH + k0,     16u);                          \
        cpasync16(d1 + 16,       bH + k0 + 8, 16u);                          \
        cpasync16(d1 + hlPitch,      bL + k0,     16u);                      \
        cpasync16(d1 + hlPitch + 16, bL + k0 + 8, 16u);                      \
        asm volatile("cp.async.commit_group;");                              \
    } while (0)

    ISSUE(0, 0);
    if (nIter > 1) ISSUE(1, 1);

    for (int it = 0; it < nIter; ++it) {
        if (it == nIter - 1) asm volatile("cp.async.wait_group 0;");
        else                 asm volatile("cp.async.wait_group 1;");
        __syncthreads();

        const int s = it & 1;
        const unsigned pA_hi = (unsigned)((s * 2 + 0) * TILE_BF16);
        const unsigned pA_lo = (unsigned)((s * 2 + 1) * TILE_BF16);
        const unsigned pB_hi = (unsigned)(SB_BASE + (s * 2 + 0) * TILE_BF16);
        const unsigned pB_lo = (unsigned)(SB_BASE + (s * 2 + 1) * TILE_BF16);

        #pragma unroll
        for (int ks = 0; ks < 2; ks++) {
            const int kb = ks * 16;
            unsigned Ahf[2][4], Alf[2][4], Bhf[8][2], Blf[8][2];
            #pragma unroll
            for (int mi = 0; mi < 2; mi++) {
                unsigned off = (unsigned)(mi * 16 * KSTRIDE + kb) + aLaneOff;
                ldsm4(smBase + 2u * (pA_hi + off), Ahf[mi][0], Ahf[mi][1], Ahf[mi][2], Ahf[mi][3]);
                ldsm4(smBase + 2u * (pA_lo + off), Alf[mi][0], Alf[mi][1], Alf[mi][2], Alf[mi][3]);
            }
            #pragma unroll
            for (int j = 0; j < 4; j++) {
                unsigned off = (unsigned)(j * 16 * KSTRIDE + kb) + bLaneOff;
                ldsm4(smBase + 2u * (pB_hi + off),
                      Bhf[j * 2][0], Bhf[j * 2][1], Bhf[j * 2 + 1][0], Bhf[j * 2 + 1][1]);
                ldsm4(smBase + 2u * (pB_lo + off),
                      Blf[j * 2][0], Blf[j * 2][1], Blf[j * 2 + 1][0], Blf[j * 2 + 1][1]);
            }
            #pragma unroll
            for (int mi = 0; mi < 2; mi++)
                #pragma unroll
                for (int ni = 0; ni < 8; ni++) {
                    mma_bf16(acc[mi][ni], Ahf[mi], Bhf[ni]);
                    mma_bf16(acc[mi][ni], Alf[mi], Bhf[ni]);
                    mma_bf16(acc[mi][ni], Ahf[mi], Blf[ni]);
                }
        }
        __syncthreads();

        if (it + 2 < nIter) ISSUE(s, it + 2);
    }
    #undef ISSUE

    #pragma unroll
    for (int mi = 0; mi < 2; mi++) {
        #pragma unroll
        for (int rr = 0; rr < 2; rr++) {
            const int m = bm + wr * 32 + mi * 16 + g + rr * 8;
            if (m >= M) continue;
            #pragma unroll
            for (int ni = 0; ni < 8; ni++) {
                #pragma unroll
                for (int cc = 0; cc < 2; cc++) {
                    const int n = bn + wc * 64 + ni * 8 + tig * 2 + cc;
                    float v = acc[mi][ni][rr * 2 + cc];
                    const long idx = cOff + (long)m * N + n;
                    if (EPI == EPI_BIAS) {
                        C[idx] = v + bias[n];
                    } else if (EPI == EPI_BIAS_RESID) {
                        C[idx] = v + bias[n] + extra[(long)m * N + n];
                    } else if (EPI == EPI_GELU_SPLIT) {
                        v += bias[n];
                        v = 0.5f * v * (1.0f + erff(v * 0.70710678118654752f));
                        split1(v, Ch + idx, Cl + idx);
                    } else if (EPI == EPI_SCORES) {
                        v += extra[(long)m * N + n];
                        if (m == n) v = -1e9f;
                        C[idx] = v;
                    }
                }
            }
        }
    }
}

// ---------------------------------------------------------------------------
// Top-K=32: 8 warps extract per-slice top-32 (no block syncs), 1 warp merges.
// Tie-break: lower index (matches lax.top_k).
// ---------------------------------------------------------------------------
__global__ void topk_kernel(const float* __restrict__ scores,
                            int* __restrict__ routes,
                            float* __restrict__ logw) {
    __shared__ float wv[8][32];
    __shared__ int   wi[8][32];
    __shared__ float sv[32];
    __shared__ int   si[32];
    const int row = blockIdx.x, tid = threadIdx.x;
    const int lane = tid & 31, w = tid >> 5;
    const float* src = scores + (size_t)row * 1024;

    // each lane holds 4 elements of its warp's 128-slice (coalesced)
    float v[4]; int id4[4];
    #pragma unroll
    for (int c = 0; c < 4; c++) {
        int id = w * 128 + c * 32 + lane;
        v[c] = src[id];
        id4[c] = id;
    }

    // 32 iterations of warp argmax -> sorted descending list per warp
    for (int it = 0; it < 32; it++) {
        float bv = v[0]; int bi = id4[0]; int bs = 0;
        #pragma unroll
        for (int c = 1; c < 4; c++)
            if (v[c] > bv || (v[c] == bv && id4[c] < bi)) { bv = v[c]; bi = id4[c]; bs = c; }
        float cv = bv; int ci = bi;
        #pragma unroll
        for (int o = 16; o; o >>= 1) {
            float ov = __shfl_xor_sync(0xffffffffu, cv, o);
            int   oi = __shfl_xor_sync(0xffffffffu, ci, o);
            if (ov > cv || (ov == cv && oi < ci)) { cv = ov; ci = oi; }
        }
        if (lane == 0) { wv[w][it] = cv; wi[w][it] = ci; }
        if (ci == bi) v[bs] = -3.4e38f;     // winner lane retires its slot
    }
    __syncthreads();

    // warp 0: 8-way merge of sorted lists, 32 picks
    if (w == 0) {
        int ptr = 0;
        for (int it = 0; it < 32; it++) {
            float cv = (lane < 8 && ptr < 32) ? wv[lane][ptr] : -3.4e38f;
            int   ci = (lane < 8 && ptr < 32) ? wi[lane][ptr] : 0x7fffffff;
            float bv = cv; int bi = ci;
            #pragma unroll
            for (int o = 4; o; o >>= 1) {
                float ov = __shfl_xor_sync(0xffffffffu, bv, o);
                int   oi = __shfl_xor_sync(0xffffffffu, bi, o);
                if (ov > bv || (ov == bv && oi < bi)) { bv = ov; bi = oi; }
            }
            if (lane < 8 && ci == bi && ptr < 32) ptr++;
            if (lane == 0) { sv[it] = bv; si[it] = bi; }
        }
    }
    __syncthreads();

    if (tid < 32) {
        float t = sv[tid] * INV_TEMP;
        float tmax = sv[0] * INV_TEMP;
        float e = expf(t - tmax);
        float z = e;
        #pragma unroll
        for (int o = 16; o; o >>= 1) z += __shfl_xor_sync(0xffffffffu, z, o);
        float lw = t - (tmax + logf(z));
        routes[(size_t)row * 32 + tid] = si[tid];
        logw[(size_t)row * 32 + tid] = fmaxf(lw, -10.f);
    }
}

// ---------------------------------------------------------------------------
// CLS attention -> hi/lo ATT planes (unchanged)
// ---------------------------------------------------------------------------
__global__ void cls_attn_kernel(const float* __restrict__ qkv,
                                __nv_bfloat16* __restrict__ atth,
                                __nv_bfloat16* __restrict__ attl) {
    __shared__ float q[64];
    __shared__ float sp[SS];
    __shared__ float red[32];
    __shared__ float po[4][64];
    int bh = blockIdx.x, b = bh >> 4, h = bh & 15;
    int tid = threadIdx.x;
    const float* base = qkv + (size_t)b * SS * 3072;
    if (tid < 64) q[tid] = base[h * 64 + tid];
    __syncthreads();

    float lmax = -3.4e38f;
    for (int j = tid; j < SS; j += 256) {
        const float* kr = base + (size_t)j * 3072 + 1024 + h * 64;
        float d = 0.f;
        #pragma unroll
        for (int dd = 0; dd < 64; dd++) d += q[dd] * kr[dd];
        d *= SCALE_;
        sp[j] = d;
        lmax = fmaxf(lmax, d);
    }
    float M = blockReduceMax(lmax, red);
    float ls = 0.f;
    for (int j = tid; j < SS; j += 256) {
        float e = expf(sp[j] - M);
        sp[j] = e;
        ls += e;
    }
    float Z = blockReduceSum(ls, red);

    int g = tid >> 6, d = tid & 63;
    float o = 0.f;
    for (int j = g; j < SS; j += 4)
        o += sp[j] * base[(size_t)j * 3072 + 2048 + h * 64 + d];
    po[g][d] = o;
    __syncthreads();
    if (tid < 64) {
        float r = (po[0][tid] + po[1][tid] + po[2][tid] + po[3][tid]) / Z;
        size_t idx = (size_t)b * SS * 1024 + h * 64 + tid;
        split1(r, atth + idx, attl + idx);
    }
}

// ---------------------------------------------------------------------------
// Routed patch attention: 512 threads, one warp per head, no block syncs
// after route load. K/V read direct from gmem (L2-resident), 8-route batches.
// ---------------------------------------------------------------------------
__global__ __launch_bounds__(512) void patch_attn_kernel(
        const float* __restrict__ qkv,
        const int* __restrict__ routes,
        const float* __restrict__ logw,
        __nv_bfloat16* __restrict__ atth,
        __nv_bfloat16* __restrict__ attl) {
    __shared__ int   rt[32];
    __shared__ float lw[32];
    const int bp = blockIdx.x, b = bp >> 10, p = bp & 1023;
    const int tid = threadIdx.x, lane = tid & 31, h = tid >> 5;   // 16 warps = heads
    if (tid < 32) {
        rt[tid] = routes[(size_t)bp * 32 + tid] + 1;
        lw[tid] = logw[(size_t)bp * 32 + tid];
    }
    __syncthreads();

    const float* base = qkv + (size_t)b * SS * 3072;
    const float* qp = base + (size_t)(p + 1) * 3072 + h * 64;
    const float q0 = qp[lane], q1 = qp[lane + 32];

    // scores (route kk's score kept by lane kk)
    float myscore = 0.f;
    #pragma unroll
    for (int kb = 0; kb < 32; kb += 8) {
        float k0[8], k1[8];
        #pragma unroll
        for (int j = 0; j < 8; j++) {
            const float* kp = base + (size_t)rt[kb + j] * 3072 + 1024 + h * 64;
            k0[j] = kp[lane];
            k1[j] = kp[lane + 32];
        }
        #pragma unroll
        for (int j = 0; j < 8; j++) {
            float d = q0 * k0[j] + q1 * k1[j];
            #pragma unroll
            for (int o = 16; o; o >>= 1) d += __shfl_xor_sync(0xffffffffu, d, o);
            if (lane == kb + j) myscore = d * SCALE_ + lw[lane];
        }
    }

    // softmax over the 32 per-lane scores
    float m = myscore;
    #pragma unroll
    for (int o = 16; o; o >>= 1) m = fmaxf(m, __shfl_xor_sync(0xffffffffu, m, o));
    float e = expf(myscore - m);
    float z = e;
    #pragma unroll
    for (int o = 16; o; o >>= 1) z += __shfl_xor_sync(0xffffffffu, z, o);
    const float pw = e / z;

    // output accumulation
    float o0 = 0.f, o1 = 0.f;
    #pragma unroll
    for (int kb = 0; kb < 32; kb += 8) {
        float v0[8], v1[8];
        #pragma unroll
        for (int j = 0; j < 8; j++) {
            const float* vp = base + (size_t)rt[kb + j] * 3072 + 2048 + h * 64;
            v0[j] = vp[lane];
            v1[j] = vp[lane + 32];
        }
        #pragma unroll
        for (int j = 0; j < 8; j++) {
            float wj = __shfl_sync(0xffffffffu, pw, kb + j);
            o0 += wj * v0[j];
            o1 += wj * v1[j];
        }
    }

    const size_t idx = ((size_t)b * SS + p + 1) * 1024 + h * 64 + lane;
    split1(o0, atth + idx, attl + idx);
    split1(o1, atth + idx + 32, attl + idx + 32);
}

// ---------------------------------------------------------------------------
// Orchestration
// ---------------------------------------------------------------------------
extern "C" void kernel_launch(void* const* d_in, const int* in_sizes, int n_in,
                              void* d_out, int out_size) {
    const float* x        = (const float*)d_in[0];
    const float* n1w      = (const float*)d_in[1];
    const float* n1b      = (const float*)d_in[2];
    const float* rq_w     = (const float*)d_in[3];
    const float* rq_b     = (const float*)d_in[4];
    const float* rk_w     = (const float*)d_in[5];
    const float* rk_b     = (const float*)d_in[6];
    const float* pos_bias = (const float*)d_in[7];
    const float* qkv_w    = (const float*)d_in[8];
    const float* qkv_b    = (const float*)d_in[9];
    const float* proj_w   = (const float*)d_in[10];
    const float* proj_b   = (const float*)d_in[11];
    const float* n2w      = (const float*)d_in[12];
    const float* n2b      = (const float*)d_in[13];
    const float* fc1_w    = (const float*)d_in[14];
    const float* fc1_b    = (const float*)d_in[15];
    const float* fc2_w    = (const float*)d_in[16];
    const float* fc2_b    = (const float*)d_in[17];
    float* out = (float*)d_out;

    void* sp = nullptr;
    cudaGetSymbolAddress(&sp, g_scratch);
    float* SCR = (float*)sp;
    float* QRf = SCR + O_QR;
    float* KRf = SCR + O_KR;
    float* SC  = SCR + O_SC;
    float* QKV = SCR + O_QKV;
    float* LW  = SCR + O_LW;
    int*   RT  = (int*)(SCR + O_RT);
    __nv_bfloat16* XNh  = (__nv_bfloat16*)(SCR + O_XNH);
    __nv_bfloat16* XNl  = (__nv_bfloat16*)(SCR + O_XNL);
    __nv_bfloat16* QKRh = (__nv_bfloat16*)(SCR + O_QKRH);
    __nv_bfloat16* QKRl = (__nv_bfloat16*)(SCR + O_QKRL);
    __nv_bfloat16* ATTh = (__nv_bfloat16*)(SCR + O_ATTH);
    __nv_bfloat16* ATTl = (__nv_bfloat16*)(SCR + O_ATTL);
    __nv_bfloat16* HNh  = (__nv_bfloat16*)(SCR + O_HNH);
    __nv_bfloat16* HNl  = (__nv_bfloat16*)(SCR + O_HNL);
    __nv_bfloat16* HHh  = (__nv_bfloat16*)(SCR + O_HHH);
    __nv_bfloat16* HHl  = (__nv_bfloat16*)(SCR + O_HHL);
    __nv_bfloat16* WH   = (__nv_bfloat16*)(SCR + O_WH);
    __nv_bfloat16* WL   = (__nv_bfloat16*)(SCR + O_WL);

    cudaFuncSetAttribute(gemm_bf3<EPI_BIAS>,
                         cudaFuncAttributeMaxDynamicSharedMemorySize, GEMM_SMEM_BYTES);
    cudaFuncSetAttribute(gemm_bf3<EPI_BIAS_RESID>,
                         cudaFuncAttributeMaxDynamicSharedMemorySize, GEMM_SMEM_BYTES);
    cudaFuncSetAttribute(gemm_bf3<EPI_GELU_SPLIT>,
                         cudaFuncAttributeMaxDynamicSharedMemorySize, GEMM_SMEM_BYTES);
    cudaFuncSetAttribute(gemm_bf3<EPI_SCORES>,
                         cudaFuncAttributeMaxDynamicSharedMemorySize, GEMM_SMEM_BYTES);

    // 0. fused weight split (one launch)
    WSplit6 wargs;
    wargs.src[0] = rq_w;   wargs.dstoff[0] = (long)W_RQ;   wargs.n4[0] = 1048576 / 4;
    wargs.src[1] = rk_w;   wargs.dstoff[1] = (long)W_RK;   wargs.n4[1] = 1048576 / 4;
    wargs.src[2] = qkv_w;  wargs.dstoff[2] = (long)W_QKV;  wargs.n4[2] = 3145728 / 4;
    wargs.src[3] = proj_w; wargs.dstoff[3] = (long)W_PROJ; wargs.n4[3] = 1048576 / 4;
    wargs.src[4] = fc1_w;  wargs.dstoff[4] = (long)W_FC1;  wargs.n4[4] = 4194304 / 4;
    wargs.src[5] = fc2_w;  wargs.dstoff[5] = (long)W_FC2;  wargs.n4[5] = 4194304 / 4;
    split_all_w_kernel<<<2048, 256>>>(wargs, WH, WL);

    // 1. LayerNorm 1
    layernorm_split_kernel<<<BB * SS, 256>>>(x, n1w, n1b, XNh, XNl);

    // 2. Routing projections (per batch via z)
    dim3 gR(8, 8, 2);
    gemm_bf3<EPI_BIAS><<<gR, 256, GEMM_SMEM_BYTES>>>(
        XNh + 1024, XNl + 1024, WH + W_RQ, WL + W_RQ, rq_b, nullptr,
        QRf, nullptr, nullptr, 1024, 1024, 1024, (long)SS * DD, 0, (long)PP * DD);
    gemm_bf3<EPI_BIAS><<<gR, 256, GEMM_SMEM_BYTES>>>(
        XNh + 1024, XNl + 1024, WH + W_RK, WL + W_RK, rk_b, nullptr,
        KRf, nullptr, nullptr, 1024, 1024, 1024, (long)SS * DD, 0, (long)PP * DD);

    // 3. L2 normalize (QRf||KRf contiguous 4096 rows)
    l2norm_split_kernel<<<2 * BB * PP, 256>>>(QRf, QKRh, QKRl);

    // 4. Routing scores
    gemm_bf3<EPI_SCORES><<<gR, 256, GEMM_SMEM_BYTES>>>(
        QKRh, QKRl, QKRh + 2048ull * 1024, QKRl + 2048ull * 1024, nullptr, pos_bias,
        SC, nullptr, nullptr, 1024, 1024, 1024,
        (long)PP * DD, (long)PP * DD, (long)PP * PP);

    // 5. Top-32 + routing weights (warp-local + merge)
    topk_kernel<<<BB * PP, 256>>>(SC, RT, LW);

    // 6. QKV projection
    dim3 gQ(24, 17, 1);
    gemm_bf3<EPI_BIAS><<<gQ, 256, GEMM_SMEM_BYTES>>>(
        XNh, XNl, WH + W_QKV, WL + W_QKV, qkv_b, nullptr,
        QKV, nullptr, nullptr, 2050, 3072, 1024, 0, 0, 0);

    // 7. CLS attention
    cls_attn_kernel<<<BB * HH_, 256>>>(QKV, ATTh, ATTl);

    // 8. Routed patch attention (warp-per-head)
    patch_attn_kernel<<<BB * PP, 512>>>(QKV, RT, LW, ATTh, ATTl);

    // 9. Output projection + residual
    dim3 gP(8, 17, 1);
    gemm_bf3<EPI_BIAS_RESID><<<gP, 256, GEMM_SMEM_BYTES>>>(
        ATTh, ATTl, WH + W_PROJ, WL + W_PROJ, proj_b, x,
        out, nullptr, nullptr, 2050, 1024, 1024, 0, 0, 0);

    // 10. LayerNorm 2
    layernorm_split_kernel<<<BB * SS, 256>>>(out, n2w, n2b, HNh, HNl);

    // 11. FC1 + exact GELU -> HH hi/lo
    dim3 gF1(32, 17, 1);
    gemm_bf3<EPI_GELU_SPLIT><<<gF1, 256, GEMM_SMEM_BYTES>>>(
        HNh, HNl, WH + W_FC1, WL + W_FC1, fc1_b, nullptr,
        nullptr, HHh, HHl, 2050, 4096, 1024, 0, 0, 0);

    // 12. FC2 + residual
    dim3 gF2(8, 17, 1);
    gemm_bf3<EPI_BIAS_RESID><<<gF2, 256, GEMM_SMEM_BYTES>>>(
        HHh, HHl, WH + W_FC2, WL + W_FC2, fc2_b, out,
        out, nullptr, nullptr, 2050, 1024, 4096, 0, 0, 0);

    (void)in_sizes; (void)n_in; (void)out_size;
}

// round 13
// speedup vs baseline: 1.2114x; 1.0679x over previous
#include <cuda_runtime.h>
#include <cuda_bf16.h>
#include <stdint.h>
#include <math.h>

// ---------------------------------------------------------------------------
// Problem constants
// ---------------------------------------------------------------------------
#define BB   2
#define SS   1025
#define DD   1024
#define HH_  16
#define HD_  64
#define PP   1024
#define KR_  32
#define SCALE_ 0.125f
#define INV_TEMP 10.0f

// ---------------------------------------------------------------------------
// Scratch (float units). bf16 buffers live inside the float array.
// ---------------------------------------------------------------------------
static const size_t F_QR   = 2048ull * 1024;
static const size_t F_KR   = 2048ull * 1024;
static const size_t F_SC   = 2048ull * 1024;
static const size_t F_QKV  = 2050ull * 3072;
static const size_t F_LW   = 2048ull * 32;
static const size_t F_RT   = 2048ull * 32;
static const size_t H_XN   = 2050ull * 1024 / 2;
static const size_t H_QKR  = 4096ull * 1024 / 2;
static const size_t H_ATT  = 2050ull * 1024 / 2;
static const size_t H_HN   = 2050ull * 1024 / 2;
static const size_t H_HH   = 2050ull * 4096 / 2;
static const size_t H_W    = 14680064ull / 2;

static const size_t O_QR   = 0;
static const size_t O_KR   = O_QR  + F_QR;
static const size_t O_SC   = O_KR  + F_KR;
static const size_t O_QKV  = O_SC  + F_SC;
static const size_t O_LW   = O_QKV + F_QKV;
static const size_t O_RT   = O_LW  + F_LW;
static const size_t O_XNH  = O_RT  + F_RT;
static const size_t O_XNL  = O_XNH + H_XN;
static const size_t O_QKRH = O_XNL + H_XN;
static const size_t O_QKRL = O_QKRH + H_QKR;
static const size_t O_ATTH = O_QKRL + H_QKR;
static const size_t O_ATTL = O_ATTH + H_ATT;
static const size_t O_HNH  = O_ATTL + H_ATT;
static const size_t O_HNL  = O_HNH + H_HN;
static const size_t O_HHH  = O_HNL + H_HN;
static const size_t O_HHL  = O_HHH + H_HH;
static const size_t O_WH   = O_HHL + H_HH;
static const size_t O_WL   = O_WH  + H_W;
static const size_t SCR_TOTAL = O_WL + H_W;

static const size_t W_RQ   = 0;
static const size_t W_RK   = 1048576;
static const size_t W_QKV  = 2097152;
static const size_t W_PROJ = 5242880;
static const size_t W_FC1  = 6291456;
static const size_t W_FC2  = 10485760;

__device__ float g_scratch[SCR_TOTAL];

// ---------------------------------------------------------------------------
// Block reductions (blockDim.x == 256)
// ---------------------------------------------------------------------------
__device__ __forceinline__ float blockReduceSum(float v, float* sbuf) {
    int lane = threadIdx.x & 31, wid = threadIdx.x >> 5;
    #pragma unroll
    for (int o = 16; o; o >>= 1) v += __shfl_xor_sync(0xffffffffu, v, o);
    if (lane == 0) sbuf[wid] = v;
    __syncthreads();
    if (wid == 0) {
        v = (lane < 8) ? sbuf[lane] : 0.f;
        #pragma unroll
        for (int o = 4; o; o >>= 1) v += __shfl_xor_sync(0xffffffffu, v, o);
        if (lane == 0) sbuf[0] = v;
    }
    __syncthreads();
    float r = sbuf[0];
    __syncthreads();
    return r;
}

__device__ __forceinline__ float blockReduceMax(float v, float* sbuf) {
    int lane = threadIdx.x & 31, wid = threadIdx.x >> 5;
    #pragma unroll
    for (int o = 16; o; o >>= 1) v = fmaxf(v, __shfl_xor_sync(0xffffffffu, v, o));
    if (lane == 0) sbuf[wid] = v;
    __syncthreads();
    if (wid == 0) {
        v = (lane < 8) ? sbuf[lane] : -3.4e38f;
        #pragma unroll
        for (int o = 4; o; o >>= 1) v = fmaxf(v, __shfl_xor_sync(0xffffffffu, v, o));
        if (lane == 0) sbuf[0] = v;
    }
    __syncthreads();
    float r = sbuf[0];
    __syncthreads();
    return r;
}

__device__ __forceinline__ void split1(float v, __nv_bfloat16* hi, __nv_bfloat16* lo) {
    __nv_bfloat16 h = __float2bfloat16(v);
    *hi = h;
    *lo = __float2bfloat16(v - __bfloat162float(h));
}

// ---------------------------------------------------------------------------
// Fused weight split: all 6 weights in one launch
// ---------------------------------------------------------------------------
struct WSplit6 {
    const float* src[6];
    long dstoff[6];
    int n4[6];
};

__global__ void split_all_w_kernel(WSplit6 a,
                                   __nv_bfloat16* __restrict__ hi,
                                   __nv_bfloat16* __restrict__ lo) {
    #pragma unroll
    for (int s = 0; s < 6; s++) {
        const float4* sp = (const float4*)a.src[s];
        __nv_bfloat16* hp = hi + a.dstoff[s];
        __nv_bfloat16* lp = lo + a.dstoff[s];
        const int n4 = a.n4[s];
        for (int i = blockIdx.x * blockDim.x + threadIdx.x; i < n4;
             i += gridDim.x * blockDim.x) {
            float4 f = sp[i];
            __nv_bfloat162 h0 = __floats2bfloat162_rn(f.x, f.y);
            __nv_bfloat162 h1 = __floats2bfloat162_rn(f.z, f.w);
            __nv_bfloat162 l0 = __floats2bfloat162_rn(f.x - __bfloat162float(h0.x),
                                                      f.y - __bfloat162float(h0.y));
            __nv_bfloat162 l1 = __floats2bfloat162_rn(f.z - __bfloat162float(h1.x),
                                                      f.w - __bfloat162float(h1.y));
            uint2 hv; hv.x = *(unsigned*)&h0; hv.y = *(unsigned*)&h1;
            uint2 lv; lv.x = *(unsigned*)&l0; lv.y = *(unsigned*)&l1;
            *(uint2*)(hp + (size_t)i * 4) = hv;
            *(uint2*)(lp + (size_t)i * 4) = lv;
        }
    }
}

// ---------------------------------------------------------------------------
// LayerNorm -> hi/lo bf16 planes
// ---------------------------------------------------------------------------
__global__ void layernorm_split_kernel(const float* __restrict__ in,
                                       const float* __restrict__ w,
                                       const float* __restrict__ b,
                                       __nv_bfloat16* __restrict__ outh,
                                       __nv_bfloat16* __restrict__ outl) {
    __shared__ float red[32];
    int row = blockIdx.x, tid = threadIdx.x;
    const float4* ip = (const float4*)(in + (size_t)row * 1024);
    float4 v = ip[tid];
    float s = v.x + v.y + v.z + v.w;
    float mean = blockReduceSum(s, red) * (1.f / 1024.f);
    float dx = v.x - mean, dy = v.y - mean, dz = v.z - mean, dw = v.w - mean;
    float ss = dx * dx + dy * dy + dz * dz + dw * dw;
    float var = blockReduceSum(ss, red) * (1.f / 1024.f);
    float rstd = rsqrtf(var + 1e-5f);
    float4 wv = ((const float4*)w)[tid];
    float4 bv = ((const float4*)b)[tid];
    float ox = dx * rstd * wv.x + bv.x;
    float oy = dy * rstd * wv.y + bv.y;
    float oz = dz * rstd * wv.z + bv.z;
    float ow = dw * rstd * wv.w + bv.w;
    __nv_bfloat162 h0 = __floats2bfloat162_rn(ox, oy);
    __nv_bfloat162 h1 = __floats2bfloat162_rn(oz, ow);
    __nv_bfloat162 l0 = __floats2bfloat162_rn(ox - __bfloat162float(h0.x),
                                              oy - __bfloat162float(h0.y));
    __nv_bfloat162 l1 = __floats2bfloat162_rn(oz - __bfloat162float(h1.x),
                                              ow - __bfloat162float(h1.y));
    uint2 hv; hv.x = *(unsigned*)&h0; hv.y = *(unsigned*)&h1;
    uint2 lv; lv.x = *(unsigned*)&l0; lv.y = *(unsigned*)&l1;
    *(uint2*)(outh + (size_t)row * 1024 + tid * 4) = hv;
    *(uint2*)(outl + (size_t)row * 1024 + tid * 4) = lv;
}

// ---------------------------------------------------------------------------
// L2 norm -> hi/lo bf16 planes
// ---------------------------------------------------------------------------
__global__ void l2norm_split_kernel(const float* __restrict__ buf,
                                    __nv_bfloat16* __restrict__ outh,
                                    __nv_bfloat16* __restrict__ outl) {
    __shared__ float red[32];
    int row = blockIdx.x, tid = threadIdx.x;
    const float4* p = (const float4*)(buf + (size_t)row * 1024);
    float4 v = p[tid];
    float ss = v.x * v.x + v.y * v.y + v.z * v.z + v.w * v.w;
    float tot = blockReduceSum(ss, red);
    float sc = 1.f / fmaxf(sqrtf(tot), 1e-12f);
    float ox = v.x * sc, oy = v.y * sc, oz = v.z * sc, ow = v.w * sc;
    __nv_bfloat162 h0 = __floats2bfloat162_rn(ox, oy);
    __nv_bfloat162 h1 = __floats2bfloat162_rn(oz, ow);
    __nv_bfloat162 l0 = __floats2bfloat162_rn(ox - __bfloat162float(h0.x),
                                              oy - __bfloat162float(h0.y));
    __nv_bfloat162 l1 = __floats2bfloat162_rn(oz - __bfloat162float(h1.x),
                                              ow - __bfloat162float(h1.y));
    uint2 hv; hv.x = *(unsigned*)&h0; hv.y = *(unsigned*)&h1;
    uint2 lv; lv.x = *(unsigned*)&l0; lv.y = *(unsigned*)&l1;
    *(uint2*)(outh + (size_t)row * 1024 + tid * 4) = hv;
    *(uint2*)(outl + (size_t)row * 1024 + tid * 4) = lv;
}

// ---------------------------------------------------------------------------
// bf16x3 tensor-core NT GEMM, pure cp.async loader + ldmatrix fragments.
// NOW __launch_bounds__(256, 2): 2 CTAs/SM -> 16 warps/SM to feed tensor pipe.
// ---------------------------------------------------------------------------
#define EPI_BIAS        1
#define EPI_BIAS_RESID  2
#define EPI_GELU_SPLIT  3
#define EPI_SCORES      4

#define KSTRIDE 40
#define TILE_BF16 (128 * KSTRIDE)
#define SB_BASE (4 * TILE_BF16)
#define GEMM_SMEM_BYTES (8 * TILE_BF16 * 2)   // 81920

__device__ __forceinline__ void mma_bf16(float* d, const unsigned* a, const unsigned* b) {
    asm volatile(
        "mma.sync.aligned.m16n8k16.row.col.f32.bf16.bf16.f32 "
        "{%0,%1,%2,%3}, {%4,%5,%6,%7}, {%8,%9}, {%0,%1,%2,%3};"
        : "+f"(d[0]), "+f"(d[1]), "+f"(d[2]), "+f"(d[3])
        : "r"(a[0]), "r"(a[1]), "r"(a[2]), "r"(a[3]), "r"(b[0]), "r"(b[1]));
}

__device__ __forceinline__ void ldsm4(unsigned addr, unsigned& r0, unsigned& r1,
                                      unsigned& r2, unsigned& r3) {
    asm volatile("ldmatrix.sync.aligned.m8n8.x4.shared.b16 {%0,%1,%2,%3}, [%4];"
                 : "=r"(r0), "=r"(r1), "=r"(r2), "=r"(r3) : "r"(addr));
}

__device__ __forceinline__ void cpasync16(unsigned dst, const void* src, unsigned sz) {
    asm volatile("cp.async.ca.shared.global [%0], [%1], 16, %2;"
                 :: "r"(dst), "l"(src), "r"(sz));
}

template <int EPI>
__global__ __launch_bounds__(256, 2) void gemm_bf3(
    const __nv_bfloat16* __restrict__ Ah, const __nv_bfloat16* __restrict__ Al,
    const __nv_bfloat16* __restrict__ Bh, const __nv_bfloat16* __restrict__ Bl,
    const float* __restrict__ bias, const float* __restrict__ extra,
    float* __restrict__ C, __nv_bfloat16* __restrict__ Ch, __nv_bfloat16* __restrict__ Cl,
    int M, int N, int Kd, long sA, long sB, long sC) {

    Ah += (long)blockIdx.z * sA;  Al += (long)blockIdx.z * sA;
    Bh += (long)blockIdx.z * sB;  Bl += (long)blockIdx.z * sB;
    const long cOff = (long)blockIdx.z * sC;

    extern __shared__ __nv_bfloat16 sm[];

    const int tid  = threadIdx.x;
    const int lane = tid & 31;
    const int wid  = tid >> 5;
    const int wr   = wid & 3;
    const int wc   = wid >> 2;
    const int g    = lane >> 2;
    const int tig  = lane & 3;
    const int bm   = blockIdx.y * 128;
    const int bn   = blockIdx.x * 128;

    float acc[2][8][4];
    #pragma unroll
    for (int mi = 0; mi < 2; mi++)
        #pragma unroll
        for (int ni = 0; ni < 8; ni++)
            #pragma unroll
            for (int r = 0; r < 4; r++) acc[mi][ni][r] = 0.f;

    const int ldRow = tid >> 1;
    const int half  = tid & 1;
    const int aRow  = bm + ldRow;
    const unsigned aSz = (aRow < M) ? 16u : 0u;
    const long aOff = (long)((aRow < M) ? aRow : 0) * Kd + half * 16;
    const long bOff = (long)(bn + ldRow) * Kd + half * 16;
    const __nv_bfloat16* aH = Ah + aOff;
    const __nv_bfloat16* aL = Al + aOff;
    const __nv_bfloat16* bH = Bh + bOff;
    const __nv_bfloat16* bL = Bl + bOff;

    const unsigned smBase = (unsigned)__cvta_generic_to_shared(sm);
    const unsigned dA0 = smBase + 2u * (unsigned)(ldRow * KSTRIDE + half * 16);
    const unsigned stagePitch = 2u * (unsigned)(2 * TILE_BF16);
    const unsigned hlPitch    = 2u * (unsigned)TILE_BF16;
    const unsigned bPlane     = 2u * (unsigned)SB_BASE;

    const int aRowL = wr * 32 + (lane & 7) + ((lane >> 3) & 1) * 8;
    const int aKL   = ((lane >> 4) & 1) * 8;
    const unsigned aLaneOff = (unsigned)(aRowL * KSTRIDE + aKL);
    const int bRowL = wc * 64 + (lane & 7) + ((lane >> 4) & 1) * 8;
    const int bKL   = ((lane >> 3) & 1) * 8;
    const unsigned bLaneOff = (unsigned)(bRowL * KSTRIDE + bKL);

    const int nIter = Kd >> 5;

    #define ISSUE(st, itv) do {                                              \
        const long k0 = (long)(itv) * 32;                                    \
        unsigned d0 = dA0 + (unsigned)(st) * stagePitch;                     \
        cpasync16(d0,            aH + k0,     aSz);                          \
        cpasync16(d0 + 16,       aH + k0 + 8, aSz);                          \
        cpasync16(d0 + hlPitch,      aL + k0,     aSz);                      \
        cpasync16(d0 + hlPitch + 16, aL + k0 + 8, aSz);                      \
        unsigned d1 = d0 + bPlane;                                           \
        cpasync16(d1,            bH + k0,     16u);                          \
        cpasync16(d1 + 16,       bH + k0 + 8, 16u);                          \
        cpasync16(d1 + hlPitch,      bL + k0,     16u);                      \
        cpasync16(d1 + hlPitch + 16, bL + k0 + 8, 16u);                      \
        asm volatile("cp.async.commit_group;");                              \
    } while (0)

    ISSUE(0, 0);
    if (nIter > 1) ISSUE(1, 1);

    for (int it = 0; it < nIter; ++it) {
        if (it == nIter - 1) asm volatile("cp.async.wait_group 0;");
        else                 asm volatile("cp.async.wait_group 1;");
        __syncthreads();

        const int s = it & 1;
        const unsigned pA_hi = (unsigned)((s * 2 + 0) * TILE_BF16);
        const unsigned pA_lo = (unsigned)((s * 2 + 1) * TILE_BF16);
        const unsigned pB_hi = (unsigned)(SB_BASE + (s * 2 + 0) * TILE_BF16);
        const unsigned pB_lo = (unsigned)(SB_BASE + (s * 2 + 1) * TILE_BF16);

        #pragma unroll
        for (int ks = 0; ks < 2; ks++) {
            const int kb = ks * 16;
            unsigned Ahf[2][4], Alf[2][4], Bhf[8][2], Blf[8][2];
            #pragma unroll
            for (int mi = 0; mi < 2; mi++) {
                unsigned off = (unsigned)(mi * 16 * KSTRIDE + kb) + aLaneOff;
                ldsm4(smBase + 2u * (pA_hi + off), Ahf[mi][0], Ahf[mi][1], Ahf[mi][2], Ahf[mi][3]);
                ldsm4(smBase + 2u * (pA_lo + off), Alf[mi][0], Alf[mi][1], Alf[mi][2], Alf[mi][3]);
            }
            #pragma unroll
            for (int j = 0; j < 4; j++) {
                unsigned off = (unsigned)(j * 16 * KSTRIDE + kb) + bLaneOff;
                ldsm4(smBase + 2u * (pB_hi + off),
                      Bhf[j * 2][0], Bhf[j * 2][1], Bhf[j * 2 + 1][0], Bhf[j * 2 + 1][1]);
                ldsm4(smBase + 2u * (pB_lo + off),
                      Blf[j * 2][0], Blf[j * 2][1], Blf[j * 2 + 1][0], Blf[j * 2 + 1][1]);
            }
            #pragma unroll
            for (int mi = 0; mi < 2; mi++)
                #pragma unroll
                for (int ni = 0; ni < 8; ni++) {
                    mma_bf16(acc[mi][ni], Ahf[mi], Bhf[ni]);
                    mma_bf16(acc[mi][ni], Alf[mi], Bhf[ni]);
                    mma_bf16(acc[mi][ni], Ahf[mi], Blf[ni]);
                }
        }
        __syncthreads();

        if (it + 2 < nIter) ISSUE(s, it + 2);
    }
    #undef ISSUE

    #pragma unroll
    for (int mi = 0; mi < 2; mi++) {
        #pragma unroll
        for (int rr = 0; rr < 2; rr++) {
            const int m = bm + wr * 32 + mi * 16 + g + rr * 8;
            if (m >= M) continue;
            #pragma unroll
            for (int ni = 0; ni < 8; ni++) {
                #pragma unroll
                for (int cc = 0; cc < 2; cc++) {
                    const int n = bn + wc * 64 + ni * 8 + tig * 2 + cc;
                    float v = acc[mi][ni][rr * 2 + cc];
                    const long idx = cOff + (long)m * N + n;
                    if (EPI == EPI_BIAS) {
                        C[idx] = v + bias[n];
                    } else if (EPI == EPI_BIAS_RESID) {
                        C[idx] = v + bias[n] + extra[(long)m * N + n];
                    } else if (EPI == EPI_GELU_SPLIT) {
                        v += bias[n];
                        v = 0.5f * v * (1.0f + erff(v * 0.70710678118654752f));
                        split1(v, Ch + idx, Cl + idx);
                    } else if (EPI == EPI_SCORES) {
                        v += extra[(long)m * N + n];
                        if (m == n) v = -1e9f;
                        C[idx] = v;
                    }
                }
            }
        }
    }
}

// ---------------------------------------------------------------------------
// Top-K=32: 8 warps extract per-slice top-32 (no block syncs), 1 warp merges.
// ---------------------------------------------------------------------------
__global__ void topk_kernel(const float* __restrict__ scores,
                            int* __restrict__ routes,
                            float* __restrict__ logw) {
    __shared__ float wv[8][32];
    __shared__ int   wi[8][32];
    __shared__ float sv[32];
    __shared__ int   si[32];
    const int row = blockIdx.x, tid = threadIdx.x;
    const int lane = tid & 31, w = tid >> 5;
    const float* src = scores + (size_t)row * 1024;

    float v[4]; int id4[4];
    #pragma unroll
    for (int c = 0; c < 4; c++) {
        int id = w * 128 + c * 32 + lane;
        v[c] = src[id];
        id4[c] = id;
    }

    for (int it = 0; it < 32; it++) {
        float bv = v[0]; int bi = id4[0]; int bs = 0;
        #pragma unroll
        for (int c = 1; c < 4; c++)
            if (v[c] > bv || (v[c] == bv && id4[c] < bi)) { bv = v[c]; bi = id4[c]; bs = c; }
        float cv = bv; int ci = bi;
        #pragma unroll
        for (int o = 16; o; o >>= 1) {
            float ov = __shfl_xor_sync(0xffffffffu, cv, o);
            int   oi = __shfl_xor_sync(0xffffffffu, ci, o);
            if (ov > cv || (ov == cv && oi < ci)) { cv = ov; ci = oi; }
        }
        if (lane == 0) { wv[w][it] = cv; wi[w][it] = ci; }
        if (ci == bi) v[bs] = -3.4e38f;
    }
    __syncthreads();

    if (w == 0) {
        int ptr = 0;
        for (int it = 0; it < 32; it++) {
            float cv = (lane < 8 && ptr < 32) ? wv[lane][ptr] : -3.4e38f;
            int   ci = (lane < 8 && ptr < 32) ? wi[lane][ptr] : 0x7fffffff;
            float bv = cv; int bi = ci;
            #pragma unroll
            for (int o = 4; o; o >>= 1) {
                float ov = __shfl_xor_sync(0xffffffffu, bv, o);
                int   oi = __shfl_xor_sync(0xffffffffu, bi, o);
                if (ov > bv || (ov == bv && oi < bi)) { bv = ov; bi = oi; }
            }
            if (lane < 8 && ci == bi && ptr < 32) ptr++;
            if (lane == 0) { sv[it] = bv; si[it] = bi; }
        }
    }
    __syncthreads();

    if (tid < 32) {
        float t = sv[tid] * INV_TEMP;
        float tmax = sv[0] * INV_TEMP;
        float e = expf(t - tmax);
        float z = e;
        #pragma unroll
        for (int o = 16; o; o >>= 1) z += __shfl_xor_sync(0xffffffffu, z, o);
        float lw = t - (tmax + logf(z));
        routes[(size_t)row * 32 + tid] = si[tid];
        logw[(size_t)row * 32 + tid] = fmaxf(lw, -10.f);
    }
}

// ---------------------------------------------------------------------------
// CLS attention -> hi/lo ATT planes
// ---------------------------------------------------------------------------
__global__ void cls_attn_kernel(const float* __restrict__ qkv,
                                __nv_bfloat16* __restrict__ atth,
                                __nv_bfloat16* __restrict__ attl) {
    __shared__ float q[64];
    __shared__ float sp[SS];
    __shared__ float red[32];
    __shared__ float po[4][64];
    int bh = blockIdx.x, b = bh >> 4, h = bh & 15;
    int tid = threadIdx.x;
    const float* base = qkv + (size_t)b * SS * 3072;
    if (tid < 64) q[tid] = base[h * 64 + tid];
    __syncthreads();

    float lmax = -3.4e38f;
    for (int j = tid; j < SS; j += 256) {
        const float* kr = base + (size_t)j * 3072 + 1024 + h * 64;
        float d = 0.f;
        #pragma unroll
        for (int dd = 0; dd < 64; dd++) d += q[dd] * kr[dd];
        d *= SCALE_;
        sp[j] = d;
        lmax = fmaxf(lmax, d);
    }
    float M = blockReduceMax(lmax, red);
    float ls = 0.f;
    for (int j = tid; j < SS; j += 256) {
        float e = expf(sp[j] - M);
        sp[j] = e;
        ls += e;
    }
    float Z = blockReduceSum(ls, red);

    int g = tid >> 6, d = tid & 63;
    float o = 0.f;
    for (int j = g; j < SS; j += 4)
        o += sp[j] * base[(size_t)j * 3072 + 2048 + h * 64 + d];
    po[g][d] = o;
    __syncthreads();
    if (tid < 64) {
        float r = (po[0][tid] + po[1][tid] + po[2][tid] + po[3][tid]) / Z;
        size_t idx = (size_t)b * SS * 1024 + h * 64 + tid;
        split1(r, atth + idx, attl + idx);
    }
}

// ---------------------------------------------------------------------------
// Routed patch attention: one warp per head
// ---------------------------------------------------------------------------
__global__ __launch_bounds__(512) void patch_attn_kernel(
        const float* __restrict__ qkv,
        const int* __restrict__ routes,
        const float* __restrict__ logw,
        __nv_bfloat16* __restrict__ atth,
        __nv_bfloat16* __restrict__ attl) {
    __shared__ int   rt[32];
    __shared__ float lw[32];
    const int bp = blockIdx.x, b = bp >> 10, p = bp & 1023;
    const int tid = threadIdx.x, lane = tid & 31, h = tid >> 5;
    if (tid < 32) {
        rt[tid] = routes[(size_t)bp * 32 + tid] + 1;
        lw[tid] = logw[(size_t)bp * 32 + tid];
    }
    __syncthreads();

    const float* base = qkv + (size_t)b * SS * 3072;
    const float* qp = base + (size_t)(p + 1) * 3072 + h * 64;
    const float q0 = qp[lane], q1 = qp[lane + 32];

    float myscore = 0.f;
    #pragma unroll
    for (int kb = 0; kb < 32; kb += 8) {
        float k0[8], k1[8];
        #pragma unroll
        for (int j = 0; j < 8; j++) {
            const float* kp = base + (size_t)rt[kb + j] * 3072 + 1024 + h * 64;
            k0[j] = kp[lane];
            k1[j] = kp[lane + 32];
        }
        #pragma unroll
        for (int j = 0; j < 8; j++) {
            float d = q0 * k0[j] + q1 * k1[j];
            #pragma unroll
            for (int o = 16; o; o >>= 1) d += __shfl_xor_sync(0xffffffffu, d, o);
            if (lane == kb + j) myscore = d * SCALE_ + lw[lane];
        }
    }

    float m = myscore;
    #pragma unroll
    for (int o = 16; o; o >>= 1) m = fmaxf(m, __shfl_xor_sync(0xffffffffu, m, o));
    float e = expf(myscore - m);
    float z = e;
    #pragma unroll
    for (int o = 16; o; o >>= 1) z += __shfl_xor_sync(0xffffffffu, z, o);
    const float pw = e / z;

    float o0 = 0.f, o1 = 0.f;
    #pragma unroll
    for (int kb = 0; kb < 32; kb += 8) {
        float v0[8], v1[8];
        #pragma unroll
        for (int j = 0; j < 8; j++) {
            const float* vp = base + (size_t)rt[kb + j] * 3072 + 2048 + h * 64;
            v0[j] = vp[lane];
            v1[j] = vp[lane + 32];
        }
        #pragma unroll
        for (int j = 0; j < 8; j++) {
            float wj = __shfl_sync(0xffffffffu, pw, kb + j);
            o0 += wj * v0[j];
            o1 += wj * v1[j];
        }
    }

    const size_t idx = ((size_t)b * SS + p + 1) * 1024 + h * 64 + lane;
    split1(o0, atth + idx, attl + idx);
    split1(o1, atth + idx + 32, attl + idx + 32);
}

// ---------------------------------------------------------------------------
// Orchestration
// ---------------------------------------------------------------------------
extern "C" void kernel_launch(void* const* d_in, const int* in_sizes, int n_in,
                              void* d_out, int out_size) {
    const float* x        = (const float*)d_in[0];
    const float* n1w      = (const float*)d_in[1];
    const float* n1b      = (const float*)d_in[2];
    const float* rq_w     = (const float*)d_in[3];
    const float* rq_b     = (const float*)d_in[4];
    const float* rk_w     = (const float*)d_in[5];
    const float* rk_b     = (const float*)d_in[6];
    const float* pos_bias = (const float*)d_in[7];
    const float* qkv_w    = (const float*)d_in[8];
    const float* qkv_b    = (const float*)d_in[9];
    const float* proj_w   = (const float*)d_in[10];
    const float* proj_b   = (const float*)d_in[11];
    const float* n2w      = (const float*)d_in[12];
    const float* n2b      = (const float*)d_in[13];
    const float* fc1_w    = (const float*)d_in[14];
    const float* fc1_b    = (const float*)d_in[15];
    const float* fc2_w    = (const float*)d_in[16];
    const float* fc2_b    = (const float*)d_in[17];
    float* out = (float*)d_out;

    void* sp = nullptr;
    cudaGetSymbolAddress(&sp, g_scratch);
    float* SCR = (float*)sp;
    float* QRf = SCR + O_QR;
    float* KRf = SCR + O_KR;
    float* SC  = SCR + O_SC;
    float* QKV = SCR + O_QKV;
    float* LW  = SCR + O_LW;
    int*   RT  = (int*)(SCR + O_RT);
    __nv_bfloat16* XNh  = (__nv_bfloat16*)(SCR + O_XNH);
    __nv_bfloat16* XNl  = (__nv_bfloat16*)(SCR + O_XNL);
    __nv_bfloat16* QKRh = (__nv_bfloat16*)(SCR + O_QKRH);
    __nv_bfloat16* QKRl = (__nv_bfloat16*)(SCR + O_QKRL);
    __nv_bfloat16* ATTh = (__nv_bfloat16*)(SCR + O_ATTH);
    __nv_bfloat16* ATTl = (__nv_bfloat16*)(SCR + O_ATTL);
    __nv_bfloat16* HNh  = (__nv_bfloat16*)(SCR + O_HNH);
    __nv_bfloat16* HNl  = (__nv_bfloat16*)(SCR + O_HNL);
    __nv_bfloat16* HHh  = (__nv_bfloat16*)(SCR + O_HHH);
    __nv_bfloat16* HHl  = (__nv_bfloat16*)(SCR + O_HHL);
    __nv_bfloat16* WH   = (__nv_bfloat16*)(SCR + O_WH);
    __nv_bfloat16* WL   = (__nv_bfloat16*)(SCR + O_WL);

    cudaFuncSetAttribute(gemm_bf3<EPI_BIAS>,
                         cudaFuncAttributeMaxDynamicSharedMemorySize, GEMM_SMEM_BYTES);
    cudaFuncSetAttribute(gemm_bf3<EPI_BIAS_RESID>,
                         cudaFuncAttributeMaxDynamicSharedMemorySize, GEMM_SMEM_BYTES);
    cudaFuncSetAttribute(gemm_bf3<EPI_GELU_SPLIT>,
                         cudaFuncAttributeMaxDynamicSharedMemorySize, GEMM_SMEM_BYTES);
    cudaFuncSetAttribute(gemm_bf3<EPI_SCORES>,
                         cudaFuncAttributeMaxDynamicSharedMemorySize, GEMM_SMEM_BYTES);

    // 0. fused weight split
    WSplit6 wargs;
    wargs.src[0] = rq_w;   wargs.dstoff[0] = (long)W_RQ;   wargs.n4[0] = 1048576 / 4;
    wargs.src[1] = rk_w;   wargs.dstoff[1] = (long)W_RK;   wargs.n4[1] = 1048576 / 4;
    wargs.src[2] = qkv_w;  wargs.dstoff[2] = (long)W_QKV;  wargs.n4[2] = 3145728 / 4;
    wargs.src[3] = proj_w; wargs.dstoff[3] = (long)W_PROJ; wargs.n4[3] = 1048576 / 4;
    wargs.src[4] = fc1_w;  wargs.dstoff[4] = (long)W_FC1;  wargs.n4[4] = 4194304 / 4;
    wargs.src[5] = fc2_w;  wargs.dstoff[5] = (long)W_FC2;  wargs.n4[5] = 4194304 / 4;
    split_all_w_kernel<<<2048, 256>>>(wargs, WH, WL);

    // 1. LayerNorm 1
    layernorm_split_kernel<<<BB * SS, 256>>>(x, n1w, n1b, XNh, XNl);

    // 2. Routing projections (per batch via z)
    dim3 gR(8, 8, 2);
    gemm_bf3<EPI_BIAS><<<gR, 256, GEMM_SMEM_BYTES>>>(
        XNh + 1024, XNl + 1024, WH + W_RQ, WL + W_RQ, rq_b, nullptr,
        QRf, nullptr, nullptr, 1024, 1024, 1024, (long)SS * DD, 0, (long)PP * DD);
    gemm_bf3<EPI_BIAS><<<gR, 256, GEMM_SMEM_BYTES>>>(
        XNh + 1024, XNl + 1024, WH + W_RK, WL + W_RK, rk_b, nullptr,
        KRf, nullptr, nullptr, 1024, 1024, 1024, (long)SS * DD, 0, (long)PP * DD);

    // 3. L2 normalize
    l2norm_split_kernel<<<2 * BB * PP, 256>>>(QRf, QKRh, QKRl);

    // 4. Routing scores
    gemm_bf3<EPI_SCORES><<<gR, 256, GEMM_SMEM_BYTES>>>(
        QKRh, QKRl, QKRh + 2048ull * 1024, QKRl + 2048ull * 1024, nullptr, pos_bias,
        SC, nullptr, nullptr, 1024, 1024, 1024,
        (long)PP * DD, (long)PP * DD, (long)PP * PP);

    // 5. Top-32 + routing weights
    topk_kernel<<<BB * PP, 256>>>(SC, RT, LW);

    // 6. QKV projection
    dim3 gQ(24, 17, 1);
    gemm_bf3<EPI_BIAS><<<gQ, 256, GEMM_SMEM_BYTES>>>(
        XNh, XNl, WH + W_QKV, WL + W_QKV, qkv_b, nullptr,
        QKV, nullptr, nullptr, 2050, 3072, 1024, 0, 0, 0);

    // 7. CLS attention
    cls_attn_kernel<<<BB * HH_, 256>>>(QKV, ATTh, ATTl);

    // 8. Routed patch attention
    patch_attn_kernel<<<BB * PP, 512>>>(QKV, RT, LW, ATTh, ATTl);

    // 9. Output projection + residual
    dim3 gP(8, 17, 1);
    gemm_bf3<EPI_BIAS_RESID><<<gP, 256, GEMM_SMEM_BYTES>>>(
        ATTh, ATTl, WH + W_PROJ, WL + W_PROJ, proj_b, x,
        out, nullptr, nullptr, 2050, 1024, 1024, 0, 0, 0);

    // 10. LayerNorm 2
    layernorm_split_kernel<<<BB * SS, 256>>>(out, n2w, n2b, HNh, HNl);

    // 11. FC1 + exact GELU
    dim3 gF1(32, 17, 1);
    gemm_bf3<EPI_GELU_SPLIT><<<gF1, 256, GEMM_SMEM_BYTES>>>(
        HNh, HNl, WH + W_FC1, WL + W_FC1, fc1_b, nullptr,
        nullptr, HHh, HHl, 2050, 4096, 1024, 0, 0, 0);

    // 12. FC2 + residual
    dim3 gF2(8, 17, 1);
    gemm_bf3<EPI_BIAS_RESID><<<gF2, 256, GEMM_SMEM_BYTES>>>(
        HHh, HHl, WH + W_FC2, WL + W_FC2, fc2_b, out,
        out, nullptr, nullptr, 2050, 1024, 4096, 0, 0, 0);

    (void)in_sizes; (void)n_in; (void)out_size;
}

// round 14
// speedup vs baseline: 1.2140x; 1.0021x over previous
#include <cuda_runtime.h>
#include <cuda_bf16.h>
#include <stdint.h>
#include <math.h>

// ---------------------------------------------------------------------------
// Problem constants
// ---------------------------------------------------------------------------
#define BB   2
#define SS   1025
#define DD   1024
#define HH_  16
#define HD_  64
#define PP   1024
#define KR_  32
#define SCALE_ 0.125f
#define INV_TEMP 10.0f

// ---------------------------------------------------------------------------
// Scratch (float units). bf16 buffers live inside the float array.
// ---------------------------------------------------------------------------
static const size_t F_QR   = 2048ull * 1024;        // with F_KR: fused rq|rk C [2048 x 2048]
static const size_t F_KR   = 2048ull * 1024;
static const size_t F_SC   = 2048ull * 1024;        // scores partial 0
static const size_t F_SC2  = 2048ull * 1024;        // scores partial 1
static const size_t F_QKV  = 2050ull * 3072;
static const size_t F_LW   = 2048ull * 32;
static const size_t F_RT   = 2048ull * 32;
static const size_t F_P1   = 2050ull * 1024;        // split-K partial 0 (proj/fc2)
static const size_t F_P2   = 2050ull * 1024;        // split-K partial 1
static const size_t H_XN   = 2050ull * 1024 / 2;
static const size_t H_QKR  = 4096ull * 1024 / 2;
static const size_t H_ATT  = 2050ull * 1024 / 2;
static const size_t H_HN   = 2050ull * 1024 / 2;
static const size_t H_HH   = 2050ull * 4096 / 2;
static const size_t H_W    = 14680064ull / 2;

static const size_t O_QR   = 0;
static const size_t O_KR   = O_QR  + F_QR;
static const size_t O_SC   = O_KR  + F_KR;
static const size_t O_SC2  = O_SC  + F_SC;
static const size_t O_QKV  = O_SC2 + F_SC2;
static const size_t O_LW   = O_QKV + F_QKV;
static const size_t O_RT   = O_LW  + F_LW;
static const size_t O_P1   = O_RT  + F_RT;
static const size_t O_P2   = O_P1  + F_P1;
static const size_t O_XNH  = O_P2  + F_P2;
static const size_t O_XNL  = O_XNH + H_XN;
static const size_t O_QKRH = O_XNL + H_XN;
static const size_t O_QKRL = O_QKRH + H_QKR;
static const size_t O_ATTH = O_QKRL + H_QKR;
static const size_t O_ATTL = O_ATTH + H_ATT;
static const size_t O_HNH  = O_ATTL + H_ATT;
static const size_t O_HNL  = O_HNH + H_HN;
static const size_t O_HHH  = O_HNL + H_HN;
static const size_t O_HHL  = O_HHH + H_HH;
static const size_t O_WH   = O_HHL + H_HH;
static const size_t O_WL   = O_WH  + H_W;
static const size_t SCR_TOTAL = O_WL + H_W;

static const size_t W_RQ   = 0;
static const size_t W_RK   = 1048576;       // adjacent to W_RQ: fused N=2048 B matrix
static const size_t W_QKV  = 2097152;
static const size_t W_PROJ = 5242880;
static const size_t W_FC1  = 6291456;
static const size_t W_FC2  = 10485760;

__device__ float g_scratch[SCR_TOTAL];

// ---------------------------------------------------------------------------
// Block reductions (blockDim.x == 256)
// ---------------------------------------------------------------------------
__device__ __forceinline__ float blockReduceSum(float v, float* sbuf) {
    int lane = threadIdx.x & 31, wid = threadIdx.x >> 5;
    #pragma unroll
    for (int o = 16; o; o >>= 1) v += __shfl_xor_sync(0xffffffffu, v, o);
    if (lane == 0) sbuf[wid] = v;
    __syncthreads();
    if (wid == 0) {
        v = (lane < 8) ? sbuf[lane] : 0.f;
        #pragma unroll
        for (int o = 4; o; o >>= 1) v += __shfl_xor_sync(0xffffffffu, v, o);
        if (lane == 0) sbuf[0] = v;
    }
    __syncthreads();
    float r = sbuf[0];
    __syncthreads();
    return r;
}

__device__ __forceinline__ void split1(float v, __nv_bfloat16* hi, __nv_bfloat16* lo) {
    __nv_bfloat16 h = __float2bfloat16(v);
    *hi = h;
    *lo = __float2bfloat16(v - __bfloat162float(h));
}

// ---------------------------------------------------------------------------
// Fused weight split: all 6 weights in one launch
// ---------------------------------------------------------------------------
struct WSplit6 {
    const float* src[6];
    long dstoff[6];
    int n4[6];
};

__global__ void split_all_w_kernel(WSplit6 a,
                                   __nv_bfloat16* __restrict__ hi,
                                   __nv_bfloat16* __restrict__ lo) {
    #pragma unroll
    for (int s = 0; s < 6; s++) {
        const float4* sp = (const float4*)a.src[s];
        __nv_bfloat16* hp = hi + a.dstoff[s];
        __nv_bfloat16* lp = lo + a.dstoff[s];
        const int n4 = a.n4[s];
        for (int i = blockIdx.x * blockDim.x + threadIdx.x; i < n4;
             i += gridDim.x * blockDim.x) {
            float4 f = sp[i];
            __nv_bfloat162 h0 = __floats2bfloat162_rn(f.x, f.y);
            __nv_bfloat162 h1 = __floats2bfloat162_rn(f.z, f.w);
            __nv_bfloat162 l0 = __floats2bfloat162_rn(f.x - __bfloat162float(h0.x),
                                                      f.y - __bfloat162float(h0.y));
            __nv_bfloat162 l1 = __floats2bfloat162_rn(f.z - __bfloat162float(h1.x),
                                                      f.w - __bfloat162float(h1.y));
            uint2 hv; hv.x = *(unsigned*)&h0; hv.y = *(unsigned*)&h1;
            uint2 lv; lv.x = *(unsigned*)&l0; lv.y = *(unsigned*)&l1;
            *(uint2*)(hp + (size_t)i * 4) = hv;
            *(uint2*)(lp + (size_t)i * 4) = lv;
        }
    }
}

// ---------------------------------------------------------------------------
// LayerNorm 1 -> hi/lo bf16 planes
// ---------------------------------------------------------------------------
__global__ void layernorm_split_kernel(const float* __restrict__ in,
                                       const float* __restrict__ w,
                                       const float* __restrict__ b,
                                       __nv_bfloat16* __restrict__ outh,
                                       __nv_bfloat16* __restrict__ outl) {
    __shared__ float red[32];
    int row = blockIdx.x, tid = threadIdx.x;
    const float4* ip = (const float4*)(in + (size_t)row * 1024);
    float4 v = ip[tid];
    float s = v.x + v.y + v.z + v.w;
    float mean = blockReduceSum(s, red) * (1.f / 1024.f);
    float dx = v.x - mean, dy = v.y - mean, dz = v.z - mean, dw = v.w - mean;
    float ss = dx * dx + dy * dy + dz * dz + dw * dw;
    float var = blockReduceSum(ss, red) * (1.f / 1024.f);
    float rstd = rsqrtf(var + 1e-5f);
    float4 wv = ((const float4*)w)[tid];
    float4 bv = ((const float4*)b)[tid];
    float ox = dx * rstd * wv.x + bv.x;
    float oy = dy * rstd * wv.y + bv.y;
    float oz = dz * rstd * wv.z + bv.z;
    float ow = dw * rstd * wv.w + bv.w;
    __nv_bfloat162 h0 = __floats2bfloat162_rn(ox, oy);
    __nv_bfloat162 h1 = __floats2bfloat162_rn(oz, ow);
    __nv_bfloat162 l0 = __floats2bfloat162_rn(ox - __bfloat162float(h0.x),
                                              oy - __bfloat162float(h0.y));
    __nv_bfloat162 l1 = __floats2bfloat162_rn(oz - __bfloat162float(h1.x),
                                              ow - __bfloat162float(h1.y));
    uint2 hv; hv.x = *(unsigned*)&h0; hv.y = *(unsigned*)&h1;
    uint2 lv; lv.x = *(unsigned*)&l0; lv.y = *(unsigned*)&l1;
    *(uint2*)(outh + (size_t)row * 1024 + tid * 4) = hv;
    *(uint2*)(outl + (size_t)row * 1024 + tid * 4) = lv;
}

// ---------------------------------------------------------------------------
// Combine(proj split-K) + residual + LayerNorm2, fused.
// out = p1 + p2 + bias + x ; HN = LN(out) -> hi/lo planes
// ---------------------------------------------------------------------------
__global__ void ln2_combine_kernel(const float* __restrict__ p1,
                                   const float* __restrict__ p2,
                                   const float* __restrict__ bias,
                                   const float* __restrict__ x,
                                   float* __restrict__ out,
                                   const float* __restrict__ w,
                                   const float* __restrict__ b,
                                   __nv_bfloat16* __restrict__ outh,
                                   __nv_bfloat16* __restrict__ outl) {
    __shared__ float red[32];
    int row = blockIdx.x, tid = threadIdx.x;
    const size_t ro = (size_t)row * 1024;
    float4 a  = ((const float4*)(p1 + ro))[tid];
    float4 c  = ((const float4*)(p2 + ro))[tid];
    float4 xr = ((const float4*)(x + ro))[tid];
    float4 bb = ((const float4*)bias)[tid];
    float4 v;
    v.x = a.x + c.x + bb.x + xr.x;
    v.y = a.y + c.y + bb.y + xr.y;
    v.z = a.z + c.z + bb.z + xr.z;
    v.w = a.w + c.w + bb.w + xr.w;
    ((float4*)(out + ro))[tid] = v;

    float s = v.x + v.y + v.z + v.w;
    float mean = blockReduceSum(s, red) * (1.f / 1024.f);
    float dx = v.x - mean, dy = v.y - mean, dz = v.z - mean, dw = v.w - mean;
    float ss = dx * dx + dy * dy + dz * dz + dw * dw;
    float var = blockReduceSum(ss, red) * (1.f / 1024.f);
    float rstd = rsqrtf(var + 1e-5f);
    float4 wv = ((const float4*)w)[tid];
    float4 bv = ((const float4*)b)[tid];
    float ox = dx * rstd * wv.x + bv.x;
    float oy = dy * rstd * wv.y + bv.y;
    float oz = dz * rstd * wv.z + bv.z;
    float ow = dw * rstd * wv.w + bv.w;
    __nv_bfloat162 h0 = __floats2bfloat162_rn(ox, oy);
    __nv_bfloat162 h1 = __floats2bfloat162_rn(oz, ow);
    __nv_bfloat162 l0 = __floats2bfloat162_rn(ox - __bfloat162float(h0.x),
                                              oy - __bfloat162float(h0.y));
    __nv_bfloat162 l1 = __floats2bfloat162_rn(oz - __bfloat162float(h1.x),
                                              ow - __bfloat162float(h1.y));
    uint2 hv; hv.x = *(unsigned*)&h0; hv.y = *(unsigned*)&h1;
    uint2 lv; lv.x = *(unsigned*)&l0; lv.y = *(unsigned*)&l1;
    *(uint2*)(outh + ro + tid * 4) = hv;
    *(uint2*)(outl + ro + tid * 4) = lv;
}

// ---------------------------------------------------------------------------
// fc2 split-K combine: out = p1 + p2 + bias + out   (2050x1024 elementwise)
// ---------------------------------------------------------------------------
__global__ void fc2_combine_kernel(const float* __restrict__ p1,
                                   const float* __restrict__ p2,
                                   const float* __restrict__ bias,
                                   float* __restrict__ out) {
    const int total = 2050 * 256;   // float4 count
    for (int i = blockIdx.x * blockDim.x + threadIdx.x; i < total;
         i += gridDim.x * blockDim.x) {
        float4 a = ((const float4*)p1)[i];
        float4 c = ((const float4*)p2)[i];
        float4 r = ((float4*)out)[i];
        float4 bb = ((const float4*)bias)[i & 255];
        r.x += a.x + c.x + bb.x;
        r.y += a.y + c.y + bb.y;
        r.z += a.z + c.z + bb.z;
        r.w += a.w + c.w + bb.w;
        ((float4*)out)[i] = r;
    }
}

// ---------------------------------------------------------------------------
// L2 norm over the fused [2048 x 2048] rq|rk output -> hi/lo QKR planes.
// Block i<2048: q_r of global row i (cols 0..1023) -> QKR row i.
// Block i>=2048: k_r of global row i-2048 (cols 1024..2047) -> QKR row i.
// ---------------------------------------------------------------------------
__global__ void l2norm_split_kernel(const float* __restrict__ c2,
                                    __nv_bfloat16* __restrict__ outh,
                                    __nv_bfloat16* __restrict__ outl) {
    __shared__ float red[32];
    int i = blockIdx.x, tid = threadIdx.x;
    const int srcRow = i & 2047;
    const int colOff = (i >> 11) * 1024;
    const float4* p = (const float4*)(c2 + (size_t)srcRow * 2048 + colOff);
    float4 v = p[tid];
    float ss = v.x * v.x + v.y * v.y + v.z * v.z + v.w * v.w;
    float tot = blockReduceSum(ss, red);
    float sc = 1.f / fmaxf(sqrtf(tot), 1e-12f);
    float ox = v.x * sc, oy = v.y * sc, oz = v.z * sc, ow = v.w * sc;
    __nv_bfloat162 h0 = __floats2bfloat162_rn(ox, oy);
    __nv_bfloat162 h1 = __floats2bfloat162_rn(oz, ow);
    __nv_bfloat162 l0 = __floats2bfloat162_rn(ox - __bfloat162float(h0.x),
                                              oy - __bfloat162float(h0.y));
    __nv_bfloat162 l1 = __floats2bfloat162_rn(oz - __bfloat162float(h1.x),
                                              ow - __bfloat162float(h1.y));
    uint2 hv; hv.x = *(unsigned*)&h0; hv.y = *(unsigned*)&h1;
    uint2 lv; lv.x = *(unsigned*)&l0; lv.y = *(unsigned*)&l1;
    *(uint2*)(outh + (size_t)i * 1024 + tid * 4) = hv;
    *(uint2*)(outl + (size_t)i * 1024 + tid * 4) = lv;
}

// ---------------------------------------------------------------------------
// bf16x3 tensor-core NT GEMM, cp.async + ldmatrix, 2 CTAs/SM.
// z encodes (batch, ksplit): b = z / KS, ks = z % KS.
// lda/ldb are row strides (full K); Kd is the K range this launch covers.
// ---------------------------------------------------------------------------
#define EPI_NONE        0
#define EPI_BIAS        1
#define EPI_BIAS2       2
#define EPI_GELU_SPLIT  3

#define KSTRIDE 40
#define TILE_BF16 (128 * KSTRIDE)
#define SB_BASE (4 * TILE_BF16)
#define GEMM_SMEM_BYTES (8 * TILE_BF16 * 2)   // 81920

__device__ __forceinline__ void mma_bf16(float* d, const unsigned* a, const unsigned* b) {
    asm volatile(
        "mma.sync.aligned.m16n8k16.row.col.f32.bf16.bf16.f32 "
        "{%0,%1,%2,%3}, {%4,%5,%6,%7}, {%8,%9}, {%0,%1,%2,%3};"
        : "+f"(d[0]), "+f"(d[1]), "+f"(d[2]), "+f"(d[3])
        : "r"(a[0]), "r"(a[1]), "r"(a[2]), "r"(a[3]), "r"(b[0]), "r"(b[1]));
}

__device__ __forceinline__ void ldsm4(unsigned addr, unsigned& r0, unsigned& r1,
                                      unsigned& r2, unsigned& r3) {
    asm volatile("ldmatrix.sync.aligned.m8n8.x4.shared.b16 {%0,%1,%2,%3}, [%4];"
                 : "=r"(r0), "=r"(r1), "=r"(r2), "=r"(r3) : "r"(addr));
}

__device__ __forceinline__ void cpasync16(unsigned dst, const void* src, unsigned sz) {
    asm volatile("cp.async.ca.shared.global [%0], [%1], 16, %2;"
                 :: "r"(dst), "l"(src), "r"(sz));
}

template <int EPI>
__global__ __launch_bounds__(256, 2) void gemm_bf3(
    const __nv_bfloat16* __restrict__ Ah, const __nv_bfloat16* __restrict__ Al,
    const __nv_bfloat16* __restrict__ Bh, const __nv_bfloat16* __restrict__ Bl,
    const float* __restrict__ bias, const float* __restrict__ extra,
    float* __restrict__ C, __nv_bfloat16* __restrict__ Ch, __nv_bfloat16* __restrict__ Cl,
    int M, int N, int Kd, int lda, int ldb,
    long sA, long sB, long sC, long sCk, int KS) {

    const int zb = blockIdx.z / KS;
    const int ks = blockIdx.z % KS;
    Ah += (long)zb * sA + (long)ks * Kd;  Al += (long)zb * sA + (long)ks * Kd;
    Bh += (long)zb * sB + (long)ks * Kd;  Bl += (long)zb * sB + (long)ks * Kd;
    const long cOff = (long)zb * sC + (long)ks * sCk;

    extern __shared__ __nv_bfloat16 sm[];

    const int tid  = threadIdx.x;
    const int lane = tid & 31;
    const int wid  = tid >> 5;
    const int wr   = wid & 3;
    const int wc   = wid >> 2;
    const int g    = lane >> 2;
    const int tig  = lane & 3;
    const int bm   = blockIdx.y * 128;
    const int bn   = blockIdx.x * 128;

    float acc[2][8][4];
    #pragma unroll
    for (int mi = 0; mi < 2; mi++)
        #pragma unroll
        for (int ni = 0; ni < 8; ni++)
            #pragma unroll
            for (int r = 0; r < 4; r++) acc[mi][ni][r] = 0.f;

    const int ldRow = tid >> 1;
    const int half  = tid & 1;
    const int aRow  = bm + ldRow;
    const unsigned aSz = (aRow < M) ? 16u : 0u;
    const long aOff = (long)((aRow < M) ? aRow : 0) * lda + half * 16;
    const long bOff = (long)(bn + ldRow) * ldb + half * 16;
    const __nv_bfloat16* aH = Ah + aOff;
    const __nv_bfloat16* aL = Al + aOff;
    const __nv_bfloat16* bH = Bh + bOff;
    const __nv_bfloat16* bL = Bl + bOff;

    const unsigned smBase = (unsigned)__cvta_generic_to_shared(sm);
    const unsigned dA0 = smBase + 2u * (unsigned)(ldRow * KSTRIDE + half * 16);
    const unsigned stagePitch = 2u * (unsigned)(2 * TILE_BF16);
    const unsigned hlPitch    = 2u * (unsigned)TILE_BF16;
    const unsigned bPlane     = 2u * (unsigned)SB_BASE;

    const int aRowL = wr * 32 + (lane & 7) + ((lane >> 3) & 1) * 8;
    const int aKL   = ((lane >> 4) & 1) * 8;
    const unsigned aLaneOff = (unsigned)(aRowL * KSTRIDE + aKL);
    const int bRowL = wc * 64 + (lane & 7) + ((lane >> 4) & 1) * 8;
    const int bKL   = ((lane >> 3) & 1) * 8;
    const unsigned bLaneOff = (unsigned)(bRowL * KSTRIDE + bKL);

    const int nIter = Kd >> 5;

    #define ISSUE(st, itv) do {                                              \
        const long k0 = (long)(itv) * 32;                                    \
        unsigned d0 = dA0 + (unsigned)(st) * stagePitch;                     \
        cpasync16(d0,            aH + k0,     aSz);                          \
        cpasync16(d0 + 16,       aH + k0 + 8, aSz);                          \
        cpasync16(d0 + hlPitch,      aL + k0,     aSz);                      \
        cpasync16(d0 + hlPitch + 16, aL + k0 + 8, aSz);                      \
        unsigned d1 = d0 + bPlane;                                           \
        cpasync16(d1,            bH + k0,     16u);                          \
        cpasync16(d1 + 16,       bH + k0 + 8, 16u);                          \
        cpasync16(d1 + hlPitch,      bL + k0,     16u);                      \
        cpasync16(d1 + hlPitch + 16, bL + k0 + 8, 16u);                      \
        asm volatile("cp.async.commit_group;");                              \
    } while (0)

    ISSUE(0, 0);
    if (nIter > 1) ISSUE(1, 1);

    for (int it = 0; it < nIter; ++it) {
        if (it == nIter - 1) asm volatile("cp.async.wait_group 0;");
        else                 asm volatile("cp.async.wait_group 1;");
        __syncthreads();

        const int s = it & 1;
        const unsigned pA_hi = (unsigned)((s * 2 + 0) * TILE_BF16);
        const unsigned pA_lo = (unsigned)((s * 2 + 1) * TILE_BF16);
        const unsigned pB_hi = (unsigned)(SB_BASE + (s * 2 + 0) * TILE_BF16);
        const unsigned pB_lo = (unsigned)(SB_BASE + (s * 2 + 1) * TILE_BF16);

        #pragma unroll
        for (int ksl = 0; ksl < 2; ksl++) {
            const int kb = ksl * 16;
            unsigned Ahf[2][4], Alf[2][4], Bhf[8][2], Blf[8][2];
            #pragma unroll
            for (int mi = 0; mi < 2; mi++) {
                unsigned off = (unsigned)(mi * 16 * KSTRIDE + kb) + aLaneOff;
                ldsm4(smBase + 2u * (pA_hi + off), Ahf[mi][0], Ahf[mi][1], Ahf[mi][2], Ahf[mi][3]);
                ldsm4(smBase + 2u * (pA_lo + off), Alf[mi][0], Alf[mi][1], Alf[mi][2], Alf[mi][3]);
            }
            #pragma unroll
            for (int j = 0; j < 4; j++) {
                unsigned off = (unsigned)(j * 16 * KSTRIDE + kb) + bLaneOff;
                ldsm4(smBase + 2u * (pB_hi + off),
                      Bhf[j * 2][0], Bhf[j * 2][1], Bhf[j * 2 + 1][0], Bhf[j * 2 + 1][1]);
                ldsm4(smBase + 2u * (pB_lo + off),
                      Blf[j * 2][0], Blf[j * 2][1], Blf[j * 2 + 1][0], Blf[j * 2 + 1][1]);
            }
            #pragma unroll
            for (int mi = 0; mi < 2; mi++)
                #pragma unroll
                for (int ni = 0; ni < 8; ni++) {
                    mma_bf16(acc[mi][ni], Ahf[mi], Bhf[ni]);
                    mma_bf16(acc[mi][ni], Alf[mi], Bhf[ni]);
                    mma_bf16(acc[mi][ni], Ahf[mi], Blf[ni]);
                }
        }
        __syncthreads();

        if (it + 2 < nIter) ISSUE(s, it + 2);
    }
    #undef ISSUE

    #pragma unroll
    for (int mi = 0; mi < 2; mi++) {
        #pragma unroll
        for (int rr = 0; rr < 2; rr++) {
            const int m = bm + wr * 32 + mi * 16 + g + rr * 8;
            if (m >= M) continue;
            #pragma unroll
            for (int ni = 0; ni < 8; ni++) {
                #pragma unroll
                for (int cc = 0; cc < 2; cc++) {
                    const int n = bn + wc * 64 + ni * 8 + tig * 2 + cc;
                    float v = acc[mi][ni][rr * 2 + cc];
                    const long idx = cOff + (long)m * N + n;
                    if (EPI == EPI_NONE) {
                        C[idx] = v;
                    } else if (EPI == EPI_BIAS) {
                        C[idx] = v + bias[n];
                    } else if (EPI == EPI_BIAS2) {
                        const int hN = N >> 1;
                        C[idx] = v + (n < hN ? bias[n] : extra[n - hN]);
                    } else if (EPI == EPI_GELU_SPLIT) {
                        v += bias[n];
                        v = 0.5f * v * (1.0f + erff(v * 0.70710678118654752f));
                        split1(v, Ch + idx, Cl + idx);
                    }
                }
            }
        }
    }
}

// ---------------------------------------------------------------------------
// Top-K=32: sums split-K partials + cantor bias + diag mask at load.
// 8 warps extract per-slice top-32, warp 0 merges. Tie-break: lower index.
// ---------------------------------------------------------------------------
__global__ void topk_kernel(const float* __restrict__ sc1,
                            const float* __restrict__ sc2,
                            const float* __restrict__ pos_bias,
                            int* __restrict__ routes,
                            float* __restrict__ logw) {
    __shared__ float wv[8][32];
    __shared__ int   wi[8][32];
    __shared__ float sv[32];
    __shared__ int   si[32];
    const int row = blockIdx.x, tid = threadIdx.x;
    const int lane = tid & 31, w = tid >> 5;
    const int p = row & 1023;
    const float* s1 = sc1 + (size_t)row * 1024;
    const float* s2 = sc2 + (size_t)row * 1024;
    const float* pb = pos_bias + (size_t)p * 1024;

    float v[4]; int id4[4];
    #pragma unroll
    for (int c = 0; c < 4; c++) {
        int id = w * 128 + c * 32 + lane;
        float val = s1[id] + s2[id] + pb[id];
        if (id == p) val = -1e9f;
        v[c] = val;
        id4[c] = id;
    }

    for (int it = 0; it < 32; it++) {
        float bv = v[0]; int bi = id4[0]; int bs = 0;
        #pragma unroll
        for (int c = 1; c < 4; c++)
            if (v[c] > bv || (v[c] == bv && id4[c] < bi)) { bv = v[c]; bi = id4[c]; bs = c; }
        float cv = bv; int ci = bi;
        #pragma unroll
        for (int o = 16; o; o >>= 1) {
            float ov = __shfl_xor_sync(0xffffffffu, cv, o);
            int   oi = __shfl_xor_sync(0xffffffffu, ci, o);
            if (ov > cv || (ov == cv && oi < ci)) { cv = ov; ci = oi; }
        }
        if (lane == 0) { wv[w][it] = cv; wi[w][it] = ci; }
        if (ci == bi) v[bs] = -3.4e38f;
    }
    __syncthreads();

    if (w == 0) {
        int ptr = 0;
        for (int it = 0; it < 32; it++) {
            float cv = (lane < 8 && ptr < 32) ? wv[lane][ptr] : -3.4e38f;
            int   ci = (lane < 8 && ptr < 32) ? wi[lane][ptr] : 0x7fffffff;
            float bv = cv; int bi = ci;
            #pragma unroll
            for (int o = 4; o; o >>= 1) {
                float ov = __shfl_xor_sync(0xffffffffu, bv, o);
                int   oi = __shfl_xor_sync(0xffffffffu, bi, o);
                if (ov > bv || (ov == bv && oi < bi)) { bv = ov; bi = oi; }
            }
            if (lane < 8 && ci == bi && ptr < 32) ptr++;
            if (lane == 0) { sv[it] = bv; si[it] = bi; }
        }
    }
    __syncthreads();

    if (tid < 32) {
        float t = sv[tid] * INV_TEMP;
        float tmax = sv[0] * INV_TEMP;
        float e = expf(t - tmax);
        float z = e;
        #pragma unroll
        for (int o = 16; o; o >>= 1) z += __shfl_xor_sync(0xffffffffu, z, o);
        float lw = t - (tmax + logf(z));
        routes[(size_t)row * 32 + tid] = si[tid];
        logw[(size_t)row * 32 + tid] = fmaxf(lw, -10.f);
    }
}

// ---------------------------------------------------------------------------
// CLS attention -> hi/lo ATT planes
// ---------------------------------------------------------------------------
__global__ void cls_attn_kernel(const float* __restrict__ qkv,
                                __nv_bfloat16* __restrict__ atth,
                                __nv_bfloat16* __restrict__ attl) {
    __shared__ float q[64];
    __shared__ float sp[SS];
    __shared__ float red[32];
    __shared__ float po[4][64];
    int bh = blockIdx.x, b = bh >> 4, h = bh & 15;
    int tid = threadIdx.x;
    const float* base = qkv + (size_t)b * SS * 3072;
    if (tid < 64) q[tid] = base[h * 64 + tid];
    __syncthreads();

    float lmax = -3.4e38f;
    for (int j = tid; j < SS; j += 256) {
        const float* kr = base + (size_t)j * 3072 + 1024 + h * 64;
        float d = 0.f;
        #pragma unroll
        for (int dd = 0; dd < 64; dd++) d += q[dd] * kr[dd];
        d *= SCALE_;
        sp[j] = d;
        lmax = fmaxf(lmax, d);
    }
    // block max
    {
        int lane = tid & 31, wid5 = tid >> 5;
        #pragma unroll
        for (int o = 16; o; o >>= 1) lmax = fmaxf(lmax, __shfl_xor_sync(0xffffffffu, lmax, o));
        if (lane == 0) red[wid5] = lmax;
        __syncthreads();
        if (wid5 == 0) {
            float t = (lane < 8) ? red[lane] : -3.4e38f;
            #pragma unroll
            for (int o = 4; o; o >>= 1) t = fmaxf(t, __shfl_xor_sync(0xffffffffu, t, o));
            if (lane == 0) red[0] = t;
        }
        __syncthreads();
        lmax = red[0];
        __syncthreads();
    }
    float ls = 0.f;
    for (int j = tid; j < SS; j += 256) {
        float e = expf(sp[j] - lmax);
        sp[j] = e;
        ls += e;
    }
    float Z = blockReduceSum(ls, red);

    int g = tid >> 6, d = tid & 63;
    float o = 0.f;
    for (int j = g; j < SS; j += 4)
        o += sp[j] * base[(size_t)j * 3072 + 2048 + h * 64 + d];
    po[g][d] = o;
    __syncthreads();
    if (tid < 64) {
        float r = (po[0][tid] + po[1][tid] + po[2][tid] + po[3][tid]) / Z;
        size_t idx = (size_t)b * SS * 1024 + h * 64 + tid;
        split1(r, atth + idx, attl + idx);
    }
}

// ---------------------------------------------------------------------------
// Routed patch attention: one warp per head
// ---------------------------------------------------------------------------
__global__ __launch_bounds__(512) void patch_attn_kernel(
        const float* __restrict__ qkv,
        const int* __restrict__ routes,
        const float* __restrict__ logw,
        __nv_bfloat16* __restrict__ atth,
        __nv_bfloat16* __restrict__ attl) {
    __shared__ int   rt[32];
    __shared__ float lw[32];
    const int bp = blockIdx.x, b = bp >> 10, p = bp & 1023;
    const int tid = threadIdx.x, lane = tid & 31, h = tid >> 5;
    if (tid < 32) {
        rt[tid] = routes[(size_t)bp * 32 + tid] + 1;
        lw[tid] = logw[(size_t)bp * 32 + tid];
    }
    __syncthreads();

    const float* base = qkv + (size_t)b * SS * 3072;
    const float* qp = base + (size_t)(p + 1) * 3072 + h * 64;
    const float q0 = qp[lane], q1 = qp[lane + 32];

    float myscore = 0.f;
    #pragma unroll
    for (int kb = 0; kb < 32; kb += 8) {
        float k0[8], k1[8];
        #pragma unroll
        for (int j = 0; j < 8; j++) {
            const float* kp = base + (size_t)rt[kb + j] * 3072 + 1024 + h * 64;
            k0[j] = kp[lane];
            k1[j] = kp[lane + 32];
        }
        #pragma unroll
        for (int j = 0; j < 8; j++) {
            float d = q0 * k0[j] + q1 * k1[j];
            #pragma unroll
            for (int o = 16; o; o >>= 1) d += __shfl_xor_sync(0xffffffffu, d, o);
            if (lane == kb + j) myscore = d * SCALE_ + lw[lane];
        }
    }

    float m = myscore;
    #pragma unroll
    for (int o = 16; o; o >>= 1) m = fmaxf(m, __shfl_xor_sync(0xffffffffu, m, o));
    float e = expf(myscore - m);
    float z = e;
    #pragma unroll
    for (int o = 16; o; o >>= 1) z += __shfl_xor_sync(0xffffffffu, z, o);
    const float pw = e / z;

    float o0 = 0.f, o1 = 0.f;
    #pragma unroll
    for (int kb = 0; kb < 32; kb += 8) {
        float v0[8], v1[8];
        #pragma unroll
        for (int j = 0; j < 8; j++) {
            const float* vp = base + (size_t)rt[kb + j] * 3072 + 2048 + h * 64;
            v0[j] = vp[lane];
            v1[j] = vp[lane + 32];
        }
        #pragma unroll
        for (int j = 0; j < 8; j++) {
            float wj = __shfl_sync(0xffffffffu, pw, kb + j);
            o0 += wj * v0[j];
            o1 += wj * v1[j];
        }
    }

    const size_t idx = ((size_t)b * SS + p + 1) * 1024 + h * 64 + lane;
    split1(o0, atth + idx, attl + idx);
    split1(o1, atth + idx + 32, attl + idx + 32);
}

// ---------------------------------------------------------------------------
// Orchestration
// ---------------------------------------------------------------------------
extern "C" void kernel_launch(void* const* d_in, const int* in_sizes, int n_in,
                              void* d_out, int out_size) {
    const float* x        = (const float*)d_in[0];
    const float* n1w      = (const float*)d_in[1];
    const float* n1b      = (const float*)d_in[2];
    const float* rq_w     = (const float*)d_in[3];
    const float* rq_b     = (const float*)d_in[4];
    const float* rk_w     = (const float*)d_in[5];
    const float* rk_b     = (const float*)d_in[6];
    const float* pos_bias = (const float*)d_in[7];
    const float* qkv_w    = (const float*)d_in[8];
    const float* qkv_b    = (const float*)d_in[9];
    const float* proj_w   = (const float*)d_in[10];
    const float* proj_b   = (const float*)d_in[11];
    const float* n2w      = (const float*)d_in[12];
    const float* n2b      = (const float*)d_in[13];
    const float* fc1_w    = (const float*)d_in[14];
    const float* fc1_b    = (const float*)d_in[15];
    const float* fc2_w    = (const float*)d_in[16];
    const float* fc2_b    = (const float*)d_in[17];
    float* out = (float*)d_out;

    void* sp = nullptr;
    cudaGetSymbolAddress(&sp, g_scratch);
    float* SCR = (float*)sp;
    float* C2  = SCR + O_QR;        // fused rq|rk output [2048 x 2048]
    float* SC  = SCR + O_SC;
    float* SC2 = SCR + O_SC2;
    float* QKV = SCR + O_QKV;
    float* LW  = SCR + O_LW;
    int*   RT  = (int*)(SCR + O_RT);
    float* P1  = SCR + O_P1;
    float* P2  = SCR + O_P2;
    __nv_bfloat16* XNh  = (__nv_bfloat16*)(SCR + O_XNH);
    __nv_bfloat16* XNl  = (__nv_bfloat16*)(SCR + O_XNL);
    __nv_bfloat16* QKRh = (__nv_bfloat16*)(SCR + O_QKRH);
    __nv_bfloat16* QKRl = (__nv_bfloat16*)(SCR + O_QKRL);
    __nv_bfloat16* ATTh = (__nv_bfloat16*)(SCR + O_ATTH);
    __nv_bfloat16* ATTl = (__nv_bfloat16*)(SCR + O_ATTL);
    __nv_bfloat16* HNh  = (__nv_bfloat16*)(SCR + O_HNH);
    __nv_bfloat16* HNl  = (__nv_bfloat16*)(SCR + O_HNL);
    __nv_bfloat16* HHh  = (__nv_bfloat16*)(SCR + O_HHH);
    __nv_bfloat16* HHl  = (__nv_bfloat16*)(SCR + O_HHL);
    __nv_bfloat16* WH   = (__nv_bfloat16*)(SCR + O_WH);
    __nv_bfloat16* WL   = (__nv_bfloat16*)(SCR + O_WL);

    cudaFuncSetAttribute(gemm_bf3<EPI_NONE>,
                         cudaFuncAttributeMaxDynamicSharedMemorySize, GEMM_SMEM_BYTES);
    cudaFuncSetAttribute(gemm_bf3<EPI_BIAS>,
                         cudaFuncAttributeMaxDynamicSharedMemorySize, GEMM_SMEM_BYTES);
    cudaFuncSetAttribute(gemm_bf3<EPI_BIAS2>,
                         cudaFuncAttributeMaxDynamicSharedMemorySize, GEMM_SMEM_BYTES);
    cudaFuncSetAttribute(gemm_bf3<EPI_GELU_SPLIT>,
                         cudaFuncAttributeMaxDynamicSharedMemorySize, GEMM_SMEM_BYTES);

    // 0. fused weight split
    WSplit6 wargs;
    wargs.src[0] = rq_w;   wargs.dstoff[0] = (long)W_RQ;   wargs.n4[0] = 1048576 / 4;
    wargs.src[1] = rk_w;   wargs.dstoff[1] = (long)W_RK;   wargs.n4[1] = 1048576 / 4;
    wargs.src[2] = qkv_w;  wargs.dstoff[2] = (long)W_QKV;  wargs.n4[2] = 3145728 / 4;
    wargs.src[3] = proj_w; wargs.dstoff[3] = (long)W_PROJ; wargs.n4[3] = 1048576 / 4;
    wargs.src[4] = fc1_w;  wargs.dstoff[4] = (long)W_FC1;  wargs.n4[4] = 4194304 / 4;
    wargs.src[5] = fc2_w;  wargs.dstoff[5] = (long)W_FC2;  wargs.n4[5] = 4194304 / 4;
    split_all_w_kernel<<<2048, 256>>>(wargs, WH, WL);

    // 1. LayerNorm 1
    layernorm_split_kernel<<<BB * SS, 256>>>(x, n1w, n1b, XNh, XNl);

    // 2. Fused routing projections: N=2048 (rq|rk weights adjacent), grid 256
    dim3 gR(16, 8, 2);
    gemm_bf3<EPI_BIAS2><<<gR, 256, GEMM_SMEM_BYTES>>>(
        XNh + 1024, XNl + 1024, WH + W_RQ, WL + W_RQ, rq_b, rk_b,
        C2, nullptr, nullptr, 1024, 2048, 1024, 1024, 1024,
        (long)SS * DD, 0, (long)PP * 2048, 0, 1);

    // 3. L2 normalize + demux to QKR planes (4096 rows)
    l2norm_split_kernel<<<4096, 256>>>(C2, QKRh, QKRl);

    // 4. Routing scores, split-K=2: z = b*2+ks, grid 256, raw partials
    dim3 gS(8, 8, 4);
    gemm_bf3<EPI_NONE><<<gS, 256, GEMM_SMEM_BYTES>>>(
        QKRh, QKRl, QKRh + 2048ull * 1024, QKRl + 2048ull * 1024, nullptr, nullptr,
        SC, nullptr, nullptr, 1024, 1024, 512, 1024, 1024,
        1024ull * 1024, 1024ull * 1024, 1024ull * 1024, (long)(SC2 - SC), 2);

    // 5. Top-32 (+ partial sum + bias + diag) + routing weights
    topk_kernel<<<BB * PP, 256>>>(SC, SC2, pos_bias, RT, LW);

    // 6. QKV projection (grid 408, 2 CTAs/SM)
    dim3 gQ(24, 17, 1);
    gemm_bf3<EPI_BIAS><<<gQ, 256, GEMM_SMEM_BYTES>>>(
        XNh, XNl, WH + W_QKV, WL + W_QKV, qkv_b, nullptr,
        QKV, nullptr, nullptr, 2050, 3072, 1024, 1024, 1024, 0, 0, 0, 0, 1);

    // 7. CLS attention
    cls_attn_kernel<<<BB * HH_, 256>>>(QKV, ATTh, ATTl);

    // 8. Routed patch attention
    patch_attn_kernel<<<BB * PP, 512>>>(QKV, RT, LW, ATTh, ATTl);

    // 9. Output projection, split-K=2 -> partials P1/P2 (grid 272)
    dim3 gP(8, 17, 2);
    gemm_bf3<EPI_NONE><<<gP, 256, GEMM_SMEM_BYTES>>>(
        ATTh, ATTl, WH + W_PROJ, WL + W_PROJ, nullptr, nullptr,
        P1, nullptr, nullptr, 2050, 1024, 512, 1024, 1024,
        0, 0, 0, (long)(P2 - P1), 2);

    // 10. Combine + residual + LayerNorm 2 (fused)
    ln2_combine_kernel<<<BB * SS, 256>>>(P1, P2, proj_b, x, out, n2w, n2b, HNh, HNl);

    // 11. FC1 + exact GELU (grid 544)
    dim3 gF1(32, 17, 1);
    gemm_bf3<EPI_GELU_SPLIT><<<gF1, 256, GEMM_SMEM_BYTES>>>(
        HNh, HNl, WH + W_FC1, WL + W_FC1, fc1_b, nullptr,
        nullptr, HHh, HHl, 2050, 4096, 1024, 1024, 1024, 0, 0, 0, 0, 1);

    // 12. FC2, split-K=2 -> partials (grid 272), then combine + residual
    dim3 gF2(8, 17, 2);
    gemm_bf3<EPI_NONE><<<gF2, 256, GEMM_SMEM_BYTES>>>(
        HHh, HHl, WH + W_FC2, WL + W_FC2, nullptr, nullptr,
        P1, nullptr, nullptr, 2050, 1024, 2048, 4096, 4096,
        0, 0, 0, (long)(P2 - P1), 2);
    fc2_combine_kernel<<<1024, 256>>>(P1, P2, fc2_b, out);

    (void)in_sizes; (void)n_in; (void)out_size;
}

// round 15
// speedup vs baseline: 1.3729x; 1.1309x over previous
#include <cuda_runtime.h>
#include <cuda_bf16.h>
#include <stdint.h>
#include <math.h>

// ---------------------------------------------------------------------------
// Problem constants
// ---------------------------------------------------------------------------
#define BB   2
#define SS   1025
#define DD   1024
#define HH_  16
#define HD_  64
#define PP   1024
#define KR_  32
#define SCALE_ 0.125f
#define INV_TEMP 10.0f

// ---------------------------------------------------------------------------
// Scratch (float units). bf16 buffers live inside the float array.
// ---------------------------------------------------------------------------
static const size_t F_QR   = 2048ull * 1024;
static const size_t F_KR   = 2048ull * 1024;
static const size_t F_SC   = 2048ull * 1024;
static const size_t F_SC2  = 2048ull * 1024;
static const size_t F_QKV  = 2050ull * 3072;
static const size_t F_LW   = 2048ull * 32;
static const size_t F_RT   = 2048ull * 32;
static const size_t F_P1   = 2050ull * 1024;
static const size_t F_P2   = 2050ull * 1024;
static const size_t H_XN   = 2050ull * 1024 / 2;
static const size_t H_QKR  = 4096ull * 1024 / 2;
static const size_t H_ATT  = 2050ull * 1024 / 2;
static const size_t H_HN   = 2050ull * 1024 / 2;
static const size_t H_HH   = 2050ull * 4096 / 2;
static const size_t H_W    = 14680064ull / 2;

static const size_t O_QR   = 0;
static const size_t O_KR   = O_QR  + F_QR;
static const size_t O_SC   = O_KR  + F_KR;
static const size_t O_SC2  = O_SC  + F_SC;
static const size_t O_QKV  = O_SC2 + F_SC2;
static const size_t O_LW   = O_QKV + F_QKV;
static const size_t O_RT   = O_LW  + F_LW;
static const size_t O_P1   = O_RT  + F_RT;
static const size_t O_P2   = O_P1  + F_P1;
static const size_t O_XNH  = O_P2  + F_P2;
static const size_t O_XNL  = O_XNH + H_XN;
static const size_t O_QKRH = O_XNL + H_XN;
static const size_t O_QKRL = O_QKRH + H_QKR;
static const size_t O_ATTH = O_QKRL + H_QKR;
static const size_t O_ATTL = O_ATTH + H_ATT;
static const size_t O_HNH  = O_ATTL + H_ATT;
static const size_t O_HNL  = O_HNH + H_HN;
static const size_t O_HHH  = O_HNL + H_HN;
static const size_t O_HHL  = O_HHH + H_HH;
static const size_t O_WH   = O_HHL + H_HH;
static const size_t O_WL   = O_WH  + H_W;
static const size_t SCR_TOTAL = O_WL + H_W;

static const size_t W_RQ   = 0;
static const size_t W_RK   = 1048576;       // adjacent to W_RQ: fused N=2048 B matrix
static const size_t W_QKV  = 2097152;
static const size_t W_PROJ = 5242880;
static const size_t W_FC1  = 6291456;
static const size_t W_FC2  = 10485760;

__device__ float g_scratch[SCR_TOTAL];

// ---------------------------------------------------------------------------
// Block reductions (blockDim.x == 256)
// ---------------------------------------------------------------------------
__device__ __forceinline__ float blockReduceSum(float v, float* sbuf) {
    int lane = threadIdx.x & 31, wid = threadIdx.x >> 5;
    #pragma unroll
    for (int o = 16; o; o >>= 1) v += __shfl_xor_sync(0xffffffffu, v, o);
    if (lane == 0) sbuf[wid] = v;
    __syncthreads();
    if (wid == 0) {
        v = (lane < 8) ? sbuf[lane] : 0.f;
        #pragma unroll
        for (int o = 4; o; o >>= 1) v += __shfl_xor_sync(0xffffffffu, v, o);
        if (lane == 0) sbuf[0] = v;
    }
    __syncthreads();
    float r = sbuf[0];
    __syncthreads();
    return r;
}

__device__ __forceinline__ void split1(float v, __nv_bfloat16* hi, __nv_bfloat16* lo) {
    __nv_bfloat16 h = __float2bfloat16(v);
    *hi = h;
    *lo = __float2bfloat16(v - __bfloat162float(h));
}

// ---------------------------------------------------------------------------
// Fused weight split: all 6 weights in one launch
// ---------------------------------------------------------------------------
struct WSplit6 {
    const float* src[6];
    long dstoff[6];
    int n4[6];
};

__global__ void split_all_w_kernel(WSplit6 a,
                                   __nv_bfloat16* __restrict__ hi,
                                   __nv_bfloat16* __restrict__ lo) {
    #pragma unroll
    for (int s = 0; s < 6; s++) {
        const float4* sp = (const float4*)a.src[s];
        __nv_bfloat16* hp = hi + a.dstoff[s];
        __nv_bfloat16* lp = lo + a.dstoff[s];
        const int n4 = a.n4[s];
        for (int i = blockIdx.x * blockDim.x + threadIdx.x; i < n4;
             i += gridDim.x * blockDim.x) {
            float4 f = sp[i];
            __nv_bfloat162 h0 = __floats2bfloat162_rn(f.x, f.y);
            __nv_bfloat162 h1 = __floats2bfloat162_rn(f.z, f.w);
            __nv_bfloat162 l0 = __floats2bfloat162_rn(f.x - __bfloat162float(h0.x),
                                                      f.y - __bfloat162float(h0.y));
            __nv_bfloat162 l1 = __floats2bfloat162_rn(f.z - __bfloat162float(h1.x),
                                                      f.w - __bfloat162float(h1.y));
            uint2 hv; hv.x = *(unsigned*)&h0; hv.y = *(unsigned*)&h1;
            uint2 lv; lv.x = *(unsigned*)&l0; lv.y = *(unsigned*)&l1;
            *(uint2*)(hp + (size_t)i * 4) = hv;
            *(uint2*)(lp + (size_t)i * 4) = lv;
        }
    }
}

// ---------------------------------------------------------------------------
// LayerNorm 1 -> hi/lo bf16 planes
// ---------------------------------------------------------------------------
__global__ void layernorm_split_kernel(const float* __restrict__ in,
                                       const float* __restrict__ w,
                                       const float* __restrict__ b,
                                       __nv_bfloat16* __restrict__ outh,
                                       __nv_bfloat16* __restrict__ outl) {
    __shared__ float red[32];
    int row = blockIdx.x, tid = threadIdx.x;
    const float4* ip = (const float4*)(in + (size_t)row * 1024);
    float4 v = ip[tid];
    float s = v.x + v.y + v.z + v.w;
    float mean = blockReduceSum(s, red) * (1.f / 1024.f);
    float dx = v.x - mean, dy = v.y - mean, dz = v.z - mean, dw = v.w - mean;
    float ss = dx * dx + dy * dy + dz * dz + dw * dw;
    float var = blockReduceSum(ss, red) * (1.f / 1024.f);
    float rstd = rsqrtf(var + 1e-5f);
    float4 wv = ((const float4*)w)[tid];
    float4 bv = ((const float4*)b)[tid];
    float ox = dx * rstd * wv.x + bv.x;
    float oy = dy * rstd * wv.y + bv.y;
    float oz = dz * rstd * wv.z + bv.z;
    float ow = dw * rstd * wv.w + bv.w;
    __nv_bfloat162 h0 = __floats2bfloat162_rn(ox, oy);
    __nv_bfloat162 h1 = __floats2bfloat162_rn(oz, ow);
    __nv_bfloat162 l0 = __floats2bfloat162_rn(ox - __bfloat162float(h0.x),
                                              oy - __bfloat162float(h0.y));
    __nv_bfloat162 l1 = __floats2bfloat162_rn(oz - __bfloat162float(h1.x),
                                              ow - __bfloat162float(h1.y));
    uint2 hv; hv.x = *(unsigned*)&h0; hv.y = *(unsigned*)&h1;
    uint2 lv; lv.x = *(unsigned*)&l0; lv.y = *(unsigned*)&l1;
    *(uint2*)(outh + (size_t)row * 1024 + tid * 4) = hv;
    *(uint2*)(outl + (size_t)row * 1024 + tid * 4) = lv;
}

// ---------------------------------------------------------------------------
// Combine(proj split-K) + residual + LayerNorm2, fused.
// ---------------------------------------------------------------------------
__global__ void ln2_combine_kernel(const float* __restrict__ p1,
                                   const float* __restrict__ p2,
                                   const float* __restrict__ bias,
                                   const float* __restrict__ x,
                                   float* __restrict__ out,
                                   const float* __restrict__ w,
                                   const float* __restrict__ b,
                                   __nv_bfloat16* __restrict__ outh,
                                   __nv_bfloat16* __restrict__ outl) {
    __shared__ float red[32];
    int row = blockIdx.x, tid = threadIdx.x;
    const size_t ro = (size_t)row * 1024;
    float4 a  = ((const float4*)(p1 + ro))[tid];
    float4 c  = ((const float4*)(p2 + ro))[tid];
    float4 xr = ((const float4*)(x + ro))[tid];
    float4 bb = ((const float4*)bias)[tid];
    float4 v;
    v.x = a.x + c.x + bb.x + xr.x;
    v.y = a.y + c.y + bb.y + xr.y;
    v.z = a.z + c.z + bb.z + xr.z;
    v.w = a.w + c.w + bb.w + xr.w;
    ((float4*)(out + ro))[tid] = v;

    float s = v.x + v.y + v.z + v.w;
    float mean = blockReduceSum(s, red) * (1.f / 1024.f);
    float dx = v.x - mean, dy = v.y - mean, dz = v.z - mean, dw = v.w - mean;
    float ss = dx * dx + dy * dy + dz * dz + dw * dw;
    float var = blockReduceSum(ss, red) * (1.f / 1024.f);
    float rstd = rsqrtf(var + 1e-5f);
    float4 wv = ((const float4*)w)[tid];
    float4 bv = ((const float4*)b)[tid];
    float ox = dx * rstd * wv.x + bv.x;
    float oy = dy * rstd * wv.y + bv.y;
    float oz = dz * rstd * wv.z + bv.z;
    float ow = dw * rstd * wv.w + bv.w;
    __nv_bfloat162 h0 = __floats2bfloat162_rn(ox, oy);
    __nv_bfloat162 h1 = __floats2bfloat162_rn(oz, ow);
    __nv_bfloat162 l0 = __floats2bfloat162_rn(ox - __bfloat162float(h0.x),
                                              oy - __bfloat162float(h0.y));
    __nv_bfloat162 l1 = __floats2bfloat162_rn(oz - __bfloat162float(h1.x),
                                              ow - __bfloat162float(h1.y));
    uint2 hv; hv.x = *(unsigned*)&h0; hv.y = *(unsigned*)&h1;
    uint2 lv; lv.x = *(unsigned*)&l0; lv.y = *(unsigned*)&l1;
    *(uint2*)(outh + ro + tid * 4) = hv;
    *(uint2*)(outl + ro + tid * 4) = lv;
}

// ---------------------------------------------------------------------------
// fc2 split-K combine
// ---------------------------------------------------------------------------
__global__ void fc2_combine_kernel(const float* __restrict__ p1,
                                   const float* __restrict__ p2,
                                   const float* __restrict__ bias,
                                   float* __restrict__ out) {
    const int total = 2050 * 256;
    for (int i = blockIdx.x * blockDim.x + threadIdx.x; i < total;
         i += gridDim.x * blockDim.x) {
        float4 a = ((const float4*)p1)[i];
        float4 c = ((const float4*)p2)[i];
        float4 r = ((float4*)out)[i];
        float4 bb = ((const float4*)bias)[i & 255];
        r.x += a.x + c.x + bb.x;
        r.y += a.y + c.y + bb.y;
        r.z += a.z + c.z + bb.z;
        r.w += a.w + c.w + bb.w;
        ((float4*)out)[i] = r;
    }
}

// ---------------------------------------------------------------------------
// L2 norm over the fused [2048 x 2048] rq|rk output -> hi/lo QKR planes.
// ---------------------------------------------------------------------------
__global__ void l2norm_split_kernel(const float* __restrict__ c2,
                                    __nv_bfloat16* __restrict__ outh,
                                    __nv_bfloat16* __restrict__ outl) {
    __shared__ float red[32];
    int i = blockIdx.x, tid = threadIdx.x;
    const int srcRow = i & 2047;
    const int colOff = (i >> 11) * 1024;
    const float4* p = (const float4*)(c2 + (size_t)srcRow * 2048 + colOff);
    float4 v = p[tid];
    float ss = v.x * v.x + v.y * v.y + v.z * v.z + v.w * v.w;
    float tot = blockReduceSum(ss, red);
    float sc = 1.f / fmaxf(sqrtf(tot), 1e-12f);
    float ox = v.x * sc, oy = v.y * sc, oz = v.z * sc, ow = v.w * sc;
    __nv_bfloat162 h0 = __floats2bfloat162_rn(ox, oy);
    __nv_bfloat162 h1 = __floats2bfloat162_rn(oz, ow);
    __nv_bfloat162 l0 = __floats2bfloat162_rn(ox - __bfloat162float(h0.x),
                                              oy - __bfloat162float(h0.y));
    __nv_bfloat162 l1 = __floats2bfloat162_rn(oz - __bfloat162float(h1.x),
                                              ow - __bfloat162float(h1.y));
    uint2 hv; hv.x = *(unsigned*)&h0; hv.y = *(unsigned*)&h1;
    uint2 lv; lv.x = *(unsigned*)&l0; lv.y = *(unsigned*)&l1;
    *(uint2*)(outh + (size_t)i * 1024 + tid * 4) = hv;
    *(uint2*)(outl + (size_t)i * 1024 + tid * 4) = lv;
}

// ---------------------------------------------------------------------------
// bf16 tensor-core NT GEMM, cp.async + ldmatrix, 2 CTAs/SM.
// TERMS=3: ah*bh + al*bh + ah*bl (full precision)
// TERMS=2: ah*bh + al*bh        (B weight-lo dropped; route-safe GEMMs only)
// ---------------------------------------------------------------------------
#define EPI_NONE        0
#define EPI_BIAS        1
#define EPI_BIAS2       2
#define EPI_GELU_SPLIT  3

#define KSTRIDE 40
#define TILE_BF16 (128 * KSTRIDE)
#define SB_BASE (4 * TILE_BF16)
#define GEMM_SMEM_BYTES (8 * TILE_BF16 * 2)   // 81920

__device__ __forceinline__ void mma_bf16(float* d, const unsigned* a, const unsigned* b) {
    asm volatile(
        "mma.sync.aligned.m16n8k16.row.col.f32.bf16.bf16.f32 "
        "{%0,%1,%2,%3}, {%4,%5,%6,%7}, {%8,%9}, {%0,%1,%2,%3};"
        : "+f"(d[0]), "+f"(d[1]), "+f"(d[2]), "+f"(d[3])
        : "r"(a[0]), "r"(a[1]), "r"(a[2]), "r"(a[3]), "r"(b[0]), "r"(b[1]));
}

__device__ __forceinline__ void ldsm4(unsigned addr, unsigned& r0, unsigned& r1,
                                      unsigned& r2, unsigned& r3) {
    asm volatile("ldmatrix.sync.aligned.m8n8.x4.shared.b16 {%0,%1,%2,%3}, [%4];"
                 : "=r"(r0), "=r"(r1), "=r"(r2), "=r"(r3) : "r"(addr));
}

__device__ __forceinline__ void cpasync16(unsigned dst, const void* src, unsigned sz) {
    asm volatile("cp.async.ca.shared.global [%0], [%1], 16, %2;"
                 :: "r"(dst), "l"(src), "r"(sz));
}

template <int EPI, int TERMS>
__global__ __launch_bounds__(256, 2) void gemm_bf3(
    const __nv_bfloat16* __restrict__ Ah, const __nv_bfloat16* __restrict__ Al,
    const __nv_bfloat16* __restrict__ Bh, const __nv_bfloat16* __restrict__ Bl,
    const float* __restrict__ bias, const float* __restrict__ extra,
    float* __restrict__ C, __nv_bfloat16* __restrict__ Ch, __nv_bfloat16* __restrict__ Cl,
    int M, int N, int Kd, int lda, int ldb,
    long sA, long sB, long sC, long sCk, int KS) {

    const int zb = blockIdx.z / KS;
    const int ks = blockIdx.z % KS;
    Ah += (long)zb * sA + (long)ks * Kd;  Al += (long)zb * sA + (long)ks * Kd;
    Bh += (long)zb * sB + (long)ks * Kd;  Bl += (long)zb * sB + (long)ks * Kd;
    const long cOff = (long)zb * sC + (long)ks * sCk;

    extern __shared__ __nv_bfloat16 sm[];

    const int tid  = threadIdx.x;
    const int lane = tid & 31;
    const int wid  = tid >> 5;
    const int wr   = wid & 3;
    const int wc   = wid >> 2;
    const int g    = lane >> 2;
    const int tig  = lane & 3;
    const int bm   = blockIdx.y * 128;
    const int bn   = blockIdx.x * 128;

    float acc[2][8][4];
    #pragma unroll
    for (int mi = 0; mi < 2; mi++)
        #pragma unroll
        for (int ni = 0; ni < 8; ni++)
            #pragma unroll
            for (int r = 0; r < 4; r++) acc[mi][ni][r] = 0.f;

    const int ldRow = tid >> 1;
    const int half  = tid & 1;
    const int aRow  = bm + ldRow;
    const unsigned aSz = (aRow < M) ? 16u : 0u;
    const long aOff = (long)((aRow < M) ? aRow : 0) * lda + half * 16;
    const long bOff = (long)(bn + ldRow) * ldb + half * 16;
    const __nv_bfloat16* aH = Ah + aOff;
    const __nv_bfloat16* aL = Al + aOff;
    const __nv_bfloat16* bH = Bh + bOff;
    const __nv_bfloat16* bL = Bl + bOff;

    const unsigned smBase = (unsigned)__cvta_generic_to_shared(sm);
    const unsigned dA0 = smBase + 2u * (unsigned)(ldRow * KSTRIDE + half * 16);
    const unsigned stagePitch = 2u * (unsigned)(2 * TILE_BF16);
    const unsigned hlPitch    = 2u * (unsigned)TILE_BF16;
    const unsigned bPlane     = 2u * (unsigned)SB_BASE;

    const int aRowL = wr * 32 + (lane & 7) + ((lane >> 3) & 1) * 8;
    const int aKL   = ((lane >> 4) & 1) * 8;
    const unsigned aLaneOff = (unsigned)(aRowL * KSTRIDE + aKL);
    const int bRowL = wc * 64 + (lane & 7) + ((lane >> 4) & 1) * 8;
    const int bKL   = ((lane >> 3) & 1) * 8;
    const unsigned bLaneOff = (unsigned)(bRowL * KSTRIDE + bKL);

    const int nIter = Kd >> 5;

    #define ISSUE(st, itv) do {                                              \
        const long k0 = (long)(itv) * 32;                                    \
        unsigned d0 = dA0 + (unsigned)(st) * stagePitch;                     \
        cpasync16(d0,            aH + k0,     aSz);                          \
        cpasync16(d0 + 16,       aH + k0 + 8, aSz);                          \
        cpasync16(d0 + hlPitch,      aL + k0,     aSz);                      \
        cpasync16(d0 + hlPitch + 16, aL + k0 + 8, aSz);                      \
        unsigned d1 = d0 + bPlane;                                           \
        cpasync16(d1,            bH + k0,     16u);                          \
        cpasync16(d1 + 16,       bH + k0 + 8, 16u);                          \
        if (TERMS == 3) {                                                    \
            cpasync16(d1 + hlPitch,      bL + k0,     16u);                  \
            cpasync16(d1 + hlPitch + 16, bL + k0 + 8, 16u);                  \
        }                                                                    \
        asm volatile("cp.async.commit_group;");                              \
    } while (0)

    ISSUE(0, 0);
    if (nIter > 1) ISSUE(1, 1);

    for (int it = 0; it < nIter; ++it) {
        if (it == nIter - 1) asm volatile("cp.async.wait_group 0;");
        else                 asm volatile("cp.async.wait_group 1;");
        __syncthreads();

        const int s = it & 1;
        const unsigned pA_hi = (unsigned)((s * 2 + 0) * TILE_BF16);
        const unsigned pA_lo = (unsigned)((s * 2 + 1) * TILE_BF16);
        const unsigned pB_hi = (unsigned)(SB_BASE + (s * 2 + 0) * TILE_BF16);
        const unsigned pB_lo = (unsigned)(SB_BASE + (s * 2 + 1) * TILE_BF16);

        #pragma unroll
        for (int ksl = 0; ksl < 2; ksl++) {
            const int kb = ksl * 16;
            unsigned Ahf[2][4], Alf[2][4], Bhf[8][2], Blf[8][2];
            #pragma unroll
            for (int mi = 0; mi < 2; mi++) {
                unsigned off = (unsigned)(mi * 16 * KSTRIDE + kb) + aLaneOff;
                ldsm4(smBase + 2u * (pA_hi + off), Ahf[mi][0], Ahf[mi][1], Ahf[mi][2], Ahf[mi][3]);
                ldsm4(smBase + 2u * (pA_lo + off), Alf[mi][0], Alf[mi][1], Alf[mi][2], Alf[mi][3]);
            }
            #pragma unroll
            for (int j = 0; j < 4; j++) {
                unsigned off = (unsigned)(j * 16 * KSTRIDE + kb) + bLaneOff;
                ldsm4(smBase + 2u * (pB_hi + off),
                      Bhf[j * 2][0], Bhf[j * 2][1], Bhf[j * 2 + 1][0], Bhf[j * 2 + 1][1]);
                if (TERMS == 3) {
                    ldsm4(smBase + 2u * (pB_lo + off),
                          Blf[j * 2][0], Blf[j * 2][1], Blf[j * 2 + 1][0], Blf[j * 2 + 1][1]);
                }
            }
            #pragma unroll
            for (int mi = 0; mi < 2; mi++)
                #pragma unroll
                for (int ni = 0; ni < 8; ni++) {
                    mma_bf16(acc[mi][ni], Ahf[mi], Bhf[ni]);
                    mma_bf16(acc[mi][ni], Alf[mi], Bhf[ni]);
                    if (TERMS == 3) mma_bf16(acc[mi][ni], Ahf[mi], Blf[ni]);
                }
        }
        __syncthreads();

        if (it + 2 < nIter) ISSUE(s, it + 2);
    }
    #undef ISSUE

    #pragma unroll
    for (int mi = 0; mi < 2; mi++) {
        #pragma unroll
        for (int rr = 0; rr < 2; rr++) {
            const int m = bm + wr * 32 + mi * 16 + g + rr * 8;
            if (m >= M) continue;
            #pragma unroll
            for (int ni = 0; ni < 8; ni++) {
                #pragma unroll
                for (int cc = 0; cc < 2; cc++) {
                    const int n = bn + wc * 64 + ni * 8 + tig * 2 + cc;
                    float v = acc[mi][ni][rr * 2 + cc];
                    const long idx = cOff + (long)m * N + n;
                    if (EPI == EPI_NONE) {
                        C[idx] = v;
                    } else if (EPI == EPI_BIAS) {
                        C[idx] = v + bias[n];
                    } else if (EPI == EPI_BIAS2) {
                        const int hN = N >> 1;
                        C[idx] = v + (n < hN ? bias[n] : extra[n - hN]);
                    } else if (EPI == EPI_GELU_SPLIT) {
                        v += bias[n];
                        v = 0.5f * v * (1.0f + erff(v * 0.70710678118654752f));
                        split1(v, Ch + idx, Cl + idx);
                    }
                }
            }
        }
    }
}

// ---------------------------------------------------------------------------
// Top-K=32: sums split-K partials + cantor bias + diag mask at load.
// ---------------------------------------------------------------------------
__global__ void topk_kernel(const float* __restrict__ sc1,
                            const float* __restrict__ sc2,
                            const float* __restrict__ pos_bias,
                            int* __restrict__ routes,
                            float* __restrict__ logw) {
    __shared__ float wv[8][32];
    __shared__ int   wi[8][32];
    __shared__ float sv[32];
    __shared__ int   si[32];
    const int row = blockIdx.x, tid = threadIdx.x;
    const int lane = tid & 31, w = tid >> 5;
    const int p = row & 1023;
    const float* s1 = sc1 + (size_t)row * 1024;
    const float* s2 = sc2 + (size_t)row * 1024;
    const float* pb = pos_bias + (size_t)p * 1024;

    float v[4]; int id4[4];
    #pragma unroll
    for (int c = 0; c < 4; c++) {
        int id = w * 128 + c * 32 + lane;
        float val = s1[id] + s2[id] + pb[id];
        if (id == p) val = -1e9f;
        v[c] = val;
        id4[c] = id;
    }

    for (int it = 0; it < 32; it++) {
        float bv = v[0]; int bi = id4[0]; int bs = 0;
        #pragma unroll
        for (int c = 1; c < 4; c++)
            if (v[c] > bv || (v[c] == bv && id4[c] < bi)) { bv = v[c]; bi = id4[c]; bs = c; }
        float cv = bv; int ci = bi;
        #pragma unroll
        for (int o = 16; o; o >>= 1) {
            float ov = __shfl_xor_sync(0xffffffffu, cv, o);
            int   oi = __shfl_xor_sync(0xffffffffu, ci, o);
            if (ov > cv || (ov == cv && oi < ci)) { cv = ov; ci = oi; }
        }
        if (lane == 0) { wv[w][it] = cv; wi[w][it] = ci; }
        if (ci == bi) v[bs] = -3.4e38f;
    }
    __syncthreads();

    if (w == 0) {
        int ptr = 0;
        for (int it = 0; it < 32; it++) {
            float cv = (lane < 8 && ptr < 32) ? wv[lane][ptr] : -3.4e38f;
            int   ci = (lane < 8 && ptr < 32) ? wi[lane][ptr] : 0x7fffffff;
            float bv = cv; int bi = ci;
            #pragma unroll
            for (int o = 4; o; o >>= 1) {
                float ov = __shfl_xor_sync(0xffffffffu, bv, o);
                int   oi = __shfl_xor_sync(0xffffffffu, bi, o);
                if (ov > bv || (ov == bv && oi < bi)) { bv = ov; bi = oi; }
            }
            if (lane < 8 && ci == bi && ptr < 32) ptr++;
            if (lane == 0) { sv[it] = bv; si[it] = bi; }
        }
    }
    __syncthreads();

    if (tid < 32) {
        float t = sv[tid] * INV_TEMP;
        float tmax = sv[0] * INV_TEMP;
        float e = expf(t - tmax);
        float z = e;
        #pragma unroll
        for (int o = 16; o; o >>= 1) z += __shfl_xor_sync(0xffffffffu, z, o);
        float lw = t - (tmax + logf(z));
        routes[(size_t)row * 32 + tid] = si[tid];
        logw[(size_t)row * 32 + tid] = fmaxf(lw, -10.f);
    }
}

// ---------------------------------------------------------------------------
// CLS attention -> hi/lo ATT planes
// ---------------------------------------------------------------------------
__global__ void cls_attn_kernel(const float* __restrict__ qkv,
                                __nv_bfloat16* __restrict__ atth,
                                __nv_bfloat16* __restrict__ attl) {
    __shared__ float q[64];
    __shared__ float sp[SS];
    __shared__ float red[32];
    __shared__ float po[4][64];
    int bh = blockIdx.x, b = bh >> 4, h = bh & 15;
    int tid = threadIdx.x;
    const float* base = qkv + (size_t)b * SS * 3072;
    if (tid < 64) q[tid] = base[h * 64 + tid];
    __syncthreads();

    float lmax = -3.4e38f;
    for (int j = tid; j < SS; j += 256) {
        const float* kr = base + (size_t)j * 3072 + 1024 + h * 64;
        float d = 0.f;
        #pragma unroll
        for (int dd = 0; dd < 64; dd++) d += q[dd] * kr[dd];
        d *= SCALE_;
        sp[j] = d;
        lmax = fmaxf(lmax, d);
    }
    {
        int lane = tid & 31, wid5 = tid >> 5;
        #pragma unroll
        for (int o = 16; o; o >>= 1) lmax = fmaxf(lmax, __shfl_xor_sync(0xffffffffu, lmax, o));
        if (lane == 0) red[wid5] = lmax;
        __syncthreads();
        if (wid5 == 0) {
            float t = (lane < 8) ? red[lane] : -3.4e38f;
            #pragma unroll
            for (int o = 4; o; o >>= 1) t = fmaxf(t, __shfl_xor_sync(0xffffffffu, t, o));
            if (lane == 0) red[0] = t;
        }
        __syncthreads();
        lmax = red[0];
        __syncthreads();
    }
    float ls = 0.f;
    for (int j = tid; j < SS; j += 256) {
        float e = expf(sp[j] - lmax);
        sp[j] = e;
        ls += e;
    }
    float Z = blockReduceSum(ls, red);

    int g = tid >> 6, d = tid & 63;
    float o = 0.f;
    for (int j = g; j < SS; j += 4)
        o += sp[j] * base[(size_t)j * 3072 + 2048 + h * 64 + d];
    po[g][d] = o;
    __syncthreads();
    if (tid < 64) {
        float r = (po[0][tid] + po[1][tid] + po[2][tid] + po[3][tid]) / Z;
        size_t idx = (size_t)b * SS * 1024 + h * 64 + tid;
        split1(r, atth + idx, attl + idx);
    }
}

// ---------------------------------------------------------------------------
// Routed patch attention: one warp per head
// ---------------------------------------------------------------------------
__global__ __launch_bounds__(512) void patch_attn_kernel(
        const float* __restrict__ qkv,
        const int* __restrict__ routes,
        const float* __restrict__ logw,
        __nv_bfloat16* __restrict__ atth,
        __nv_bfloat16* __restrict__ attl) {
    __shared__ int   rt[32];
    __shared__ float lw[32];
    const int bp = blockIdx.x, b = bp >> 10, p = bp & 1023;
    const int tid = threadIdx.x, lane = tid & 31, h = tid >> 5;
    if (tid < 32) {
        rt[tid] = routes[(size_t)bp * 32 + tid] + 1;
        lw[tid] = logw[(size_t)bp * 32 + tid];
    }
    __syncthreads();

    const float* base = qkv + (size_t)b * SS * 3072;
    const float* qp = base + (size_t)(p + 1) * 3072 + h * 64;
    const float q0 = qp[lane], q1 = qp[lane + 32];

    float myscore = 0.f;
    #pragma unroll
    for (int kb = 0; kb < 32; kb += 8) {
        float k0[8], k1[8];
        #pragma unroll
        for (int j = 0; j < 8; j++) {
            const float* kp = base + (size_t)rt[kb + j] * 3072 + 1024 + h * 64;
            k0[j] = kp[lane];
            k1[j] = kp[lane + 32];
        }
        #pragma unroll
        for (int j = 0; j < 8; j++) {
            float d = q0 * k0[j] + q1 * k1[j];
            #pragma unroll
            for (int o = 16; o; o >>= 1) d += __shfl_xor_sync(0xffffffffu, d, o);
            if (lane == kb + j) myscore = d * SCALE_ + lw[lane];
        }
    }

    float m = myscore;
    #pragma unroll
    for (int o = 16; o; o >>= 1) m = fmaxf(m, __shfl_xor_sync(0xffffffffu, m, o));
    float e = expf(myscore - m);
    float z = e;
    #pragma unroll
    for (int o = 16; o; o >>= 1) z += __shfl_xor_sync(0xffffffffu, z, o);
    const float pw = e / z;

    float o0 = 0.f, o1 = 0.f;
    #pragma unroll
    for (int kb = 0; kb < 32; kb += 8) {
        float v0[8], v1[8];
        #pragma unroll
        for (int j = 0; j < 8; j++) {
            const float* vp = base + (size_t)rt[kb + j] * 3072 + 2048 + h * 64;
            v0[j] = vp[lane];
            v1[j] = vp[lane + 32];
        }
        #pragma unroll
        for (int j = 0; j < 8; j++) {
            float wj = __shfl_sync(0xffffffffu, pw, kb + j);
            o0 += wj * v0[j];
            o1 += wj * v1[j];
        }
    }

    const size_t idx = ((size_t)b * SS + p + 1) * 1024 + h * 64 + lane;
    split1(o0, atth + idx, attl + idx);
    split1(o1, atth + idx + 32, attl + idx + 32);
}

// ---------------------------------------------------------------------------
// Orchestration
// ---------------------------------------------------------------------------
extern "C" void kernel_launch(void* const* d_in, const int* in_sizes, int n_in,
                              void* d_out, int out_size) {
    const float* x        = (const float*)d_in[0];
    const float* n1w      = (const float*)d_in[1];
    const float* n1b      = (const float*)d_in[2];
    const float* rq_w     = (const float*)d_in[3];
    const float* rq_b     = (const float*)d_in[4];
    const float* rk_w     = (const float*)d_in[5];
    const float* rk_b     = (const float*)d_in[6];
    const float* pos_bias = (const float*)d_in[7];
    const float* qkv_w    = (const float*)d_in[8];
    const float* qkv_b    = (const float*)d_in[9];
    const float* proj_w   = (const float*)d_in[10];
    const float* proj_b   = (const float*)d_in[11];
    const float* n2w      = (const float*)d_in[12];
    const float* n2b      = (const float*)d_in[13];
    const float* fc1_w    = (const float*)d_in[14];
    const float* fc1_b    = (const float*)d_in[15];
    const float* fc2_w    = (const float*)d_in[16];
    const float* fc2_b    = (const float*)d_in[17];
    float* out = (float*)d_out;

    void* sp = nullptr;
    cudaGetSymbolAddress(&sp, g_scratch);
    float* SCR = (float*)sp;
    float* C2  = SCR + O_QR;
    float* SC  = SCR + O_SC;
    float* SC2 = SCR + O_SC2;
    float* QKV = SCR + O_QKV;
    float* LW  = SCR + O_LW;
    int*   RT  = (int*)(SCR + O_RT);
    float* P1  = SCR + O_P1;
    float* P2  = SCR + O_P2;
    __nv_bfloat16* XNh  = (__nv_bfloat16*)(SCR + O_XNH);
    __nv_bfloat16* XNl  = (__nv_bfloat16*)(SCR + O_XNL);
    __nv_bfloat16* QKRh = (__nv_bfloat16*)(SCR + O_QKRH);
    __nv_bfloat16* QKRl = (__nv_bfloat16*)(SCR + O_QKRL);
    __nv_bfloat16* ATTh = (__nv_bfloat16*)(SCR + O_ATTH);
    __nv_bfloat16* ATTl = (__nv_bfloat16*)(SCR + O_ATTL);
    __nv_bfloat16* HNh  = (__nv_bfloat16*)(SCR + O_HNH);
    __nv_bfloat16* HNl  = (__nv_bfloat16*)(SCR + O_HNL);
    __nv_bfloat16* HHh  = (__nv_bfloat16*)(SCR + O_HHH);
    __nv_bfloat16* HHl  = (__nv_bfloat16*)(SCR + O_HHL);
    __nv_bfloat16* WH   = (__nv_bfloat16*)(SCR + O_WH);
    __nv_bfloat16* WL   = (__nv_bfloat16*)(SCR + O_WL);

    cudaFuncSetAttribute(gemm_bf3<EPI_NONE, 3>,
                         cudaFuncAttributeMaxDynamicSharedMemorySize, GEMM_SMEM_BYTES);
    cudaFuncSetAttribute(gemm_bf3<EPI_NONE, 2>,
                         cudaFuncAttributeMaxDynamicSharedMemorySize, GEMM_SMEM_BYTES);
    cudaFuncSetAttribute(gemm_bf3<EPI_BIAS, 2>,
                         cudaFuncAttributeMaxDynamicSharedMemorySize, GEMM_SMEM_BYTES);
    cudaFuncSetAttribute(gemm_bf3<EPI_BIAS2, 3>,
                         cudaFuncAttributeMaxDynamicSharedMemorySize, GEMM_SMEM_BYTES);
    cudaFuncSetAttribute(gemm_bf3<EPI_GELU_SPLIT, 3>,
                         cudaFuncAttributeMaxDynamicSharedMemorySize, GEMM_SMEM_BYTES);

    // 0. fused weight split
    WSplit6 wargs;
    wargs.src[0] = rq_w;   wargs.dstoff[0] = (long)W_RQ;   wargs.n4[0] = 1048576 / 4;
    wargs.src[1] = rk_w;   wargs.dstoff[1] = (long)W_RK;   wargs.n4[1] = 1048576 / 4;
    wargs.src[2] = qkv_w;  wargs.dstoff[2] = (long)W_QKV;  wargs.n4[2] = 3145728 / 4;
    wargs.src[3] = proj_w; wargs.dstoff[3] = (long)W_PROJ; wargs.n4[3] = 1048576 / 4;
    wargs.src[4] = fc1_w;  wargs.dstoff[4] = (long)W_FC1;  wargs.n4[4] = 4194304 / 4;
    wargs.src[5] = fc2_w;  wargs.dstoff[5] = (long)W_FC2;  wargs.n4[5] = 4194304 / 4;
    split_all_w_kernel<<<2048, 256>>>(wargs, WH, WL);

    // 1. LayerNorm 1
    layernorm_split_kernel<<<BB * SS, 256>>>(x, n1w, n1b, XNh, XNl);

    // 2. Fused routing projections (3-term: feeds routes)
    dim3 gR(16, 8, 2);
    gemm_bf3<EPI_BIAS2, 3><<<gR, 256, GEMM_SMEM_BYTES>>>(
        XNh + 1024, XNl + 1024, WH + W_RQ, WL + W_RQ, rq_b, rk_b,
        C2, nullptr, nullptr, 1024, 2048, 1024, 1024, 1024,
        (long)SS * DD, 0, (long)PP * 2048, 0, 1);

    // 3. L2 normalize + demux
    l2norm_split_kernel<<<4096, 256>>>(C2, QKRh, QKRl);

    // 4. Routing scores, split-K=2 (3-term: feeds routes)
    dim3 gS(8, 8, 4);
    gemm_bf3<EPI_NONE, 3><<<gS, 256, GEMM_SMEM_BYTES>>>(
        QKRh, QKRl, QKRh + 2048ull * 1024, QKRl + 2048ull * 1024, nullptr, nullptr,
        SC, nullptr, nullptr, 1024, 1024, 512, 1024, 1024,
        1024ull * 1024, 1024ull * 1024, 1024ull * 1024, (long)(SC2 - SC), 2);

    // 5. Top-32 + routing weights
    topk_kernel<<<BB * PP, 256>>>(SC, SC2, pos_bias, RT, LW);

    // 6. QKV projection (2-term: route-safe)
    dim3 gQ(24, 17, 1);
    gemm_bf3<EPI_BIAS, 2><<<gQ, 256, GEMM_SMEM_BYTES>>>(
        XNh, XNl, WH + W_QKV, WL + W_QKV, qkv_b, nullptr,
        QKV, nullptr, nullptr, 2050, 3072, 1024, 1024, 1024, 0, 0, 0, 0, 1);

    // 7. CLS attention
    cls_attn_kernel<<<BB * HH_, 256>>>(QKV, ATTh, ATTl);

    // 8. Routed patch attention
    patch_attn_kernel<<<BB * PP, 512>>>(QKV, RT, LW, ATTh, ATTl);

    // 9. Output projection, split-K=2 (2-term)
    dim3 gP(8, 17, 2);
    gemm_bf3<EPI_NONE, 2><<<gP, 256, GEMM_SMEM_BYTES>>>(
        ATTh, ATTl, WH + W_PROJ, WL + W_PROJ, nullptr, nullptr,
        P1, nullptr, nullptr, 2050, 1024, 512, 1024, 1024,
        0, 0, 0, (long)(P2 - P1), 2);

    // 10. Combine + residual + LayerNorm 2
    ln2_combine_kernel<<<BB * SS, 256>>>(P1, P2, proj_b, x, out, n2w, n2b, HNh, HNl);

    // 11. FC1 + exact GELU (3-term: noise amplifies through fc2 K=4096)
    dim3 gF1(32, 17, 1);
    gemm_bf3<EPI_GELU_SPLIT, 3><<<gF1, 256, GEMM_SMEM_BYTES>>>(
        HNh, HNl, WH + W_FC1, WL + W_FC1, fc1_b, nullptr,
        nullptr, HHh, HHl, 2050, 4096, 1024, 1024, 1024, 0, 0, 0, 0, 1);

    // 12. FC2, split-K=2 (2-term), combine + residual
    dim3 gF2(8, 17, 2);
    gemm_bf3<EPI_NONE, 2><<<gF2, 256, GEMM_SMEM_BYTES>>>(
        HHh, HHl, WH + W_FC2, WL + W_FC2, nullptr, nullptr,
        P1, nullptr, nullptr, 2050, 1024, 2048, 4096, 4096,
        0, 0, 0, (long)(P2 - P1), 2);
    fc2_combine_kernel<<<1024, 256>>>(P1, P2, fc2_b, out);

    (void)in_sizes; (void)n_in; (void)out_size;
}

// round 16
// speedup vs baseline: 1.3881x; 1.0110x over previous
#include <cuda_runtime.h>
#include <cuda_bf16.h>
#include <stdint.h>
#include <math.h>

// ---------------------------------------------------------------------------
// Problem constants
// ---------------------------------------------------------------------------
#define BB   2
#define SS   1025
#define DD   1024
#define HH_  16
#define HD_  64
#define PP   1024
#define KR_  32
#define SCALE_ 0.125f
#define INV_TEMP 10.0f

// ---------------------------------------------------------------------------
// Scratch
// ---------------------------------------------------------------------------
static const size_t F_QR   = 2048ull * 1024;
static const size_t F_KR   = 2048ull * 1024;
static const size_t F_SC   = 2048ull * 1024;
static const size_t F_SC2  = 2048ull * 1024;
static const size_t F_QKV  = 2050ull * 3072;
static const size_t F_LW   = 2048ull * 32;
static const size_t F_RT   = 2048ull * 32;
static const size_t F_P1   = 2050ull * 1024;
static const size_t F_P2   = 2050ull * 1024;
static const size_t H_XN   = 2050ull * 1024 / 2;
static const size_t H_QKR  = 4096ull * 1024 / 2;
static const size_t H_ATT  = 2050ull * 1024 / 2;
static const size_t H_HN   = 2050ull * 1024 / 2;
static const size_t H_HH   = 2050ull * 4096 / 2;
static const size_t H_W    = 14680064ull / 2;

static const size_t O_QR   = 0;
static const size_t O_KR   = O_QR  + F_QR;
static const size_t O_SC   = O_KR  + F_KR;
static const size_t O_SC2  = O_SC  + F_SC;
static const size_t O_QKV  = O_SC2 + F_SC2;
static const size_t O_LW   = O_QKV + F_QKV;
static const size_t O_RT   = O_LW  + F_LW;
static const size_t O_P1   = O_RT  + F_RT;
static const size_t O_P2   = O_P1  + F_P1;
static const size_t O_XNH  = O_P2  + F_P2;
static const size_t O_XNL  = O_XNH + H_XN;
static const size_t O_QKRH = O_XNL + H_XN;
static const size_t O_QKRL = O_QKRH + H_QKR;
static const size_t O_ATTH = O_QKRL + H_QKR;
static const size_t O_ATTL = O_ATTH + H_ATT;
static const size_t O_HNH  = O_ATTL + H_ATT;
static const size_t O_HNL  = O_HNH + H_HN;
static const size_t O_HHH  = O_HNL + H_HN;
static const size_t O_HHL  = O_HHH + H_HH;
static const size_t O_WH   = O_HHL + H_HH;
static const size_t O_WL   = O_WH  + H_W;
static const size_t SCR_TOTAL = O_WL + H_W;

static const size_t W_RQ   = 0;
static const size_t W_RK   = 1048576;
static const size_t W_QKV  = 2097152;
static const size_t W_PROJ = 5242880;
static const size_t W_FC1  = 6291456;
static const size_t W_FC2  = 10485760;

__device__ float g_scratch[SCR_TOTAL];

// ---------------------------------------------------------------------------
// Block reductions (256-thread blocks)
// ---------------------------------------------------------------------------
__device__ __forceinline__ float blockReduceSum(float v, float* sbuf) {
    int lane = threadIdx.x & 31, wid = threadIdx.x >> 5;
    #pragma unroll
    for (int o = 16; o; o >>= 1) v += __shfl_xor_sync(0xffffffffu, v, o);
    if (lane == 0) sbuf[wid] = v;
    __syncthreads();
    if (wid == 0) {
        v = (lane < 8) ? sbuf[lane] : 0.f;
        #pragma unroll
        for (int o = 4; o; o >>= 1) v += __shfl_xor_sync(0xffffffffu, v, o);
        if (lane == 0) sbuf[0] = v;
    }
    __syncthreads();
    float r = sbuf[0];
    __syncthreads();
    return r;
}

// 512-thread block sum (16 warps)
__device__ __forceinline__ float blockReduceSum512(float v, float* sbuf) {
    int lane = threadIdx.x & 31, wid = threadIdx.x >> 5;
    #pragma unroll
    for (int o = 16; o; o >>= 1) v += __shfl_xor_sync(0xffffffffu, v, o);
    if (lane == 0) sbuf[wid] = v;
    __syncthreads();
    if (wid == 0) {
        v = (lane < 16) ? sbuf[lane] : 0.f;
        #pragma unroll
        for (int o = 8; o; o >>= 1) v += __shfl_xor_sync(0xffffffffu, v, o);
        if (lane == 0) sbuf[0] = v;
    }
    __syncthreads();
    float r = sbuf[0];
    __syncthreads();
    return r;
}

__device__ __forceinline__ float blockReduceMax512(float v, float* sbuf) {
    int lane = threadIdx.x & 31, wid = threadIdx.x >> 5;
    #pragma unroll
    for (int o = 16; o; o >>= 1) v = fmaxf(v, __shfl_xor_sync(0xffffffffu, v, o));
    if (lane == 0) sbuf[wid] = v;
    __syncthreads();
    if (wid == 0) {
        v = (lane < 16) ? sbuf[lane] : -3.4e38f;
        #pragma unroll
        for (int o = 8; o; o >>= 1) v = fmaxf(v, __shfl_xor_sync(0xffffffffu, v, o));
        if (lane == 0) sbuf[0] = v;
    }
    __syncthreads();
    float r = sbuf[0];
    __syncthreads();
    return r;
}

__device__ __forceinline__ void split1(float v, __nv_bfloat16* hi, __nv_bfloat16* lo) {
    __nv_bfloat16 h = __float2bfloat16(v);
    *hi = h;
    *lo = __float2bfloat16(v - __bfloat162float(h));
}

// ---------------------------------------------------------------------------
// Merged: LayerNorm1 (blocks 0..2049) + weight split (blocks 2050..4097)
// ---------------------------------------------------------------------------
struct WSplit6 {
    const float* src[6];
    long dstoff[6];
    int n4[6];
};

__global__ void ln1_splitw_kernel(WSplit6 a,
                                  __nv_bfloat16* __restrict__ whi,
                                  __nv_bfloat16* __restrict__ wlo,
                                  const float* __restrict__ in,
                                  const float* __restrict__ w,
                                  const float* __restrict__ b,
                                  __nv_bfloat16* __restrict__ outh,
                                  __nv_bfloat16* __restrict__ outl) {
    __shared__ float red[32];
    const int tid = threadIdx.x;
    if (blockIdx.x < 2050) {
        const int row = blockIdx.x;
        const float4* ip = (const float4*)(in + (size_t)row * 1024);
        float4 v = ip[tid];
        float s = v.x + v.y + v.z + v.w;
        float mean = blockReduceSum(s, red) * (1.f / 1024.f);
        float dx = v.x - mean, dy = v.y - mean, dz = v.z - mean, dw = v.w - mean;
        float ss = dx * dx + dy * dy + dz * dz + dw * dw;
        float var = blockReduceSum(ss, red) * (1.f / 1024.f);
        float rstd = rsqrtf(var + 1e-5f);
        float4 wv = ((const float4*)w)[tid];
        float4 bv = ((const float4*)b)[tid];
        float ox = dx * rstd * wv.x + bv.x;
        float oy = dy * rstd * wv.y + bv.y;
        float oz = dz * rstd * wv.z + bv.z;
        float ow = dw * rstd * wv.w + bv.w;
        __nv_bfloat162 h0 = __floats2bfloat162_rn(ox, oy);
        __nv_bfloat162 h1 = __floats2bfloat162_rn(oz, ow);
        __nv_bfloat162 l0 = __floats2bfloat162_rn(ox - __bfloat162float(h0.x),
                                                  oy - __bfloat162float(h0.y));
        __nv_bfloat162 l1 = __floats2bfloat162_rn(oz - __bfloat162float(h1.x),
                                                  ow - __bfloat162float(h1.y));
        uint2 hv; hv.x = *(unsigned*)&h0; hv.y = *(unsigned*)&h1;
        uint2 lv; lv.x = *(unsigned*)&l0; lv.y = *(unsigned*)&l1;
        *(uint2*)(outh + (size_t)row * 1024 + tid * 4) = hv;
        *(uint2*)(outl + (size_t)row * 1024 + tid * 4) = lv;
    } else {
        const int vb = blockIdx.x - 2050;   // 0..2047
        #pragma unroll
        for (int s = 0; s < 6; s++) {
            const float4* sp = (const float4*)a.src[s];
            __nv_bfloat16* hp = whi + a.dstoff[s];
            __nv_bfloat16* lp = wlo + a.dstoff[s];
            const int n4 = a.n4[s];
            for (int i = vb * 256 + tid; i < n4; i += 2048 * 256) {
                float4 f = sp[i];
                __nv_bfloat162 h0 = __floats2bfloat162_rn(f.x, f.y);
                __nv_bfloat162 h1 = __floats2bfloat162_rn(f.z, f.w);
                __nv_bfloat162 l0 = __floats2bfloat162_rn(f.x - __bfloat162float(h0.x),
                                                          f.y - __bfloat162float(h0.y));
                __nv_bfloat162 l1 = __floats2bfloat162_rn(f.z - __bfloat162float(h1.x),
                                                          f.w - __bfloat162float(h1.y));
                uint2 hv; hv.x = *(unsigned*)&h0; hv.y = *(unsigned*)&h1;
                uint2 lv; lv.x = *(unsigned*)&l0; lv.y = *(unsigned*)&l1;
                *(uint2*)(hp + (size_t)i * 4) = hv;
                *(uint2*)(lp + (size_t)i * 4) = lv;
            }
        }
    }
}

// ---------------------------------------------------------------------------
// Combine(proj split-K) + residual + LayerNorm2, fused.
// ---------------------------------------------------------------------------
__global__ void ln2_combine_kernel(const float* __restrict__ p1,
                                   const float* __restrict__ p2,
                                   const float* __restrict__ bias,
                                   const float* __restrict__ x,
                                   float* __restrict__ out,
                                   const float* __restrict__ w,
                                   const float* __restrict__ b,
                                   __nv_bfloat16* __restrict__ outh,
                                   __nv_bfloat16* __restrict__ outl) {
    __shared__ float red[32];
    int row = blockIdx.x, tid = threadIdx.x;
    const size_t ro = (size_t)row * 1024;
    float4 a  = ((const float4*)(p1 + ro))[tid];
    float4 c  = ((const float4*)(p2 + ro))[tid];
    float4 xr = ((const float4*)(x + ro))[tid];
    float4 bb = ((const float4*)bias)[tid];
    float4 v;
    v.x = a.x + c.x + bb.x + xr.x;
    v.y = a.y + c.y + bb.y + xr.y;
    v.z = a.z + c.z + bb.z + xr.z;
    v.w = a.w + c.w + bb.w + xr.w;
    ((float4*)(out + ro))[tid] = v;

    float s = v.x + v.y + v.z + v.w;
    float mean = blockReduceSum(s, red) * (1.f / 1024.f);
    float dx = v.x - mean, dy = v.y - mean, dz = v.z - mean, dw = v.w - mean;
    float ss = dx * dx + dy * dy + dz * dz + dw * dw;
    float var = blockReduceSum(ss, red) * (1.f / 1024.f);
    float rstd = rsqrtf(var + 1e-5f);
    float4 wv = ((const float4*)w)[tid];
    float4 bv = ((const float4*)b)[tid];
    float ox = dx * rstd * wv.x + bv.x;
    float oy = dy * rstd * wv.y + bv.y;
    float oz = dz * rstd * wv.z + bv.z;
    float ow = dw * rstd * wv.w + bv.w;
    __nv_bfloat162 h0 = __floats2bfloat162_rn(ox, oy);
    __nv_bfloat162 h1 = __floats2bfloat162_rn(oz, ow);
    __nv_bfloat162 l0 = __floats2bfloat162_rn(ox - __bfloat162float(h0.x),
                                              oy - __bfloat162float(h0.y));
    __nv_bfloat162 l1 = __floats2bfloat162_rn(oz - __bfloat162float(h1.x),
                                              ow - __bfloat162float(h1.y));
    uint2 hv; hv.x = *(unsigned*)&h0; hv.y = *(unsigned*)&h1;
    uint2 lv; lv.x = *(unsigned*)&l0; lv.y = *(unsigned*)&l1;
    *(uint2*)(outh + ro + tid * 4) = hv;
    *(uint2*)(outl + ro + tid * 4) = lv;
}

// ---------------------------------------------------------------------------
// fc2 split-K combine
// ---------------------------------------------------------------------------
__global__ void fc2_combine_kernel(const float* __restrict__ p1,
                                   const float* __restrict__ p2,
                                   const float* __restrict__ bias,
                                   float* __restrict__ out) {
    const int total = 2050 * 256;
    for (int i = blockIdx.x * blockDim.x + threadIdx.x; i < total;
         i += gridDim.x * blockDim.x) {
        float4 a = ((const float4*)p1)[i];
        float4 c = ((const float4*)p2)[i];
        float4 r = ((float4*)out)[i];
        float4 bb = ((const float4*)bias)[i & 255];
        r.x += a.x + c.x + bb.x;
        r.y += a.y + c.y + bb.y;
        r.z += a.z + c.z + bb.z;
        r.w += a.w + c.w + bb.w;
        ((float4*)out)[i] = r;
    }
}

// ---------------------------------------------------------------------------
// L2 norm over the fused [2048 x 2048] rq|rk output -> hi/lo QKR planes.
// ---------------------------------------------------------------------------
__global__ void l2norm_split_kernel(const float* __restrict__ c2,
                                    __nv_bfloat16* __restrict__ outh,
                                    __nv_bfloat16* __restrict__ outl) {
    __shared__ float red[32];
    int i = blockIdx.x, tid = threadIdx.x;
    const int srcRow = i & 2047;
    const int colOff = (i >> 11) * 1024;
    const float4* p = (const float4*)(c2 + (size_t)srcRow * 2048 + colOff);
    float4 v = p[tid];
    float ss = v.x * v.x + v.y * v.y + v.z * v.z + v.w * v.w;
    float tot = blockReduceSum(ss, red);
    float sc = 1.f / fmaxf(sqrtf(tot), 1e-12f);
    float ox = v.x * sc, oy = v.y * sc, oz = v.z * sc, ow = v.w * sc;
    __nv_bfloat162 h0 = __floats2bfloat162_rn(ox, oy);
    __nv_bfloat162 h1 = __floats2bfloat162_rn(oz, ow);
    __nv_bfloat162 l0 = __floats2bfloat162_rn(ox - __bfloat162float(h0.x),
                                              oy - __bfloat162float(h0.y));
    __nv_bfloat162 l1 = __floats2bfloat162_rn(oz - __bfloat162float(h1.x),
                                              ow - __bfloat162float(h1.y));
    uint2 hv; hv.x = *(unsigned*)&h0; hv.y = *(unsigned*)&h1;
    uint2 lv; lv.x = *(unsigned*)&l0; lv.y = *(unsigned*)&l1;
    *(uint2*)(outh + (size_t)i * 1024 + tid * 4) = hv;
    *(uint2*)(outl + (size_t)i * 1024 + tid * 4) = lv;
}

// ---------------------------------------------------------------------------
// bf16 tensor-core NT GEMM core (device function).
// TERMS=3: ah*bh + al*bh + ah*bl ; TERMS=2: ah*bh + al*bh
// ---------------------------------------------------------------------------
#define EPI_NONE        0
#define EPI_BIAS        1
#define EPI_BIAS2       2
#define EPI_GELU_SPLIT  3

#define KSTRIDE 40
#define TILE_BF16 (128 * KSTRIDE)
#define SB_BASE (4 * TILE_BF16)
#define GEMM_SMEM_BYTES (8 * TILE_BF16 * 2)   // 81920

__device__ __forceinline__ void mma_bf16(float* d, const unsigned* a, const unsigned* b) {
    asm volatile(
        "mma.sync.aligned.m16n8k16.row.col.f32.bf16.bf16.f32 "
        "{%0,%1,%2,%3}, {%4,%5,%6,%7}, {%8,%9}, {%0,%1,%2,%3};"
        : "+f"(d[0]), "+f"(d[1]), "+f"(d[2]), "+f"(d[3])
        : "r"(a[0]), "r"(a[1]), "r"(a[2]), "r"(a[3]), "r"(b[0]), "r"(b[1]));
}

__device__ __forceinline__ void ldsm4(unsigned addr, unsigned& r0, unsigned& r1,
                                      unsigned& r2, unsigned& r3) {
    asm volatile("ldmatrix.sync.aligned.m8n8.x4.shared.b16 {%0,%1,%2,%3}, [%4];"
                 : "=r"(r0), "=r"(r1), "=r"(r2), "=r"(r3) : "r"(addr));
}

__device__ __forceinline__ void cpasync16(unsigned dst, const void* src, unsigned sz) {
    asm volatile("cp.async.ca.shared.global [%0], [%1], 16, %2;"
                 :: "r"(dst), "l"(src), "r"(sz));
}

template <int EPI, int TERMS>
__device__ __forceinline__ void gemm_core(
    const __nv_bfloat16* __restrict__ Ah, const __nv_bfloat16* __restrict__ Al,
    const __nv_bfloat16* __restrict__ Bh, const __nv_bfloat16* __restrict__ Bl,
    const float* __restrict__ bias, const float* __restrict__ extra,
    float* __restrict__ C, __nv_bfloat16* __restrict__ Ch, __nv_bfloat16* __restrict__ Cl,
    int M, int N, int Kd, int lda, int ldb,
    long sA, long sB, long sC, long sCk, int KS,
    int bxv, int byv, int bzv) {

    const int zb = bzv / KS;
    const int ks = bzv % KS;
    Ah += (long)zb * sA + (long)ks * Kd;  Al += (long)zb * sA + (long)ks * Kd;
    Bh += (long)zb * sB + (long)ks * Kd;  Bl += (long)zb * sB + (long)ks * Kd;
    const long cOff = (long)zb * sC + (long)ks * sCk;

    extern __shared__ __nv_bfloat16 sm[];

    const int tid  = threadIdx.x;
    const int lane = tid & 31;
    const int wid  = tid >> 5;
    const int wr   = wid & 3;
    const int wc   = wid >> 2;
    const int g    = lane >> 2;
    const int tig  = lane & 3;
    const int bm   = byv * 128;
    const int bn   = bxv * 128;

    float acc[2][8][4];
    #pragma unroll
    for (int mi = 0; mi < 2; mi++)
        #pragma unroll
        for (int ni = 0; ni < 8; ni++)
            #pragma unroll
            for (int r = 0; r < 4; r++) acc[mi][ni][r] = 0.f;

    const int ldRow = tid >> 1;
    const int half  = tid & 1;
    const int aRow  = bm + ldRow;
    const unsigned aSz = (aRow < M) ? 16u : 0u;
    const long aOff = (long)((aRow < M) ? aRow : 0) * lda + half * 16;
    const long bOff = (long)(bn + ldRow) * ldb + half * 16;
    const __nv_bfloat16* aH = Ah + aOff;
    const __nv_bfloat16* aL = Al + aOff;
    const __nv_bfloat16* bH = Bh + bOff;
    const __nv_bfloat16* bL = Bl + bOff;

    const unsigned smBase = (unsigned)__cvta_generic_to_shared(sm);
    const unsigned dA0 = smBase + 2u * (unsigned)(ldRow * KSTRIDE + half * 16);
    const unsigned stagePitch = 2u * (unsigned)(2 * TILE_BF16);
    const unsigned hlPitch    = 2u * (unsigned)TILE_BF16;
    const unsigned bPlane     = 2u * (unsigned)SB_BASE;

    const int aRowL = wr * 32 + (lane & 7) + ((lane >> 3) & 1) * 8;
    const int aKL   = ((lane >> 4) & 1) * 8;
    const unsigned aLaneOff = (unsigned)(aRowL * KSTRIDE + aKL);
    const int bRowL = wc * 64 + (lane & 7) + ((lane >> 4) & 1) * 8;
    const int bKL   = ((lane >> 3) & 1) * 8;
    const unsigned bLaneOff = (unsigned)(bRowL * KSTRIDE + bKL);

    const int nIter = Kd >> 5;

    #define ISSUE(st, itv) do {                                              \
        const long k0 = (long)(itv) * 32;                                    \
        unsigned d0 = dA0 + (unsigned)(st) * stagePitch;                     \
        cpasync16(d0,            aH + k0,     aSz);                          \
        cpasync16(d0 + 16,       aH + k0 + 8, aSz);                          \
        cpasync16(d0 + hlPitch,      aL + k0,     aSz);                      \
        cpasync16(d0 + hlPitch + 16, aL + k0 + 8, aSz);                      \
        unsigned d1 = d0 + bPlane;                                           \
        cpasync16(d1,            bH + k0,     16u);                          \
        cpasync16(d1 + 16,       bH + k0 + 8, 16u);                          \
        if (TERMS == 3) {                                                    \
            cpasync16(d1 + hlPitch,      bL + k0,     16u);                  \
            cpasync16(d1 + hlPitch + 16, bL + k0 + 8, 16u);                  \
        }                                                                    \
        asm volatile("cp.async.commit_group;");                              \
    } while (0)

    ISSUE(0, 0);
    if (nIter > 1) ISSUE(1, 1);

    for (int it = 0; it < nIter; ++it) {
        if (it == nIter - 1) asm volatile("cp.async.wait_group 0;");
        else                 asm volatile("cp.async.wait_group 1;");
        __syncthreads();

        const int s = it & 1;
        const unsigned pA_hi = (unsigned)((s * 2 + 0) * TILE_BF16);
        const unsigned pA_lo = (unsigned)((s * 2 + 1) * TILE_BF16);
        const unsigned pB_hi = (unsigned)(SB_BASE + (s * 2 + 0) * TILE_BF16);
        const unsigned pB_lo = (unsigned)(SB_BASE + (s * 2 + 1) * TILE_BF16);

        #pragma unroll
        for (int ksl = 0; ksl < 2; ksl++) {
            const int kb = ksl * 16;
            unsigned Ahf[2][4], Alf[2][4], Bhf[8][2], Blf[8][2];
            #pragma unroll
            for (int mi = 0; mi < 2; mi++) {
                unsigned off = (unsigned)(mi * 16 * KSTRIDE + kb) + aLaneOff;
                ldsm4(smBase + 2u * (pA_hi + off), Ahf[mi][0], Ahf[mi][1], Ahf[mi][2], Ahf[mi][3]);
                ldsm4(smBase + 2u * (pA_lo + off), Alf[mi][0], Alf[mi][1], Alf[mi][2], Alf[mi][3]);
            }
            #pragma unroll
            for (int j = 0; j < 4; j++) {
                unsigned off = (unsigned)(j * 16 * KSTRIDE + kb) + bLaneOff;
                ldsm4(smBase + 2u * (pB_hi + off),
                      Bhf[j * 2][0], Bhf[j * 2][1], Bhf[j * 2 + 1][0], Bhf[j * 2 + 1][1]);
                if (TERMS == 3) {
                    ldsm4(smBase + 2u * (pB_lo + off),
                          Blf[j * 2][0], Blf[j * 2][1], Blf[j * 2 + 1][0], Blf[j * 2 + 1][1]);
                }
            }
            #pragma unroll
            for (int mi = 0; mi < 2; mi++)
                #pragma unroll
                for (int ni = 0; ni < 8; ni++) {
                    mma_bf16(acc[mi][ni], Ahf[mi], Bhf[ni]);
                    mma_bf16(acc[mi][ni], Alf[mi], Bhf[ni]);
                    if (TERMS == 3) mma_bf16(acc[mi][ni], Ahf[mi], Blf[ni]);
                }
        }
        __syncthreads();

        if (it + 2 < nIter) ISSUE(s, it + 2);
    }
    #undef ISSUE

    #pragma unroll
    for (int mi = 0; mi < 2; mi++) {
        #pragma unroll
        for (int rr = 0; rr < 2; rr++) {
            const int m = bm + wr * 32 + mi * 16 + g + rr * 8;
            if (m >= M) continue;
            #pragma unroll
            for (int ni = 0; ni < 8; ni++) {
                #pragma unroll
                for (int cc = 0; cc < 2; cc++) {
                    const int n = bn + wc * 64 + ni * 8 + tig * 2 + cc;
                    float v = acc[mi][ni][rr * 2 + cc];
                    const long idx = cOff + (long)m * N + n;
                    if (EPI == EPI_NONE) {
                        C[idx] = v;
                    } else if (EPI == EPI_BIAS) {
                        C[idx] = v + bias[n];
                    } else if (EPI == EPI_BIAS2) {
                        const int hN = N >> 1;
                        C[idx] = v + (n < hN ? bias[n] : extra[n - hN]);
                    } else if (EPI == EPI_GELU_SPLIT) {
                        v += bias[n];
                        v = 0.5f * v * (1.0f + erff(v * 0.70710678118654752f));
                        split1(v, Ch + idx, Cl + idx);
                    }
                }
            }
        }
    }
}

// standalone wrapper (3D grid as before)
template <int EPI, int TERMS>
__global__ __launch_bounds__(256, 2) void gemm_one(
    const __nv_bfloat16* __restrict__ Ah, const __nv_bfloat16* __restrict__ Al,
    const __nv_bfloat16* __restrict__ Bh, const __nv_bfloat16* __restrict__ Bl,
    const float* __restrict__ bias, const float* __restrict__ extra,
    float* __restrict__ C, __nv_bfloat16* __restrict__ Ch, __nv_bfloat16* __restrict__ Cl,
    int M, int N, int Kd, int lda, int ldb,
    long sA, long sB, long sC, long sCk, int KS) {
    gemm_core<EPI, TERMS>(Ah, Al, Bh, Bl, bias, extra, C, Ch, Cl,
                          M, N, Kd, lda, ldb, sA, sB, sC, sCk, KS,
                          blockIdx.x, blockIdx.y, blockIdx.z);
}

// merged scores (blocks 0..255, 3-term split-K) + qkv (blocks 256..663, 2-term)
__global__ __launch_bounds__(256, 2) void gemm_scores_qkv(
    const __nv_bfloat16* __restrict__ QKRh, const __nv_bfloat16* __restrict__ QKRl,
    float* __restrict__ SC, long sCk,
    const __nv_bfloat16* __restrict__ XNh, const __nv_bfloat16* __restrict__ XNl,
    const __nv_bfloat16* __restrict__ WQh, const __nv_bfloat16* __restrict__ WQl,
    const float* __restrict__ qkv_b, float* __restrict__ QKV) {
    if (blockIdx.x < 256) {
        const int l = blockIdx.x;
        gemm_core<EPI_NONE, 3>(QKRh, QKRl, QKRh + 2048ull * 1024, QKRl + 2048ull * 1024,
                               nullptr, nullptr, SC, nullptr, nullptr,
                               1024, 1024, 512, 1024, 1024,
                               1024ll * 1024, 1024ll * 1024, 1024ll * 1024, sCk, 2,
                               l & 7, (l >> 3) & 7, l >> 6);
    } else {
        const int l = blockIdx.x - 256;
        gemm_core<EPI_BIAS, 2>(XNh, XNl, WQh, WQl, qkv_b, nullptr,
                               QKV, nullptr, nullptr,
                               2050, 3072, 1024, 1024, 1024, 0, 0, 0, 0, 1,
                               l % 24, l / 24, 0);
    }
}

// ---------------------------------------------------------------------------
// Top-K=32: sums split-K partials + cantor bias + diag mask at load.
// ---------------------------------------------------------------------------
__global__ void topk_kernel(const float* __restrict__ sc1,
                            const float* __restrict__ sc2,
                            const float* __restrict__ pos_bias,
                            int* __restrict__ routes,
                            float* __restrict__ logw) {
    __shared__ float wv[8][32];
    __shared__ int   wi[8][32];
    __shared__ float sv[32];
    __shared__ int   si[32];
    const int row = blockIdx.x, tid = threadIdx.x;
    const int lane = tid & 31, w = tid >> 5;
    const int p = row & 1023;
    const float* s1 = sc1 + (size_t)row * 1024;
    const float* s2 = sc2 + (size_t)row * 1024;
    const float* pb = pos_bias + (size_t)p * 1024;

    float v[4]; int id4[4];
    #pragma unroll
    for (int c = 0; c < 4; c++) {
        int id = w * 128 + c * 32 + lane;
        float val = s1[id] + s2[id] + pb[id];
        if (id == p) val = -1e9f;
        v[c] = val;
        id4[c] = id;
    }

    for (int it = 0; it < 32; it++) {
        float bv = v[0]; int bi = id4[0]; int bs = 0;
        #pragma unroll
        for (int c = 1; c < 4; c++)
            if (v[c] > bv || (v[c] == bv && id4[c] < bi)) { bv = v[c]; bi = id4[c]; bs = c; }
        float cv = bv; int ci = bi;
        #pragma unroll
        for (int o = 16; o; o >>= 1) {
            float ov = __shfl_xor_sync(0xffffffffu, cv, o);
            int   oi = __shfl_xor_sync(0xffffffffu, ci, o);
            if (ov > cv || (ov == cv && oi < ci)) { cv = ov; ci = oi; }
        }
        if (lane == 0) { wv[w][it] = cv; wi[w][it] = ci; }
        if (ci == bi) v[bs] = -3.4e38f;
    }
    __syncthreads();

    if (w == 0) {
        int ptr = 0;
        for (int it = 0; it < 32; it++) {
            float cv = (lane < 8 && ptr < 32) ? wv[lane][ptr] : -3.4e38f;
            int   ci = (lane < 8 && ptr < 32) ? wi[lane][ptr] : 0x7fffffff;
            float bv = cv; int bi = ci;
            #pragma unroll
            for (int o = 4; o; o >>= 1) {
                float ov = __shfl_xor_sync(0xffffffffu, bv, o);
                int   oi = __shfl_xor_sync(0xffffffffu, bi, o);
                if (ov > bv || (ov == bv && oi < bi)) { bv = ov; bi = oi; }
            }
            if (lane < 8 && ci == bi && ptr < 32) ptr++;
            if (lane == 0) { sv[it] = bv; si[it] = bi; }
        }
    }
    __syncthreads();

    if (tid < 32) {
        float t = sv[tid] * INV_TEMP;
        float tmax = sv[0] * INV_TEMP;
        float e = expf(t - tmax);
        float z = e;
        #pragma unroll
        for (int o = 16; o; o >>= 1) z += __shfl_xor_sync(0xffffffffu, z, o);
        float lw = t - (tmax + logf(z));
        routes[(size_t)row * 32 + tid] = si[tid];
        logw[(size_t)row * 32 + tid] = fmaxf(lw, -10.f);
    }
}

// ---------------------------------------------------------------------------
// Merged attention: blocks [0,2048) routed patch attn (warp-per-head),
// blocks [2048,2080) CLS attention with 512 threads.
// ---------------------------------------------------------------------------
__global__ __launch_bounds__(512) void attn_kernel(
        const float* __restrict__ qkv,
        const int* __restrict__ routes,
        const float* __restrict__ logw,
        __nv_bfloat16* __restrict__ atth,
        __nv_bfloat16* __restrict__ attl) {
    const int tid = threadIdx.x, lane = tid & 31;
    if (blockIdx.x < 2048) {
        __shared__ int   rt[32];
        __shared__ float lw[32];
        const int bp = blockIdx.x, b = bp >> 10, p = bp & 1023;
        const int h = tid >> 5;
        if (tid < 32) {
            rt[tid] = routes[(size_t)bp * 32 + tid] + 1;
            lw[tid] = logw[(size_t)bp * 32 + tid];
        }
        __syncthreads();

        const float* base = qkv + (size_t)b * SS * 3072;
        const float* qp = base + (size_t)(p + 1) * 3072 + h * 64;
        const float q0 = qp[lane], q1 = qp[lane + 32];

        float myscore = 0.f;
        #pragma unroll
        for (int kb = 0; kb < 32; kb += 8) {
            float k0[8], k1[8];
            #pragma unroll
            for (int j = 0; j < 8; j++) {
                const float* kp = base + (size_t)rt[kb + j] * 3072 + 1024 + h * 64;
                k0[j] = kp[lane];
                k1[j] = kp[lane + 32];
            }
            #pragma unroll
            for (int j = 0; j < 8; j++) {
                float d = q0 * k0[j] + q1 * k1[j];
                #pragma unroll
                for (int o = 16; o; o >>= 1) d += __shfl_xor_sync(0xffffffffu, d, o);
                if (lane == kb + j) myscore = d * SCALE_ + lw[lane];
            }
        }

        float m = myscore;
        #pragma unroll
        for (int o = 16; o; o >>= 1) m = fmaxf(m, __shfl_xor_sync(0xffffffffu, m, o));
        float e = expf(myscore - m);
        float z = e;
        #pragma unroll
        for (int o = 16; o; o >>= 1) z += __shfl_xor_sync(0xffffffffu, z, o);
        const float pw = e / z;

        float o0 = 0.f, o1 = 0.f;
        #pragma unroll
        for (int kb = 0; kb < 32; kb += 8) {
            float v0[8], v1[8];
            #pragma unroll
            for (int j = 0; j < 8; j++) {
                const float* vp = base + (size_t)rt[kb + j] * 3072 + 2048 + h * 64;
                v0[j] = vp[lane];
                v1[j] = vp[lane + 32];
            }
            #pragma unroll
            for (int j = 0; j < 8; j++) {
                float wj = __shfl_sync(0xffffffffu, pw, kb + j);
                o0 += wj * v0[j];
                o1 += wj * v1[j];
            }
        }

        const size_t idx = ((size_t)b * SS + p + 1) * 1024 + h * 64 + lane;
        split1(o0, atth + idx, attl + idx);
        split1(o1, atth + idx + 32, attl + idx + 32);
    } else {
        __shared__ float q[64];
        __shared__ float sp[SS];
        __shared__ float red[32];
        __shared__ float po[8][64];
        const int bh = blockIdx.x - 2048, b = bh >> 4, h = bh & 15;
        const float* base = qkv + (size_t)b * SS * 3072;
        if (tid < 64) q[tid] = base[h * 64 + tid];
        __syncthreads();

        float lmax = -3.4e38f;
        for (int j = tid; j < SS; j += 512) {
            const float* kr = base + (size_t)j * 3072 + 1024 + h * 64;
            float d = 0.f;
            #pragma unroll
            for (int dd = 0; dd < 64; dd++) d += q[dd] * kr[dd];
            d *= SCALE_;
            sp[j] = d;
            lmax = fmaxf(lmax, d);
        }
        float M = blockReduceMax512(lmax, red);
        float ls = 0.f;
        for (int j = tid; j < SS; j += 512) {
            float e = expf(sp[j] - M);
            sp[j] = e;
            ls += e;
        }
        float Z = blockReduceSum512(ls, red);

        int g = tid >> 6, d = tid & 63;   // 8 groups of 64
        float o = 0.f;
        for (int j = g; j < SS; j += 8)
            o += sp[j] * base[(size_t)j * 3072 + 2048 + h * 64 + d];
        po[g][d] = o;
        __syncthreads();
        if (tid < 64) {
            float r = 0.f;
            #pragma unroll
            for (int gg = 0; gg < 8; gg++) r += po[gg][tid];
            r /= Z;
            size_t idx = (size_t)b * SS * 1024 + h * 64 + tid;
            split1(r, atth + idx, attl + idx);
        }
    }
}

// ---------------------------------------------------------------------------
// Orchestration
// ---------------------------------------------------------------------------
extern "C" void kernel_launch(void* const* d_in, const int* in_sizes, int n_in,
                              void* d_out, int out_size) {
    const float* x        = (const float*)d_in[0];
    const float* n1w      = (const float*)d_in[1];
    const float* n1b      = (const float*)d_in[2];
    const float* rq_w     = (const float*)d_in[3];
    const float* rq_b     = (const float*)d_in[4];
    const float* rk_w     = (const float*)d_in[5];
    const float* rk_b     = (const float*)d_in[6];
    const float* pos_bias = (const float*)d_in[7];
    const float* qkv_w    = (const float*)d_in[8];
    const float* qkv_b    = (const float*)d_in[9];
    const float* proj_w   = (const float*)d_in[10];
    const float* proj_b   = (const float*)d_in[11];
    const float* n2w      = (const float*)d_in[12];
    const float* n2b      = (const float*)d_in[13];
    const float* fc1_w    = (const float*)d_in[14];
    const float* fc1_b    = (const float*)d_in[15];
    const float* fc2_w    = (const float*)d_in[16];
    const float* fc2_b    = (const float*)d_in[17];
    float* out = (float*)d_out;

    void* sp = nullptr;
    cudaGetSymbolAddress(&sp, g_scratch);
    float* SCR = (float*)sp;
    float* C2  = SCR + O_QR;
    float* SC  = SCR + O_SC;
    float* SC2 = SCR + O_SC2;
    float* QKV = SCR + O_QKV;
    float* LW  = SCR + O_LW;
    int*   RT  = (int*)(SCR + O_RT);
    float* P1  = SCR + O_P1;
    float* P2  = SCR + O_P2;
    __nv_bfloat16* XNh  = (__nv_bfloat16*)(SCR + O_XNH);
    __nv_bfloat16* XNl  = (__nv_bfloat16*)(SCR + O_XNL);
    __nv_bfloat16* QKRh = (__nv_bfloat16*)(SCR + O_QKRH);
    __nv_bfloat16* QKRl = (__nv_bfloat16*)(SCR + O_QKRL);
    __nv_bfloat16* ATTh = (__nv_bfloat16*)(SCR + O_ATTH);
    __nv_bfloat16* ATTl = (__nv_bfloat16*)(SCR + O_ATTL);
    __nv_bfloat16* HNh  = (__nv_bfloat16*)(SCR + O_HNH);
    __nv_bfloat16* HNl  = (__nv_bfloat16*)(SCR + O_HNL);
    __nv_bfloat16* HHh  = (__nv_bfloat16*)(SCR + O_HHH);
    __nv_bfloat16* HHl  = (__nv_bfloat16*)(SCR + O_HHL);
    __nv_bfloat16* WH   = (__nv_bfloat16*)(SCR + O_WH);
    __nv_bfloat16* WL   = (__nv_bfloat16*)(SCR + O_WL);

    cudaFuncSetAttribute(gemm_one<EPI_BIAS2, 3>,
                         cudaFuncAttributeMaxDynamicSharedMemorySize, GEMM_SMEM_BYTES);
    cudaFuncSetAttribute(gemm_one<EPI_NONE, 2>,
                         cudaFuncAttributeMaxDynamicSharedMemorySize, GEMM_SMEM_BYTES);
    cudaFuncSetAttribute(gemm_one<EPI_GELU_SPLIT, 3>,
                         cudaFuncAttributeMaxDynamicSharedMemorySize, GEMM_SMEM_BYTES);
    cudaFuncSetAttribute(gemm_scores_qkv,
                         cudaFuncAttributeMaxDynamicSharedMemorySize, GEMM_SMEM_BYTES);

    // 0+1. merged weight split + LayerNorm1
    WSplit6 wargs;
    wargs.src[0] = rq_w;   wargs.dstoff[0] = (long)W_RQ;   wargs.n4[0] = 1048576 / 4;
    wargs.src[1] = rk_w;   wargs.dstoff[1] = (long)W_RK;   wargs.n4[1] = 1048576 / 4;
    wargs.src[2] = qkv_w;  wargs.dstoff[2] = (long)W_QKV;  wargs.n4[2] = 3145728 / 4;
    wargs.src[3] = proj_w; wargs.dstoff[3] = (long)W_PROJ; wargs.n4[3] = 1048576 / 4;
    wargs.src[4] = fc1_w;  wargs.dstoff[4] = (long)W_FC1;  wargs.n4[4] = 4194304 / 4;
    wargs.src[5] = fc2_w;  wargs.dstoff[5] = (long)W_FC2;  wargs.n4[5] = 4194304 / 4;
    ln1_splitw_kernel<<<4098, 256>>>(wargs, WH, WL, x, n1w, n1b, XNh, XNl);

    // 2. Fused routing projections (3-term)
    dim3 gR(16, 8, 2);
    gemm_one<EPI_BIAS2, 3><<<gR, 256, GEMM_SMEM_BYTES>>>(
        XNh + 1024, XNl + 1024, WH + W_RQ, WL + W_RQ, rq_b, rk_b,
        C2, nullptr, nullptr, 1024, 2048, 1024, 1024, 1024,
        (long)SS * DD, 0, (long)PP * 2048, 0, 1);

    // 3. L2 normalize + demux
    l2norm_split_kernel<<<4096, 256>>>(C2, QKRh, QKRl);

    // 4+6. merged scores (split-K, 3-term) + qkv (2-term): grid 664
    gemm_scores_qkv<<<664, 256, GEMM_SMEM_BYTES>>>(
        QKRh, QKRl, SC, (long)(SC2 - SC),
        XNh, XNl, WH + W_QKV, WL + W_QKV, qkv_b, QKV);

    // 5. Top-32 + routing weights
    topk_kernel<<<BB * PP, 256>>>(SC, SC2, pos_bias, RT, LW);

    // 7+8. merged patch + CLS attention: grid 2080
    attn_kernel<<<2080, 512>>>(QKV, RT, LW, ATTh, ATTl);

    // 9. Output projection, split-K=2 (2-term)
    dim3 gP(8, 17, 2);
    gemm_one<EPI_NONE, 2><<<gP, 256, GEMM_SMEM_BYTES>>>(
        ATTh, ATTl, WH + W_PROJ, WL + W_PROJ, nullptr, nullptr,
        P1, nullptr, nullptr, 2050, 1024, 512, 1024, 1024,
        0, 0, 0, (long)(P2 - P1), 2);

    // 10. Combine + residual + LayerNorm 2
    ln2_combine_kernel<<<BB * SS, 256>>>(P1, P2, proj_b, x, out, n2w, n2b, HNh, HNl);

    // 11. FC1 + exact GELU (3-term)
    dim3 gF1(32, 17, 1);
    gemm_one<EPI_GELU_SPLIT, 3><<<gF1, 256, GEMM_SMEM_BYTES>>>(
        HNh, HNl, WH + W_FC1, WL + W_FC1, fc1_b, nullptr,
        nullptr, HHh, HHl, 2050, 4096, 1024, 1024, 1024, 0, 0, 0, 0, 1);

    // 12. FC2, split-K=2 (2-term), combine + residual
    dim3 gF2(8, 17, 2);
    gemm_one<EPI_NONE, 2><<<gF2, 256, GEMM_SMEM_BYTES>>>(
        HHh, HHl, WH + W_FC2, WL + W_FC2, nullptr, nullptr,
        P1, nullptr, nullptr, 2050, 1024, 2048, 4096, 4096,
        0, 0, 0, (long)(P2 - P1), 2);
    fc2_combine_kernel<<<1024, 256>>>(P1, P2, fc2_b, out);

    (void)in_sizes; (void)n_in; (void)out_size;
}